// round 1
// baseline (speedup 1.0000x reference)
#include <cuda_runtime.h>
#include <cuda_bf16.h>
#include <math.h>

// ---------------- problem constants ----------------
#define VOCAB 50257
#define DMODEL 768
#define NHEAD 12
#define HDIM 64
#define TLEN 1024
#define NLAYER 6
#define BATCH 4
#define BT (BATCH * TLEN)     // 4096
#define FFDIM (4 * DMODEL)    // 3072
#define LNEPS 1e-5f

// ---------------- scratch (device globals: alloc-free rule) ----------------
__device__ float g_x [BT * DMODEL];
__device__ float g_q [BT * DMODEL];
__device__ float g_k [BT * DMODEL];
__device__ float g_v [BT * DMODEL];
__device__ float g_y [BT * DMODEL];
__device__ float g_ff[BT * FFDIM];
__device__ float g_rowloss[BT];

// ---------------- embedding: x = tok_emb[idx] + pos_emb ----------------
__global__ void embed_kernel(const int* __restrict__ idx,
                             const float* __restrict__ tok,
                             const float* __restrict__ pos,
                             float* __restrict__ x)
{
    int i = blockIdx.x * blockDim.x + threadIdx.x;
    if (i < BT * DMODEL) {
        int row = i / DMODEL;
        int d   = i - row * DMODEL;
        int t   = row % TLEN;
        x[i] = tok[(size_t)idx[row] * DMODEL + d] + pos[(size_t)t * DMODEL + d];
    }
}

// ---------------- generic tiled fp32 GEMM: C = A(MxK) @ B(KxN) (+bias)(+relu) ----------------
// 64x64 tile, BK=16, 256 threads, 4x4 microtile per thread.
__global__ void gemm_kernel(const float* __restrict__ A,
                            const float* __restrict__ Bm,
                            const float* __restrict__ bias,
                            float* __restrict__ C,
                            int M, int N, int K, int relu)
{
    __shared__ float As[64][17];   // padded: conflict-free column reads
    __shared__ float Bs[16][64];

    int tid = threadIdx.x;
    int ty = tid >> 4;             // 0..15
    int tx = tid & 15;             // 0..15
    int rowBase = blockIdx.y * 64;
    int colBase = blockIdx.x * 64;

    float acc[4][4];
    #pragma unroll
    for (int i = 0; i < 4; i++)
        #pragma unroll
        for (int j = 0; j < 4; j++) acc[i][j] = 0.f;

    for (int k0 = 0; k0 < K; k0 += 16) {
        // load A tile 64x16
        #pragma unroll
        for (int i = 0; i < 4; i++) {
            int e = tid + i * 256;
            int r = e >> 4, c = e & 15;
            int gr = rowBase + r, gc = k0 + c;
            As[r][c] = (gr < M && gc < K) ? A[(size_t)gr * K + gc] : 0.f;
        }
        // load B tile 16x64
        #pragma unroll
        for (int i = 0; i < 4; i++) {
            int e = tid + i * 256;
            int r = e >> 6, c = e & 63;
            int gr = k0 + r, gc = colBase + c;
            Bs[r][c] = (gr < K && gc < N) ? Bm[(size_t)gr * N + gc] : 0.f;
        }
        __syncthreads();

        #pragma unroll
        for (int k = 0; k < 16; k++) {
            float a[4], b[4];
            #pragma unroll
            for (int i = 0; i < 4; i++) a[i] = As[ty * 4 + i][k];
            #pragma unroll
            for (int j = 0; j < 4; j++) b[j] = Bs[k][tx * 4 + j];
            #pragma unroll
            for (int i = 0; i < 4; i++)
                #pragma unroll
                for (int j = 0; j < 4; j++)
                    acc[i][j] += a[i] * b[j];
        }
        __syncthreads();
    }

    #pragma unroll
    for (int i = 0; i < 4; i++) {
        int gr = rowBase + ty * 4 + i;
        if (gr >= M) continue;
        #pragma unroll
        for (int j = 0; j < 4; j++) {
            int gc = colBase + tx * 4 + j;
            if (gc >= N) continue;
            float vv = acc[i][j];
            if (bias) vv += bias[gc];
            if (relu) vv = fmaxf(vv, 0.f);
            C[(size_t)gr * N + gc] = vv;
        }
    }
}

// ---------------- fused causal attention: one block per (b, h, query row) ----------------
// 128 threads; streaming scores into shared, online softmax, weighted V sum.
__global__ void attn_kernel(const float* __restrict__ q,
                            const float* __restrict__ k,
                            const float* __restrict__ v,
                            float* __restrict__ y)
{
    int t = blockIdx.x;
    int h = blockIdx.y;
    int b = blockIdx.z;
    int tid = threadIdx.x;   // 128

    __shared__ float sq[HDIM];
    __shared__ float sc[TLEN];
    __shared__ float red[128];
    __shared__ float yacc[128];

    size_t base = (size_t)b * TLEN * DMODEL + (size_t)h * HDIM;

    if (tid < HDIM) sq[tid] = q[base + (size_t)t * DMODEL + tid];
    __syncthreads();

    int nk = t + 1;

    // scores + local max
    float lmax = -1e30f;
    for (int s = tid; s < nk; s += 128) {
        const float* kr = k + base + (size_t)s * DMODEL;
        float dot = 0.f;
        #pragma unroll
        for (int d = 0; d < HDIM; d++) dot += sq[d] * kr[d];
        dot *= 0.125f;   // 1/sqrt(64)
        sc[s] = dot;
        lmax = fmaxf(lmax, dot);
    }
    red[tid] = lmax;
    __syncthreads();
    for (int off = 64; off > 0; off >>= 1) {
        if (tid < off) red[tid] = fmaxf(red[tid], red[tid + off]);
        __syncthreads();
    }
    float m = red[0];
    __syncthreads();

    // exp + local sum
    float lsum = 0.f;
    for (int s = tid; s < nk; s += 128) {
        float e = __expf(sc[s] - m);
        sc[s] = e;
        lsum += e;
    }
    red[tid] = lsum;
    __syncthreads();
    for (int off = 64; off > 0; off >>= 1) {
        if (tid < off) red[tid] += red[tid + off];
        __syncthreads();
    }
    float inv = 1.f / red[0];
    __syncthreads();

    // weighted sum of V: thread -> (dim, half of key range)
    int d = tid & 63;
    int part = tid >> 6;
    float acc = 0.f;
    for (int s = part; s < nk; s += 2)
        acc += sc[s] * v[base + (size_t)s * DMODEL + d];
    yacc[tid] = acc;
    __syncthreads();
    if (tid < HDIM)
        y[base + (size_t)t * DMODEL + tid] = (yacc[tid] + yacc[tid + 64]) * inv;
}

// ---------------- residual + layernorm: xout = LN(xin + res) * g + b ----------------
__global__ void resln_kernel(const float* __restrict__ xin,
                             const float* __restrict__ res,
                             const float* __restrict__ gamma,
                             const float* __restrict__ beta,
                             float* __restrict__ xout)
{
    int row = blockIdx.x;
    int tid = threadIdx.x;   // 256
    __shared__ float red[256];

    float vals[3];
    float s1 = 0.f;
    #pragma unroll
    for (int i = 0; i < 3; i++) {
        int c = tid + i * 256;
        float vv = xin[(size_t)row * DMODEL + c] + res[(size_t)row * DMODEL + c];
        vals[i] = vv;
        s1 += vv;
    }
    red[tid] = s1;
    __syncthreads();
    for (int off = 128; off > 0; off >>= 1) {
        if (tid < off) red[tid] += red[tid + off];
        __syncthreads();
    }
    float mu = red[0] * (1.f / DMODEL);
    __syncthreads();

    float s2 = 0.f;
    #pragma unroll
    for (int i = 0; i < 3; i++) {
        float dv = vals[i] - mu;
        s2 += dv * dv;
    }
    red[tid] = s2;
    __syncthreads();
    for (int off = 128; off > 0; off >>= 1) {
        if (tid < off) red[tid] += red[tid + off];
        __syncthreads();
    }
    float inv = rsqrtf(red[0] * (1.f / DMODEL) + LNEPS);
    __syncthreads();

    #pragma unroll
    for (int i = 0; i < 3; i++) {
        int c = tid + i * 256;
        xout[(size_t)row * DMODEL + c] = (vals[i] - mu) * inv * gamma[c] + beta[c];
    }
}

// ---------------- per-row cross-entropy: rowloss = -(logit[tgt] - max - log(sum exp)) ----------------
__global__ void loss_row_kernel(const float* __restrict__ logits,
                                const int* __restrict__ tgt,
                                float* __restrict__ rowloss)
{
    int row = blockIdx.x;
    int tid = threadIdx.x;   // 256
    const float* lr = logits + (size_t)row * VOCAB;
    __shared__ float red[256];

    float m = -1e30f;
    for (int c = tid; c < VOCAB; c += 256) m = fmaxf(m, lr[c]);
    red[tid] = m;
    __syncthreads();
    for (int off = 128; off > 0; off >>= 1) {
        if (tid < off) red[tid] = fmaxf(red[tid], red[tid + off]);
        __syncthreads();
    }
    float M = red[0];
    __syncthreads();

    float s = 0.f;
    for (int c = tid; c < VOCAB; c += 256) s += __expf(lr[c] - M);
    red[tid] = s;
    __syncthreads();
    for (int off = 128; off > 0; off >>= 1) {
        if (tid < off) red[tid] += red[tid + off];
        __syncthreads();
    }
    if (tid == 0)
        rowloss[row] = -(lr[tgt[row]] - M - logf(red[0]));
}

__global__ void loss_final_kernel(const float* __restrict__ rowloss,
                                  float* __restrict__ out)
{
    int tid = threadIdx.x;   // 256
    __shared__ float red[256];
    float s = 0.f;
    for (int i = tid; i < BT; i += 256) s += rowloss[i];
    red[tid] = s;
    __syncthreads();
    for (int off = 128; off > 0; off >>= 1) {
        if (tid < off) red[tid] += red[tid + off];
        __syncthreads();
    }
    if (tid == 0) out[0] = red[0] * (1.f / BT);
}

// ---------------- host orchestration ----------------
static inline void launch_gemm(const float* A, const float* B, const float* bias,
                               float* C, int M, int N, int K, int relu)
{
    dim3 grid((N + 63) / 64, (M + 63) / 64);
    gemm_kernel<<<grid, 256>>>(A, B, bias, C, M, N, K, relu);
}

extern "C" void kernel_launch(void* const* d_in, const int* in_sizes, int n_in,
                              void* d_out, int out_size)
{
    const int*   idx     = (const int*)  d_in[0];
    const int*   targets = (const int*)  d_in[1];
    const float* tok_emb = (const float*)d_in[2];
    const float* pos_emb = (const float*)d_in[3];
    const float* Wq      = (const float*)d_in[4];
    const float* Wk      = (const float*)d_in[5];
    const float* Wv      = (const float*)d_in[6];
    const float* ln1_g   = (const float*)d_in[7];
    const float* ln1_b   = (const float*)d_in[8];
    const float* W1      = (const float*)d_in[9];
    const float* b1      = (const float*)d_in[10];
    const float* W2      = (const float*)d_in[11];
    const float* b2      = (const float*)d_in[12];
    const float* ln2_g   = (const float*)d_in[13];
    const float* ln2_b   = (const float*)d_in[14];
    const float* head_w  = (const float*)d_in[15];
    const float* head_b  = (const float*)d_in[16];

    void *px, *pq, *pk, *pv, *py, *pff, *prl;
    cudaGetSymbolAddress(&px,  g_x);
    cudaGetSymbolAddress(&pq,  g_q);
    cudaGetSymbolAddress(&pk,  g_k);
    cudaGetSymbolAddress(&pv,  g_v);
    cudaGetSymbolAddress(&py,  g_y);
    cudaGetSymbolAddress(&pff, g_ff);
    cudaGetSymbolAddress(&prl, g_rowloss);
    float* x  = (float*)px;
    float* q  = (float*)pq;
    float* k  = (float*)pk;
    float* v  = (float*)pv;
    float* y  = (float*)py;
    float* ff = (float*)pff;
    float* rl = (float*)prl;

    float* out = (float*)d_out;
    size_t logits_n = (size_t)BT * VOCAB;

    // embedding
    embed_kernel<<<(BT * DMODEL + 255) / 256, 256>>>(idx, tok_emb, pos_emb, x);

    for (int l = 0; l < NLAYER; l++) {
        const float* wq = Wq + (size_t)l * DMODEL * DMODEL;
        const float* wk = Wk + (size_t)l * DMODEL * DMODEL;
        const float* wv = Wv + (size_t)l * DMODEL * DMODEL;

        launch_gemm(x, wq, nullptr, q, BT, DMODEL, DMODEL, 0);
        launch_gemm(x, wk, nullptr, k, BT, DMODEL, DMODEL, 0);
        launch_gemm(x, wv, nullptr, v, BT, DMODEL, DMODEL, 0);

        attn_kernel<<<dim3(TLEN, NHEAD, BATCH), 128>>>(q, k, v, y);

        resln_kernel<<<BT, 256>>>(y, x, ln1_g + (size_t)l * DMODEL,
                                  ln1_b + (size_t)l * DMODEL, x);

        launch_gemm(x, W1 + (size_t)l * DMODEL * FFDIM, b1 + (size_t)l * FFDIM,
                    ff, BT, FFDIM, DMODEL, 1);
        launch_gemm(ff, W2 + (size_t)l * FFDIM * DMODEL, b2 + (size_t)l * DMODEL,
                    y, BT, DMODEL, FFDIM, 0);

        resln_kernel<<<BT, 256>>>(y, x, ln2_g + (size_t)l * DMODEL,
                                  ln2_b + (size_t)l * DMODEL, x);
    }

    // lm head -> logits directly into d_out
    launch_gemm(x, head_w, head_b, out, BT, VOCAB, DMODEL, 0);

    // cross-entropy loss (deterministic two-stage reduction)
    loss_row_kernel<<<BT, 256>>>(out, targets, rl);
    if ((size_t)out_size >= logits_n + 1)
        loss_final_kernel<<<1, 256>>>(rl, out + logits_n);
}

// round 3
// speedup vs baseline: 3.3932x; 3.3932x over previous
#include <cuda_runtime.h>
#include <cuda_bf16.h>
#include <math.h>
#include <stdint.h>

// ---------------- problem constants ----------------
#define VOCAB 50257
#define DMODEL 768
#define NHEAD 12
#define HDIM 64
#define TLEN 1024
#define NLAYER 6
#define BATCH 4
#define BT (BATCH * TLEN)     // 4096
#define FFDIM (4 * DMODEL)    // 3072
#define LNEPS 1e-5f

// ---------------- scratch (device globals: alloc-free rule) ----------------
__device__ __align__(128) float g_x [BT * DMODEL];
__device__ __align__(128) float g_q [BT * DMODEL];
__device__ __align__(128) float g_k [BT * DMODEL];
__device__ __align__(128) float g_v [BT * DMODEL];
__device__ __align__(128) float g_y [BT * DMODEL];
__device__ __align__(128) float g_ff[BT * FFDIM];
__device__ __align__(128) float g_rowloss[BT];

// ---------------- embedding ----------------
__global__ void embed_kernel(const int* __restrict__ idx,
                             const float* __restrict__ tok,
                             const float* __restrict__ pos,
                             float* __restrict__ x)
{
    int i = blockIdx.x * blockDim.x + threadIdx.x;
    if (i < BT * DMODEL) {
        int row = i / DMODEL;
        int d   = i - row * DMODEL;
        int t   = row % TLEN;
        x[i] = tok[(size_t)idx[row] * DMODEL + d] + pos[(size_t)t * DMODEL + d];
    }
}

// ---------------- tensor-core GEMM: bf16 hi/lo split (3-product) ----------------
// C[M,N] = A[M,K] @ B[K,N] (+bias)(+relu), fp32 in/out, near-fp32 precision.
// Block tile 128x128, BK=16. 256 threads = 8 warps (4 M x 2 N),
// warp tile 32x64 via m16n8k16 bf16 mma with fp32 accumulate.
// N may be arbitrary (odd VOCAB): vectorized paths are guarded by uniform
// runtime alignment checks.

#define GSTRIDE 20   // padded bf16 row stride (40B) -> conflict-free frag LDS

__device__ __forceinline__ void mma_bf16(float c[4], const uint32_t a[4], const uint32_t b[2])
{
    asm volatile(
        "mma.sync.aligned.m16n8k16.row.col.f32.bf16.bf16.f32 "
        "{%0,%1,%2,%3}, {%4,%5,%6,%7}, {%8,%9}, {%0,%1,%2,%3};\n"
        : "+f"(c[0]), "+f"(c[1]), "+f"(c[2]), "+f"(c[3])
        : "r"(a[0]), "r"(a[1]), "r"(a[2]), "r"(a[3]), "r"(b[0]), "r"(b[1]));
}

__global__ __launch_bounds__(256)
void gemm_tc_kernel(const float* __restrict__ A,
                    const float* __restrict__ Bm,
                    const float* __restrict__ bias,
                    float* __restrict__ C,
                    int M, int N, int K, int relu)
{
    __shared__ __align__(16) __nv_bfloat16 As_hi[128 * GSTRIDE];
    __shared__ __align__(16) __nv_bfloat16 As_lo[128 * GSTRIDE];
    __shared__ __align__(16) __nv_bfloat16 Bs_hi[128 * GSTRIDE];
    __shared__ __align__(16) __nv_bfloat16 Bs_lo[128 * GSTRIDE];

    int tid  = threadIdx.x;
    int warp = tid >> 5;
    int lane = tid & 31;
    int wr = warp >> 1;            // 0..3 -> 32 M-rows each
    int wc = warp & 1;             // 0..1 -> 64 N-cols each
    int m0 = wr * 32, n0 = wc * 64;
    int g  = lane >> 2;            // 0..7
    int tg = lane & 3;             // 0..3

    int rowBase = blockIdx.y * 128;
    int colBase = blockIdx.x * 128;

    bool vec4N = ((N & 3) == 0);   // uniform: B-row float4 loads safe
    bool vec2N = ((N & 1) == 0);   // uniform: C float2 stores safe

    float c[2][8][4];
    #pragma unroll
    for (int i = 0; i < 2; i++)
        #pragma unroll
        for (int j = 0; j < 8; j++)
            #pragma unroll
            for (int r = 0; r < 4; r++) c[i][j][r] = 0.f;

    // global load coords
    int ra = tid >> 2, ca = (tid & 3) * 4;       // A: 2 passes of 64 rows, float4
    int rb = tid >> 4, cb = (tid & 15) * 8;      // B: 16 rows, 8 cols each

    for (int k0 = 0; k0 < K; k0 += 16) {
        // ---- A tile: 128x16 fp32 -> split hi/lo bf16 (K always %16, A 16B-aligned) ----
        #pragma unroll
        for (int p = 0; p < 2; p++) {
            int r  = ra + p * 64;
            int gr = rowBase + r;
            float4 v4 = make_float4(0.f, 0.f, 0.f, 0.f);
            if (gr < M) v4 = *(const float4*)(A + (size_t)gr * K + k0 + ca);
            const float* vv = &v4.x;
            #pragma unroll
            for (int q = 0; q < 4; q++) {
                float xv = vv[q];
                __nv_bfloat16 hi = __float2bfloat16_rn(xv);
                __nv_bfloat16 lo = __float2bfloat16_rn(xv - __bfloat162float(hi));
                As_hi[r * GSTRIDE + ca + q] = hi;
                As_lo[r * GSTRIDE + ca + q] = lo;
            }
        }
        // ---- B tile: 16x128 fp32 -> transposed [n][k] hi/lo bf16 ----
        {
            int gr = k0 + rb;
            #pragma unroll
            for (int p = 0; p < 2; p++) {
                int gc0 = colBase + cb + p * 4;
                float4 v4 = make_float4(0.f, 0.f, 0.f, 0.f);
                float* vv = &v4.x;
                if (vec4N) {
                    if (gc0 + 3 < N)
                        v4 = *(const float4*)(Bm + (size_t)gr * N + gc0);
                    else {
                        #pragma unroll
                        for (int q = 0; q < 4; q++)
                            if (gc0 + q < N) vv[q] = Bm[(size_t)gr * N + gc0 + q];
                    }
                } else {
                    #pragma unroll
                    for (int q = 0; q < 4; q++)
                        if (gc0 + q < N) vv[q] = Bm[(size_t)gr * N + gc0 + q];
                }
                #pragma unroll
                for (int q = 0; q < 4; q++) {
                    float xv = vv[q];
                    __nv_bfloat16 hi = __float2bfloat16_rn(xv);
                    __nv_bfloat16 lo = __float2bfloat16_rn(xv - __bfloat162float(hi));
                    int n = cb + p * 4 + q;
                    Bs_hi[n * GSTRIDE + rb] = hi;
                    Bs_lo[n * GSTRIDE + rb] = lo;
                }
            }
        }
        __syncthreads();

        // ---- fragments ----
        uint32_t ahi[2][4], alo[2][4], bhi[8][2], blo[8][2];
        #pragma unroll
        for (int i = 0; i < 2; i++) {
            int r = m0 + 16 * i + g;
            ahi[i][0] = *(const uint32_t*)&As_hi[r * GSTRIDE + 2 * tg];
            ahi[i][1] = *(const uint32_t*)&As_hi[(r + 8) * GSTRIDE + 2 * tg];
            ahi[i][2] = *(const uint32_t*)&As_hi[r * GSTRIDE + 2 * tg + 8];
            ahi[i][3] = *(const uint32_t*)&As_hi[(r + 8) * GSTRIDE + 2 * tg + 8];
            alo[i][0] = *(const uint32_t*)&As_lo[r * GSTRIDE + 2 * tg];
            alo[i][1] = *(const uint32_t*)&As_lo[(r + 8) * GSTRIDE + 2 * tg];
            alo[i][2] = *(const uint32_t*)&As_lo[r * GSTRIDE + 2 * tg + 8];
            alo[i][3] = *(const uint32_t*)&As_lo[(r + 8) * GSTRIDE + 2 * tg + 8];
        }
        #pragma unroll
        for (int j = 0; j < 8; j++) {
            int n = n0 + 8 * j + g;
            bhi[j][0] = *(const uint32_t*)&Bs_hi[n * GSTRIDE + 2 * tg];
            bhi[j][1] = *(const uint32_t*)&Bs_hi[n * GSTRIDE + 2 * tg + 8];
            blo[j][0] = *(const uint32_t*)&Bs_lo[n * GSTRIDE + 2 * tg];
            blo[j][1] = *(const uint32_t*)&Bs_lo[n * GSTRIDE + 2 * tg + 8];
        }

        #pragma unroll
        for (int i = 0; i < 2; i++)
            #pragma unroll
            for (int j = 0; j < 8; j++) {
                mma_bf16(c[i][j], ahi[i], bhi[j]);
                mma_bf16(c[i][j], ahi[i], blo[j]);
                mma_bf16(c[i][j], alo[i], bhi[j]);
            }
        __syncthreads();
    }

    // ---- epilogue: bias + relu; float2 stores only when N even ----
    #pragma unroll
    for (int i = 0; i < 2; i++) {
        #pragma unroll
        for (int j = 0; j < 8; j++) {
            int col = colBase + n0 + 8 * j + 2 * tg;
            #pragma unroll
            for (int h = 0; h < 2; h++) {       // h=0 -> rows g, h=1 -> rows g+8
                int row = rowBase + m0 + 16 * i + g + 8 * h;
                if (row >= M) continue;
                float v0 = c[i][j][2 * h + 0];
                float v1 = c[i][j][2 * h + 1];
                if (bias) {
                    if (col < N)     v0 += bias[col];
                    if (col + 1 < N) v1 += bias[col + 1];
                }
                if (relu) { v0 = fmaxf(v0, 0.f); v1 = fmaxf(v1, 0.f); }
                float* dst = C + (size_t)row * N + col;
                if (vec2N && col + 1 < N) {
                    *(float2*)dst = make_float2(v0, v1);
                } else {
                    if (col < N)     dst[0] = v0;
                    if (col + 1 < N) dst[1] = v1;
                }
            }
        }
    }
}

// ---------------- tiled flash attention (fp32, 64q x 32k tiles) ----------------
__global__ __launch_bounds__(256)
void attn_tile_kernel(const float* __restrict__ q,
                      const float* __restrict__ k,
                      const float* __restrict__ v,
                      float* __restrict__ y)
{
    int qt = blockIdx.x;    // 0..15 (64-query tiles)
    int h  = blockIdx.y;
    int b  = blockIdx.z;
    int tid = threadIdx.x;  // 256

    __shared__ float Qs[64][65];
    __shared__ float Ks[32][65];
    __shared__ float Vs[32][65];
    __shared__ float Ss[64][33];
    __shared__ float rowm[64], rowl[64], rowa[64];

    size_t headbase = (size_t)b * TLEN * DMODEL + (size_t)h * HDIM;
    int q0 = qt * 64;

    // load Q tile 64x64
    {
        int r = tid >> 2, c0 = (tid & 3) * 16;
        const float* src = q + headbase + (size_t)(q0 + r) * DMODEL + c0;
        #pragma unroll
        for (int i = 0; i < 4; i++) {
            float4 t4 = *(const float4*)(src + 4 * i);
            Qs[r][c0 + 4 * i + 0] = t4.x;
            Qs[r][c0 + 4 * i + 1] = t4.y;
            Qs[r][c0 + 4 * i + 2] = t4.z;
            Qs[r][c0 + 4 * i + 3] = t4.w;
        }
    }
    if (tid < 64) { rowm[tid] = -1e30f; rowl[tid] = 0.f; }

    float o[4][4];
    #pragma unroll
    for (int i = 0; i < 4; i++)
        #pragma unroll
        for (int j = 0; j < 4; j++) o[i][j] = 0.f;

    int tx = tid & 15, ty = tid >> 4;   // 16x16 compute grid
    __syncthreads();

    for (int s0 = 0; s0 < q0 + 64; s0 += 32) {
        // load K,V tiles 32x64
        {
            int kr = tid >> 3, kc = (tid & 7) * 8;
            const float* ksrc = k + headbase + (size_t)(s0 + kr) * DMODEL + kc;
            const float* vsrc = v + headbase + (size_t)(s0 + kr) * DMODEL + kc;
            #pragma unroll
            for (int i = 0; i < 2; i++) {
                float4 t4 = *(const float4*)(ksrc + 4 * i);
                Ks[kr][kc + 4 * i + 0] = t4.x; Ks[kr][kc + 4 * i + 1] = t4.y;
                Ks[kr][kc + 4 * i + 2] = t4.z; Ks[kr][kc + 4 * i + 3] = t4.w;
                float4 u4 = *(const float4*)(vsrc + 4 * i);
                Vs[kr][kc + 4 * i + 0] = u4.x; Vs[kr][kc + 4 * i + 1] = u4.y;
                Vs[kr][kc + 4 * i + 2] = u4.z; Vs[kr][kc + 4 * i + 3] = u4.w;
            }
        }
        __syncthreads();

        // S = Q K^T / 8 with causal mask
        float acc[4][2];
        #pragma unroll
        for (int i = 0; i < 4; i++) { acc[i][0] = 0.f; acc[i][1] = 0.f; }
        for (int d = 0; d < 64; d++) {
            float bv0 = Ks[tx][d], bv1 = Ks[tx + 16][d];
            #pragma unroll
            for (int i = 0; i < 4; i++) {
                float av = Qs[ty + 16 * i][d];
                acc[i][0] += av * bv0;
                acc[i][1] += av * bv1;
            }
        }
        #pragma unroll
        for (int i = 0; i < 4; i++)
            #pragma unroll
            for (int jj = 0; jj < 2; jj++) {
                int r = ty + 16 * i, cc = tx + 16 * jj;
                int gq = q0 + r, gs = s0 + cc;
                Ss[r][cc] = (gs <= gq) ? acc[i][jj] * 0.125f : -1e30f;
            }
        __syncthreads();

        // online softmax per row
        if (tid < 64) {
            float mo = rowm[tid];
            float mx = mo;
            #pragma unroll 8
            for (int cc = 0; cc < 32; cc++) mx = fmaxf(mx, Ss[tid][cc]);
            float alpha = __expf(mo - mx);
            float sum = 0.f;
            #pragma unroll 8
            for (int cc = 0; cc < 32; cc++) {
                float p = __expf(Ss[tid][cc] - mx);
                Ss[tid][cc] = p;
                sum += p;
            }
            rowl[tid] = rowl[tid] * alpha + sum;
            rowm[tid] = mx;
            rowa[tid] = alpha;
        }
        __syncthreads();

        // O = O*alpha + P V
        #pragma unroll
        for (int i = 0; i < 4; i++) {
            float al = rowa[ty + 16 * i];
            #pragma unroll
            for (int jj = 0; jj < 4; jj++) o[i][jj] *= al;
        }
        for (int cc = 0; cc < 32; cc++) {
            float p0 = Ss[ty][cc], p1 = Ss[ty + 16][cc];
            float p2 = Ss[ty + 32][cc], p3 = Ss[ty + 48][cc];
            #pragma unroll
            for (int jj = 0; jj < 4; jj++) {
                float vv = Vs[cc][tx + 16 * jj];
                o[0][jj] += p0 * vv;
                o[1][jj] += p1 * vv;
                o[2][jj] += p2 * vv;
                o[3][jj] += p3 * vv;
            }
        }
        __syncthreads();
    }

    // write out
    #pragma unroll
    for (int i = 0; i < 4; i++) {
        int r = ty + 16 * i;
        float inv = 1.f / rowl[r];
        #pragma unroll
        for (int jj = 0; jj < 4; jj++) {
            int cc = tx + 16 * jj;
            y[headbase + (size_t)(q0 + r) * DMODEL + cc] = o[i][jj] * inv;
        }
    }
}

// ---------------- residual + layernorm ----------------
__global__ void resln_kernel(const float* __restrict__ xin,
                             const float* __restrict__ res,
                             const float* __restrict__ gamma,
                             const float* __restrict__ beta,
                             float* __restrict__ xout)
{
    int row = blockIdx.x;
    int tid = threadIdx.x;   // 256
    __shared__ float red[256];

    float vals[3];
    float s1 = 0.f;
    #pragma unroll
    for (int i = 0; i < 3; i++) {
        int cidx = tid + i * 256;
        float vv = xin[(size_t)row * DMODEL + cidx] + res[(size_t)row * DMODEL + cidx];
        vals[i] = vv;
        s1 += vv;
    }
    red[tid] = s1;
    __syncthreads();
    for (int off = 128; off > 0; off >>= 1) {
        if (tid < off) red[tid] += red[tid + off];
        __syncthreads();
    }
    float mu = red[0] * (1.f / DMODEL);
    __syncthreads();

    float s2 = 0.f;
    #pragma unroll
    for (int i = 0; i < 3; i++) {
        float dv = vals[i] - mu;
        s2 += dv * dv;
    }
    red[tid] = s2;
    __syncthreads();
    for (int off = 128; off > 0; off >>= 1) {
        if (tid < off) red[tid] += red[tid + off];
        __syncthreads();
    }
    float inv = rsqrtf(red[0] * (1.f / DMODEL) + LNEPS);
    __syncthreads();

    #pragma unroll
    for (int i = 0; i < 3; i++) {
        int cidx = tid + i * 256;
        xout[(size_t)row * DMODEL + cidx] = (vals[i] - mu) * inv * gamma[cidx] + beta[cidx];
    }
}

// ---------------- cross-entropy ----------------
__global__ void loss_row_kernel(const float* __restrict__ logits,
                                const int* __restrict__ tgt,
                                float* __restrict__ rowloss)
{
    int row = blockIdx.x;
    int tid = threadIdx.x;   // 256
    const float* lr = logits + (size_t)row * VOCAB;
    __shared__ float red[256];

    float m = -1e30f;
    for (int cc = tid; cc < VOCAB; cc += 256) m = fmaxf(m, lr[cc]);
    red[tid] = m;
    __syncthreads();
    for (int off = 128; off > 0; off >>= 1) {
        if (tid < off) red[tid] = fmaxf(red[tid], red[tid + off]);
        __syncthreads();
    }
    float M = red[0];
    __syncthreads();

    float s = 0.f;
    for (int cc = tid; cc < VOCAB; cc += 256) s += __expf(lr[cc] - M);
    red[tid] = s;
    __syncthreads();
    for (int off = 128; off > 0; off >>= 1) {
        if (tid < off) red[tid] += red[tid + off];
        __syncthreads();
    }
    if (tid == 0)
        rowloss[row] = -(lr[tgt[row]] - M - logf(red[0]));
}

__global__ void loss_final_kernel(const float* __restrict__ rowloss,
                                  float* __restrict__ out)
{
    int tid = threadIdx.x;   // 256
    __shared__ float red[256];
    float s = 0.f;
    for (int i = tid; i < BT; i += 256) s += rowloss[i];
    red[tid] = s;
    __syncthreads();
    for (int off = 128; off > 0; off >>= 1) {
        if (tid < off) red[tid] += red[tid + off];
        __syncthreads();
    }
    if (tid == 0) out[0] = red[0] * (1.f / BT);
}

// ---------------- host orchestration ----------------
static inline void launch_gemm(const float* A, const float* B, const float* bias,
                               float* C, int M, int N, int K, int relu)
{
    dim3 grid((N + 127) / 128, (M + 127) / 128);
    gemm_tc_kernel<<<grid, 256>>>(A, B, bias, C, M, N, K, relu);
}

extern "C" void kernel_launch(void* const* d_in, const int* in_sizes, int n_in,
                              void* d_out, int out_size)
{
    const int*   idx     = (const int*)  d_in[0];
    const int*   targets = (const int*)  d_in[1];
    const float* tok_emb = (const float*)d_in[2];
    const float* pos_emb = (const float*)d_in[3];
    const float* Wq      = (const float*)d_in[4];
    const float* Wk      = (const float*)d_in[5];
    const float* Wv      = (const float*)d_in[6];
    const float* ln1_g   = (const float*)d_in[7];
    const float* ln1_b   = (const float*)d_in[8];
    const float* W1      = (const float*)d_in[9];
    const float* b1      = (const float*)d_in[10];
    const float* W2      = (const float*)d_in[11];
    const float* b2      = (const float*)d_in[12];
    const float* ln2_g   = (const float*)d_in[13];
    const float* ln2_b   = (const float*)d_in[14];
    const float* head_w  = (const float*)d_in[15];
    const float* head_b  = (const float*)d_in[16];

    void *px, *pq, *pk, *pv, *py, *pff, *prl;
    cudaGetSymbolAddress(&px,  g_x);
    cudaGetSymbolAddress(&pq,  g_q);
    cudaGetSymbolAddress(&pk,  g_k);
    cudaGetSymbolAddress(&pv,  g_v);
    cudaGetSymbolAddress(&py,  g_y);
    cudaGetSymbolAddress(&pff, g_ff);
    cudaGetSymbolAddress(&prl, g_rowloss);
    float* x  = (float*)px;
    float* q  = (float*)pq;
    float* k  = (float*)pk;
    float* v  = (float*)pv;
    float* y  = (float*)py;
    float* ff = (float*)pff;
    float* rl = (float*)prl;

    float* out = (float*)d_out;
    size_t logits_n = (size_t)BT * VOCAB;

    embed_kernel<<<(BT * DMODEL + 255) / 256, 256>>>(idx, tok_emb, pos_emb, x);

    for (int l = 0; l < NLAYER; l++) {
        const float* wq = Wq + (size_t)l * DMODEL * DMODEL;
        const float* wk = Wk + (size_t)l * DMODEL * DMODEL;
        const float* wv = Wv + (size_t)l * DMODEL * DMODEL;

        launch_gemm(x, wq, nullptr, q, BT, DMODEL, DMODEL, 0);
        launch_gemm(x, wk, nullptr, k, BT, DMODEL, DMODEL, 0);
        launch_gemm(x, wv, nullptr, v, BT, DMODEL, DMODEL, 0);

        attn_tile_kernel<<<dim3(TLEN / 64, NHEAD, BATCH), 256>>>(q, k, v, y);

        resln_kernel<<<BT, 256>>>(y, x, ln1_g + (size_t)l * DMODEL,
                                  ln1_b + (size_t)l * DMODEL, x);

        launch_gemm(x, W1 + (size_t)l * DMODEL * FFDIM, b1 + (size_t)l * FFDIM,
                    ff, BT, FFDIM, DMODEL, 1);
        launch_gemm(ff, W2 + (size_t)l * FFDIM * DMODEL, b2 + (size_t)l * DMODEL,
                    y, BT, DMODEL, FFDIM, 0);

        resln_kernel<<<BT, 256>>>(y, x, ln2_g + (size_t)l * DMODEL,
                                  ln2_b + (size_t)l * DMODEL, x);
    }

    // lm head -> logits directly into d_out
    launch_gemm(x, head_w, head_b, out, BT, VOCAB, DMODEL, 0);

    loss_row_kernel<<<BT, 256>>>(out, targets, rl);
    if ((size_t)out_size >= logits_n + 1)
        loss_final_kernel<<<1, 256>>>(rl, out + logits_n);
}

// round 6
// speedup vs baseline: 5.2974x; 1.5612x over previous
#include <cuda_runtime.h>
#include <cuda_bf16.h>
#include <math.h>
#include <stdint.h>

// ---------------- problem constants ----------------
#define VOCAB 50257
#define DMODEL 768
#define NHEAD 12
#define HDIM 64
#define TLEN 1024
#define NLAYER 6
#define BATCH 4
#define BT (BATCH * TLEN)     // 4096
#define FFDIM (4 * DMODEL)    // 3072
#define LNEPS 1e-5f

// ---------------- scratch (device globals: alloc-free rule) ----------------
__device__ __align__(128) float g_x [BT * DMODEL];
__device__ __align__(128) float g_q [BT * DMODEL];
__device__ __align__(128) float g_k [BT * DMODEL];
__device__ __align__(128) float g_v [BT * DMODEL];
__device__ __align__(128) float g_y [BT * DMODEL];
__device__ __align__(128) float g_ff[BT * FFDIM];
__device__ __align__(128) float g_rowloss[BT];

// bf16 hi/lo activation buffers (max 4096 x 3072)
__device__ __align__(128) __nv_bfloat16 g_ah[BT * FFDIM];
__device__ __align__(128) __nv_bfloat16 g_al[BT * FFDIM];
// bf16 hi/lo transposed weight buffers (max 50257 x 768)
__device__ __align__(128) __nv_bfloat16 g_bh[(size_t)VOCAB * DMODEL];
__device__ __align__(128) __nv_bfloat16 g_bl[(size_t)VOCAB * DMODEL];

// ---------------- embedding ----------------
__global__ void embed_kernel(const int* __restrict__ idx,
                             const float* __restrict__ tok,
                             const float* __restrict__ pos,
                             float* __restrict__ x)
{
    int i = blockIdx.x * blockDim.x + threadIdx.x;
    if (i < BT * DMODEL) {
        int row = i / DMODEL;
        int d   = i - row * DMODEL;
        int t   = row % TLEN;
        x[i] = tok[(size_t)idx[row] * DMODEL + d] + pos[(size_t)t * DMODEL + d];
    }
}

// ---------------- fp32 -> bf16 hi/lo split ----------------
__global__ void split_kernel(const float* __restrict__ A,
                             __nv_bfloat16* __restrict__ hi,
                             __nv_bfloat16* __restrict__ lo,
                             int n4)
{
    int i = blockIdx.x * blockDim.x + threadIdx.x;
    if (i < n4) {
        float4 v = *(const float4*)(A + 4 * (size_t)i);
        const float* vv = &v.x;
        __nv_bfloat16 h[4], l[4];
        #pragma unroll
        for (int q = 0; q < 4; q++) {
            h[q] = __float2bfloat16_rn(vv[q]);
            l[q] = __float2bfloat16_rn(vv[q] - __bfloat162float(h[q]));
        }
        *(uint2*)(hi + 4 * (size_t)i) = *(uint2*)h;
        *(uint2*)(lo + 4 * (size_t)i) = *(uint2*)l;
    }
}

// ---------------- weight convert + transpose ----------------
__global__ void convT_kernel(const float* __restrict__ B,
                             __nv_bfloat16* __restrict__ Th,
                             __nv_bfloat16* __restrict__ Tl,
                             int K, int N)
{
    __shared__ float tile[32][33];
    int n0 = blockIdx.x * 32;
    int k0 = blockIdx.y * 32;
    int tx = threadIdx.x;    // 32
    int ty = threadIdx.y;    // 8
    #pragma unroll
    for (int i = 0; i < 4; i++) {
        int k = k0 + ty + 8 * i;
        int n = n0 + tx;
        tile[ty + 8 * i][tx] = (n < N) ? B[(size_t)k * N + n] : 0.f;
    }
    __syncthreads();
    #pragma unroll
    for (int i = 0; i < 4; i++) {
        int n = n0 + ty + 8 * i;
        int k = k0 + tx;
        if (n < N) {
            float v = tile[tx][ty + 8 * i];
            __nv_bfloat16 h = __float2bfloat16_rn(v);
            Th[(size_t)n * K + k] = h;
            Tl[(size_t)n * K + k] = __float2bfloat16_rn(v - __bfloat162float(h));
        }
    }
}

// ---------------- tensor-core GEMM (pre-split bf16, cp.async 3-stage, ldmatrix) ----------------
#define GPAD 40                   // halfs per 32-half smem row (80B)
#define TSH (128 * GPAD)          // halfs per tile array (5120)
#define GSMEM_BYTES (3 * 4 * TSH * 2)   // 122880 B

__device__ __forceinline__ void mma_bf16(float c[4], const uint32_t a[4], const uint32_t b[2])
{
    asm volatile(
        "mma.sync.aligned.m16n8k16.row.col.f32.bf16.bf16.f32 "
        "{%0,%1,%2,%3}, {%4,%5,%6,%7}, {%8,%9}, {%0,%1,%2,%3};\n"
        : "+f"(c[0]), "+f"(c[1]), "+f"(c[2]), "+f"(c[3])
        : "r"(a[0]), "r"(a[1]), "r"(a[2]), "r"(a[3]), "r"(b[0]), "r"(b[1]));
}

__device__ __forceinline__ void ldsm4(uint32_t r[4], uint32_t addr)
{
    asm volatile("ldmatrix.sync.aligned.m8n8.x4.shared.b16 {%0,%1,%2,%3}, [%4];\n"
                 : "=r"(r[0]), "=r"(r[1]), "=r"(r[2]), "=r"(r[3]) : "r"(addr));
}

// One pipeline stage load: 2048 16B chunks across 256 threads (8 each).
// All source addresses are clamped in-bounds; OOB rows use src-size 0 (zero-fill).
__device__ __forceinline__ void gemm_load_stage(
    uint32_t sbase, int s, int kt, int tid,
    const __nv_bfloat16* Ah, const __nv_bfloat16* Al,
    const __nv_bfloat16* Bh, const __nv_bfloat16* Bl,
    int rowBase, int colBase, int M, int N, int K)
{
    #pragma unroll
    for (int j = 0; j < 8; j++) {
        int c   = tid + j * 256;
        int arr = c >> 9;          // 0:Ah 1:Al 2:Bh 3:Bl
        int cc  = c & 511;
        int row = cc >> 2;
        int ch  = cc & 3;
        const __nv_bfloat16* bp = (arr == 0) ? Ah : (arr == 1) ? Al
                                 : (arr == 2) ? Bh : Bl;
        bool isB = (arr >= 2);
        int lim  = isB ? N : M;
        int grow = (isB ? colBase : rowBase) + row;
        int grow_c = (grow < lim) ? grow : (lim - 1);     // clamp: address always valid
        const void* gptr = bp + (size_t)grow_c * K + kt * 32 + ch * 8;
        uint32_t daddr = sbase + (uint32_t)(((s * 4 + arr) * TSH + row * GPAD + ch * 8) * 2);
        int sz = (grow < lim) ? 16 : 0;
        asm volatile("cp.async.cg.shared.global [%0], [%1], 16, %2;\n"
                     :: "r"(daddr), "l"(gptr), "r"(sz));
    }
    asm volatile("cp.async.commit_group;\n" ::);
}

__global__ __launch_bounds__(256)
void gemm_bf16_kernel(const __nv_bfloat16* __restrict__ Ah,
                      const __nv_bfloat16* __restrict__ Al,
                      const __nv_bfloat16* __restrict__ Bh,
                      const __nv_bfloat16* __restrict__ Bl,
                      const float* __restrict__ bias,
                      float* __restrict__ C,
                      int M, int N, int K, int relu)
{
    extern __shared__ __nv_bfloat16 smem[];
    uint32_t sbase = (uint32_t)__cvta_generic_to_shared(smem);

    int tid  = threadIdx.x;
    int warp = tid >> 5;
    int lane = tid & 31;
    int m0 = (warp >> 1) * 32;
    int n0 = (warp & 1) * 64;
    int rowBase = blockIdx.y * 128;
    int colBase = blockIdx.x * 128;
    int KT = K / 32;

    bool vec2N = ((N & 1) == 0);

    float acc[2][8][4];
    #pragma unroll
    for (int i = 0; i < 2; i++)
        #pragma unroll
        for (int j = 0; j < 8; j++)
            #pragma unroll
            for (int r = 0; r < 4; r++) acc[i][j][r] = 0.f;

    gemm_load_stage(sbase, 0, 0, tid, Ah, Al, Bh, Bl, rowBase, colBase, M, N, K);
    gemm_load_stage(sbase, 1, 1, tid, Ah, Al, Bh, Bl, rowBase, colBase, M, N, K);

    for (int kt = 0; kt < KT; kt++) {
        if (kt < KT - 1) asm volatile("cp.async.wait_group 1;\n" ::);
        else             asm volatile("cp.async.wait_group 0;\n" ::);
        __syncthreads();

        if (kt + 2 < KT)
            gemm_load_stage(sbase, (kt + 2) % 3, kt + 2, tid,
                            Ah, Al, Bh, Bl, rowBase, colBase, M, N, K);

        int s = kt % 3;
        uint32_t ah_b = sbase + (uint32_t)((s * 4 + 0) * TSH * 2);
        uint32_t al_b = sbase + (uint32_t)((s * 4 + 1) * TSH * 2);
        uint32_t bh_b = sbase + (uint32_t)((s * 4 + 2) * TSH * 2);
        uint32_t bl_b = sbase + (uint32_t)((s * 4 + 3) * TSH * 2);

        #pragma unroll
        for (int ks = 0; ks < 2; ks++) {
            uint32_t ahf[2][4], alf[2][4], bhf[4][4], blf[4][4];
            #pragma unroll
            for (int i = 0; i < 2; i++) {
                int r = m0 + 16 * i + (lane & 15);
                uint32_t off = (uint32_t)((r * GPAD + ks * 16 + (lane >> 4) * 8) * 2);
                ldsm4(ahf[i], ah_b + off);
                ldsm4(alf[i], al_b + off);
            }
            #pragma unroll
            for (int j = 0; j < 4; j++) {
                int r = n0 + 16 * j + ((lane >> 4) * 8 + (lane & 7));
                uint32_t off = (uint32_t)((r * GPAD + ks * 16 + ((lane >> 3) & 1) * 8) * 2);
                ldsm4(bhf[j], bh_b + off);
                ldsm4(blf[j], bl_b + off);
            }
            #pragma unroll
            for (int i = 0; i < 2; i++)
                #pragma unroll
                for (int jj = 0; jj < 8; jj++) {
                    const uint32_t* b2h = &bhf[jj >> 1][(jj & 1) * 2];
                    const uint32_t* b2l = &blf[jj >> 1][(jj & 1) * 2];
                    mma_bf16(acc[i][jj], ahf[i], b2h);
                    mma_bf16(acc[i][jj], ahf[i], b2l);
                    mma_bf16(acc[i][jj], alf[i], b2h);
                }
        }
    }

    // ---- epilogue ----
    int g = lane >> 2, tg = lane & 3;
    #pragma unroll
    for (int i = 0; i < 2; i++) {
        #pragma unroll
        for (int jj = 0; jj < 8; jj++) {
            int col = colBase + n0 + 8 * jj + 2 * tg;
            #pragma unroll
            for (int h = 0; h < 2; h++) {
                int row = rowBase + m0 + 16 * i + g + 8 * h;
                if (row >= M) continue;
                float v0 = acc[i][jj][2 * h + 0];
                float v1 = acc[i][jj][2 * h + 1];
                if (bias) {
                    if (col < N)     v0 += bias[col];
                    if (col + 1 < N) v1 += bias[col + 1];
                }
                if (relu) { v0 = fmaxf(v0, 0.f); v1 = fmaxf(v1, 0.f); }
                float* dst = C + (size_t)row * N + col;
                if (vec2N && col + 1 < N) {
                    *(float2*)dst = make_float2(v0, v1);
                } else {
                    if (col < N)     dst[0] = v0;
                    if (col + 1 < N) dst[1] = v1;
                }
            }
        }
    }
}

// ---------------- tiled flash attention (fp32, 64q x 32k tiles) ----------------
__global__ __launch_bounds__(256)
void attn_tile_kernel(const float* __restrict__ q,
                      const float* __restrict__ k,
                      const float* __restrict__ v,
                      float* __restrict__ y)
{
    int qt = blockIdx.x;
    int h  = blockIdx.y;
    int b  = blockIdx.z;
    int tid = threadIdx.x;  // 256

    __shared__ float Qs[64][65];
    __shared__ float Ks[32][65];
    __shared__ float Vs[32][65];
    __shared__ float Ss[64][33];
    __shared__ float rowm[64], rowl[64], rowa[64];

    size_t headbase = (size_t)b * TLEN * DMODEL + (size_t)h * HDIM;
    int q0 = qt * 64;

    {
        int r = tid >> 2, c0 = (tid & 3) * 16;
        const float* src = q + headbase + (size_t)(q0 + r) * DMODEL + c0;
        #pragma unroll
        for (int i = 0; i < 4; i++) {
            float4 t4 = *(const float4*)(src + 4 * i);
            Qs[r][c0 + 4 * i + 0] = t4.x;
            Qs[r][c0 + 4 * i + 1] = t4.y;
            Qs[r][c0 + 4 * i + 2] = t4.z;
            Qs[r][c0 + 4 * i + 3] = t4.w;
        }
    }
    if (tid < 64) { rowm[tid] = -1e30f; rowl[tid] = 0.f; }

    float o[4][4];
    #pragma unroll
    for (int i = 0; i < 4; i++)
        #pragma unroll
        for (int j = 0; j < 4; j++) o[i][j] = 0.f;

    int tx = tid & 15, ty = tid >> 4;
    __syncthreads();

    for (int s0 = 0; s0 < q0 + 64; s0 += 32) {
        {
            int kr = tid >> 3, kc = (tid & 7) * 8;
            const float* ksrc = k + headbase + (size_t)(s0 + kr) * DMODEL + kc;
            const float* vsrc = v + headbase + (size_t)(s0 + kr) * DMODEL + kc;
            #pragma unroll
            for (int i = 0; i < 2; i++) {
                float4 t4 = *(const float4*)(ksrc + 4 * i);
                Ks[kr][kc + 4 * i + 0] = t4.x; Ks[kr][kc + 4 * i + 1] = t4.y;
                Ks[kr][kc + 4 * i + 2] = t4.z; Ks[kr][kc + 4 * i + 3] = t4.w;
                float4 u4 = *(const float4*)(vsrc + 4 * i);
                Vs[kr][kc + 4 * i + 0] = u4.x; Vs[kr][kc + 4 * i + 1] = u4.y;
                Vs[kr][kc + 4 * i + 2] = u4.z; Vs[kr][kc + 4 * i + 3] = u4.w;
            }
        }
        __syncthreads();

        float accv[4][2];
        #pragma unroll
        for (int i = 0; i < 4; i++) { accv[i][0] = 0.f; accv[i][1] = 0.f; }
        for (int d = 0; d < 64; d++) {
            float bv0 = Ks[tx][d], bv1 = Ks[tx + 16][d];
            #pragma unroll
            for (int i = 0; i < 4; i++) {
                float av = Qs[ty + 16 * i][d];
                accv[i][0] += av * bv0;
                accv[i][1] += av * bv1;
            }
        }
        #pragma unroll
        for (int i = 0; i < 4; i++)
            #pragma unroll
            for (int jj = 0; jj < 2; jj++) {
                int r = ty + 16 * i, cc = tx + 16 * jj;
                int gq = q0 + r, gs = s0 + cc;
                Ss[r][cc] = (gs <= gq) ? accv[i][jj] * 0.125f : -1e30f;
            }
        __syncthreads();

        if (tid < 64) {
            float mo = rowm[tid];
            float mx = mo;
            #pragma unroll 8
            for (int cc = 0; cc < 32; cc++) mx = fmaxf(mx, Ss[tid][cc]);
            float alpha = __expf(mo - mx);
            float sum = 0.f;
            #pragma unroll 8
            for (int cc = 0; cc < 32; cc++) {
                float p = __expf(Ss[tid][cc] - mx);
                Ss[tid][cc] = p;
                sum += p;
            }
            rowl[tid] = rowl[tid] * alpha + sum;
            rowm[tid] = mx;
            rowa[tid] = alpha;
        }
        __syncthreads();

        #pragma unroll
        for (int i = 0; i < 4; i++) {
            float al = rowa[ty + 16 * i];
            #pragma unroll
            for (int jj = 0; jj < 4; jj++) o[i][jj] *= al;
        }
        for (int cc = 0; cc < 32; cc++) {
            float p0 = Ss[ty][cc], p1 = Ss[ty + 16][cc];
            float p2 = Ss[ty + 32][cc], p3 = Ss[ty + 48][cc];
            #pragma unroll
            for (int jj = 0; jj < 4; jj++) {
                float vv = Vs[cc][tx + 16 * jj];
                o[0][jj] += p0 * vv;
                o[1][jj] += p1 * vv;
                o[2][jj] += p2 * vv;
                o[3][jj] += p3 * vv;
            }
        }
        __syncthreads();
    }

    #pragma unroll
    for (int i = 0; i < 4; i++) {
        int r = ty + 16 * i;
        float inv = 1.f / rowl[r];
        #pragma unroll
        for (int jj = 0; jj < 4; jj++) {
            int cc = tx + 16 * jj;
            y[headbase + (size_t)(q0 + r) * DMODEL + cc] = o[i][jj] * inv;
        }
    }
}

// ---------------- residual + layernorm ----------------
__global__ void resln_kernel(const float* __restrict__ xin,
                             const float* __restrict__ res,
                             const float* __restrict__ gamma,
                             const float* __restrict__ beta,
                             float* __restrict__ xout)
{
    int row = blockIdx.x;
    int tid = threadIdx.x;   // 256
    __shared__ float red[256];

    float vals[3];
    float s1 = 0.f;
    #pragma unroll
    for (int i = 0; i < 3; i++) {
        int cidx = tid + i * 256;
        float vv = xin[(size_t)row * DMODEL + cidx] + res[(size_t)row * DMODEL + cidx];
        vals[i] = vv;
        s1 += vv;
    }
    red[tid] = s1;
    __syncthreads();
    for (int off = 128; off > 0; off >>= 1) {
        if (tid < off) red[tid] += red[tid + off];
        __syncthreads();
    }
    float mu = red[0] * (1.f / DMODEL);
    __syncthreads();

    float s2 = 0.f;
    #pragma unroll
    for (int i = 0; i < 3; i++) {
        float dv = vals[i] - mu;
        s2 += dv * dv;
    }
    red[tid] = s2;
    __syncthreads();
    for (int off = 128; off > 0; off >>= 1) {
        if (tid < off) red[tid] += red[tid + off];
        __syncthreads();
    }
    float inv = rsqrtf(red[0] * (1.f / DMODEL) + LNEPS);
    __syncthreads();

    #pragma unroll
    for (int i = 0; i < 3; i++) {
        int cidx = tid + i * 256;
        xout[(size_t)row * DMODEL + cidx] = (vals[i] - mu) * inv * gamma[cidx] + beta[cidx];
    }
}

// ---------------- cross-entropy ----------------
__global__ void loss_row_kernel(const float* __restrict__ logits,
                                const int* __restrict__ tgt,
                                float* __restrict__ rowloss)
{
    int row = blockIdx.x;
    int tid = threadIdx.x;   // 256
    const float* lr = logits + (size_t)row * VOCAB;
    __shared__ float red[256];

    float m = -1e30f;
    for (int cc = tid; cc < VOCAB; cc += 256) m = fmaxf(m, lr[cc]);
    red[tid] = m;
    __syncthreads();
    for (int off = 128; off > 0; off >>= 1) {
        if (tid < off) red[tid] = fmaxf(red[tid], red[tid + off]);
        __syncthreads();
    }
    float M = red[0];
    __syncthreads();

    float s = 0.f;
    for (int cc = tid; cc < VOCAB; cc += 256) s += __expf(lr[cc] - M);
    red[tid] = s;
    __syncthreads();
    for (int off = 128; off > 0; off >>= 1) {
        if (tid < off) red[tid] += red[tid + off];
        __syncthreads();
    }
    if (tid == 0)
        rowloss[row] = -(lr[tgt[row]] - M - logf(red[0]));
}

__global__ void loss_final_kernel(const float* __restrict__ rowloss,
                                  float* __restrict__ out)
{
    int tid = threadIdx.x;   // 256
    __shared__ float red[256];
    float s = 0.f;
    for (int i = tid; i < BT; i += 256) s += rowloss[i];
    red[tid] = s;
    __syncthreads();
    for (int off = 128; off > 0; off >>= 1) {
        if (tid < off) red[tid] += red[tid + off];
        __syncthreads();
    }
    if (tid == 0) out[0] = red[0] * (1.f / BT);
}

// ---------------- host orchestration ----------------
struct Scratch {
    float *x, *q, *k, *v, *y, *ff, *rl;
    __nv_bfloat16 *ah, *al, *bh, *bl;
};

static inline void split_launch(const float* A, __nv_bfloat16* hi, __nv_bfloat16* lo, int n)
{
    int n4 = n / 4;
    split_kernel<<<(n4 + 255) / 256, 256>>>(A, hi, lo, n4);
}

static inline void convT_launch(const float* B, __nv_bfloat16* Th, __nv_bfloat16* Tl, int K, int N)
{
    dim3 grid((N + 31) / 32, K / 32);
    convT_kernel<<<grid, dim3(32, 8)>>>(B, Th, Tl, K, N);
}

static inline void gemm_launch(const Scratch& s, const float* bias, float* C,
                               int M, int N, int K, int relu)
{
    dim3 grid((N + 127) / 128, (M + 127) / 128);
    gemm_bf16_kernel<<<grid, 256, GSMEM_BYTES>>>(s.ah, s.al, s.bh, s.bl, bias, C, M, N, K, relu);
}

extern "C" void kernel_launch(void* const* d_in, const int* in_sizes, int n_in,
                              void* d_out, int out_size)
{
    const int*   idx     = (const int*)  d_in[0];
    const int*   targets = (const int*)  d_in[1];
    const float* tok_emb = (const float*)d_in[2];
    const float* pos_emb = (const float*)d_in[3];
    const float* Wq      = (const float*)d_in[4];
    const float* Wk      = (const float*)d_in[5];
    const float* Wv      = (const float*)d_in[6];
    const float* ln1_g   = (const float*)d_in[7];
    const float* ln1_b   = (const float*)d_in[8];
    const float* W1      = (const float*)d_in[9];
    const float* b1      = (const float*)d_in[10];
    const float* W2      = (const float*)d_in[11];
    const float* b2      = (const float*)d_in[12];
    const float* ln2_g   = (const float*)d_in[13];
    const float* ln2_b   = (const float*)d_in[14];
    const float* head_w  = (const float*)d_in[15];
    const float* head_b  = (const float*)d_in[16];

    cudaFuncSetAttribute(gemm_bf16_kernel,
                         cudaFuncAttributeMaxDynamicSharedMemorySize, GSMEM_BYTES);

    Scratch s;
    void* p;
    cudaGetSymbolAddress(&p, g_x);  s.x  = (float*)p;
    cudaGetSymbolAddress(&p, g_q);  s.q  = (float*)p;
    cudaGetSymbolAddress(&p, g_k);  s.k  = (float*)p;
    cudaGetSymbolAddress(&p, g_v);  s.v  = (float*)p;
    cudaGetSymbolAddress(&p, g_y);  s.y  = (float*)p;
    cudaGetSymbolAddress(&p, g_ff); s.ff = (float*)p;
    cudaGetSymbolAddress(&p, g_rowloss); s.rl = (float*)p;
    cudaGetSymbolAddress(&p, g_ah); s.ah = (__nv_bfloat16*)p;
    cudaGetSymbolAddress(&p, g_al); s.al = (__nv_bfloat16*)p;
    cudaGetSymbolAddress(&p, g_bh); s.bh = (__nv_bfloat16*)p;
    cudaGetSymbolAddress(&p, g_bl); s.bl = (__nv_bfloat16*)p;

    float* out = (float*)d_out;
    size_t logits_n = (size_t)BT * VOCAB;

    embed_kernel<<<(BT * DMODEL + 255) / 256, 256>>>(idx, tok_emb, pos_emb, s.x);

    for (int l = 0; l < NLAYER; l++) {
        const float* wq = Wq + (size_t)l * DMODEL * DMODEL;
        const float* wk = Wk + (size_t)l * DMODEL * DMODEL;
        const float* wv = Wv + (size_t)l * DMODEL * DMODEL;

        split_launch(s.x, s.ah, s.al, BT * DMODEL);
        convT_launch(wq, s.bh, s.bl, DMODEL, DMODEL);
        gemm_launch(s, nullptr, s.q, BT, DMODEL, DMODEL, 0);
        convT_launch(wk, s.bh, s.bl, DMODEL, DMODEL);
        gemm_launch(s, nullptr, s.k, BT, DMODEL, DMODEL, 0);
        convT_launch(wv, s.bh, s.bl, DMODEL, DMODEL);
        gemm_launch(s, nullptr, s.v, BT, DMODEL, DMODEL, 0);

        attn_tile_kernel<<<dim3(TLEN / 64, NHEAD, BATCH), 256>>>(s.q, s.k, s.v, s.y);

        resln_kernel<<<BT, 256>>>(s.y, s.x, ln1_g + (size_t)l * DMODEL,
                                  ln1_b + (size_t)l * DMODEL, s.x);

        split_launch(s.x, s.ah, s.al, BT * DMODEL);
        convT_launch(W1 + (size_t)l * DMODEL * FFDIM, s.bh, s.bl, DMODEL, FFDIM);
        gemm_launch(s, b1 + (size_t)l * FFDIM, s.ff, BT, FFDIM, DMODEL, 1);

        split_launch(s.ff, s.ah, s.al, BT * FFDIM);
        convT_launch(W2 + (size_t)l * FFDIM * DMODEL, s.bh, s.bl, FFDIM, DMODEL);
        gemm_launch(s, b2 + (size_t)l * DMODEL, s.y, BT, DMODEL, FFDIM, 0);

        resln_kernel<<<BT, 256>>>(s.y, s.x, ln2_g + (size_t)l * DMODEL,
                                  ln2_b + (size_t)l * DMODEL, s.x);
    }

    // lm head
    split_launch(s.x, s.ah, s.al, BT * DMODEL);
    convT_launch(head_w, s.bh, s.bl, DMODEL, VOCAB);
    gemm_launch(s, head_b, out, BT, VOCAB, DMODEL, 0);

    loss_row_kernel<<<BT, 256>>>(out, targets, s.rl);
    if ((size_t)out_size >= logits_n + 1)
        loss_final_kernel<<<1, 256>>>(s.rl, out + logits_n);
}

// round 8
// speedup vs baseline: 6.1045x; 1.1524x over previous
#include <cuda_runtime.h>
#include <cuda_bf16.h>
#include <math.h>
#include <stdint.h>

// ---------------- problem constants ----------------
#define VOCAB 50257
#define DMODEL 768
#define NHEAD 12
#define HDIM 64
#define TLEN 1024
#define NLAYER 6
#define BATCH 4
#define BT (BATCH * TLEN)     // 4096
#define FFDIM (4 * DMODEL)    // 3072
#define LNEPS 1e-5f

// ---------------- scratch (device globals: alloc-free rule) ----------------
__device__ __align__(128) float g_x [BT * DMODEL];
__device__ __align__(128) float g_q [BT * DMODEL];
__device__ __align__(128) float g_k [BT * DMODEL];
__device__ __align__(128) float g_v [BT * DMODEL];
__device__ __align__(128) float g_y [BT * DMODEL];
__device__ __align__(128) float g_ff[BT * FFDIM];
__device__ __align__(128) float g_rowloss[BT];

// bf16 hi/lo activation buffers (max 4096 x 3072)
__device__ __align__(128) __nv_bfloat16 g_ah[BT * FFDIM];
__device__ __align__(128) __nv_bfloat16 g_al[BT * FFDIM];
// bf16 hi/lo transposed weight buffers (max 50257 x 768)
__device__ __align__(128) __nv_bfloat16 g_bh[(size_t)VOCAB * DMODEL];
__device__ __align__(128) __nv_bfloat16 g_bl[(size_t)VOCAB * DMODEL];

// ---------------- embedding ----------------
__global__ void embed_kernel(const int* __restrict__ idx,
                             const float* __restrict__ tok,
                             const float* __restrict__ pos,
                             float* __restrict__ x)
{
    int i = blockIdx.x * blockDim.x + threadIdx.x;
    if (i < BT * DMODEL) {
        int row = i / DMODEL;
        int d   = i - row * DMODEL;
        int t   = row % TLEN;
        x[i] = tok[(size_t)idx[row] * DMODEL + d] + pos[(size_t)t * DMODEL + d];
    }
}

// ---------------- fp32 -> bf16 hi/lo split ----------------
__global__ void split_kernel(const float* __restrict__ A,
                             __nv_bfloat16* __restrict__ hi,
                             __nv_bfloat16* __restrict__ lo,
                             int n4)
{
    int i = blockIdx.x * blockDim.x + threadIdx.x;
    if (i < n4) {
        float4 v = *(const float4*)(A + 4 * (size_t)i);
        const float* vv = &v.x;
        __nv_bfloat16 h[4], l[4];
        #pragma unroll
        for (int q = 0; q < 4; q++) {
            h[q] = __float2bfloat16_rn(vv[q]);
            l[q] = __float2bfloat16_rn(vv[q] - __bfloat162float(h[q]));
        }
        *(uint2*)(hi + 4 * (size_t)i) = *(uint2*)h;
        *(uint2*)(lo + 4 * (size_t)i) = *(uint2*)l;
    }
}

// ---------------- weight convert + transpose ----------------
__global__ void convT_kernel(const float* __restrict__ B,
                             __nv_bfloat16* __restrict__ Th,
                             __nv_bfloat16* __restrict__ Tl,
                             int K, int N)
{
    __shared__ float tile[32][33];
    int n0 = blockIdx.x * 32;
    int k0 = blockIdx.y * 32;
    int tx = threadIdx.x;    // 32
    int ty = threadIdx.y;    // 8
    #pragma unroll
    for (int i = 0; i < 4; i++) {
        int k = k0 + ty + 8 * i;
        int n = n0 + tx;
        tile[ty + 8 * i][tx] = (n < N) ? B[(size_t)k * N + n] : 0.f;
    }
    __syncthreads();
    #pragma unroll
    for (int i = 0; i < 4; i++) {
        int n = n0 + ty + 8 * i;
        int k = k0 + tx;
        if (n < N) {
            float v = tile[tx][ty + 8 * i];
            __nv_bfloat16 h = __float2bfloat16_rn(v);
            Th[(size_t)n * K + k] = h;
            Tl[(size_t)n * K + k] = __float2bfloat16_rn(v - __bfloat162float(h));
        }
    }
}

// ---------------- tensor-core GEMM (pre-split bf16, cp.async 2-stage, ldmatrix) ----------------
// 2 stages (81920B smem) so 2 CTAs/SM co-reside; the partner CTA hides load latency.
#define GPAD 40                   // halfs per 32-half smem row (80B)
#define TSH (128 * GPAD)          // halfs per tile array (5120)
#define GSMEM_BYTES (2 * 4 * TSH * 2)   // 2 stages x 4 arrays = 81920 B

__device__ __forceinline__ void mma_bf16(float c[4], const uint32_t a[4], const uint32_t b[2])
{
    asm volatile(
        "mma.sync.aligned.m16n8k16.row.col.f32.bf16.bf16.f32 "
        "{%0,%1,%2,%3}, {%4,%5,%6,%7}, {%8,%9}, {%0,%1,%2,%3};\n"
        : "+f"(c[0]), "+f"(c[1]), "+f"(c[2]), "+f"(c[3])
        : "r"(a[0]), "r"(a[1]), "r"(a[2]), "r"(a[3]), "r"(b[0]), "r"(b[1]));
}

__device__ __forceinline__ void ldsm4(uint32_t r[4], uint32_t addr)
{
    asm volatile("ldmatrix.sync.aligned.m8n8.x4.shared.b16 {%0,%1,%2,%3}, [%4];\n"
                 : "=r"(r[0]), "=r"(r[1]), "=r"(r[2]), "=r"(r[3]) : "r"(addr));
}

// One pipeline stage load: 2048 16B chunks across 256 threads (8 each).
// All source addresses clamped in-bounds; OOB rows use src-size 0 (zero-fill).
__device__ __forceinline__ void gemm_load_stage(
    uint32_t sbase, int s, int kt, int tid,
    const __nv_bfloat16* Ah, const __nv_bfloat16* Al,
    const __nv_bfloat16* Bh, const __nv_bfloat16* Bl,
    int rowBase, int colBase, int M, int N, int K)
{
    #pragma unroll
    for (int j = 0; j < 8; j++) {
        int c   = tid + j * 256;
        int arr = c >> 9;          // 0:Ah 1:Al 2:Bh 3:Bl
        int cc  = c & 511;
        int row = cc >> 2;
        int ch  = cc & 3;
        const __nv_bfloat16* bp = (arr == 0) ? Ah : (arr == 1) ? Al
                                 : (arr == 2) ? Bh : Bl;
        bool isB = (arr >= 2);
        int lim  = isB ? N : M;
        int grow = (isB ? colBase : rowBase) + row;
        int grow_c = (grow < lim) ? grow : (lim - 1);
        const void* gptr = bp + (size_t)grow_c * K + kt * 32 + ch * 8;
        uint32_t daddr = sbase + (uint32_t)(((s * 4 + arr) * TSH + row * GPAD + ch * 8) * 2);
        int sz = (grow < lim) ? 16 : 0;
        asm volatile("cp.async.cg.shared.global [%0], [%1], 16, %2;\n"
                     :: "r"(daddr), "l"(gptr), "r"(sz));
    }
    asm volatile("cp.async.commit_group;\n" ::);
}

__global__ __launch_bounds__(256, 2)
void gemm_bf16_kernel(const __nv_bfloat16* __restrict__ Ah,
                      const __nv_bfloat16* __restrict__ Al,
                      const __nv_bfloat16* __restrict__ Bh,
                      const __nv_bfloat16* __restrict__ Bl,
                      const float* __restrict__ bias,
                      float* __restrict__ C,
                      int M, int N, int K, int relu)
{
    extern __shared__ __nv_bfloat16 smem[];
    uint32_t sbase = (uint32_t)__cvta_generic_to_shared(smem);

    int tid  = threadIdx.x;
    int warp = tid >> 5;
    int lane = tid & 31;
    int m0 = (warp >> 1) * 32;
    int n0 = (warp & 1) * 64;
    int rowBase = blockIdx.y * 128;
    int colBase = blockIdx.x * 128;
    int KT = K / 32;

    bool vec2N = ((N & 1) == 0);

    float acc[2][8][4];
    #pragma unroll
    for (int i = 0; i < 2; i++)
        #pragma unroll
        for (int j = 0; j < 8; j++)
            #pragma unroll
            for (int r = 0; r < 4; r++) acc[i][j][r] = 0.f;

    gemm_load_stage(sbase, 0, 0, tid, Ah, Al, Bh, Bl, rowBase, colBase, M, N, K);

    for (int kt = 0; kt < KT; kt++) {
        asm volatile("cp.async.wait_group 0;\n" ::);
        __syncthreads();

        if (kt + 1 < KT)
            gemm_load_stage(sbase, (kt + 1) & 1, kt + 1, tid,
                            Ah, Al, Bh, Bl, rowBase, colBase, M, N, K);

        int s = kt & 1;
        uint32_t ah_b = sbase + (uint32_t)((s * 4 + 0) * TSH * 2);
        uint32_t al_b = sbase + (uint32_t)((s * 4 + 1) * TSH * 2);
        uint32_t bh_b = sbase + (uint32_t)((s * 4 + 2) * TSH * 2);
        uint32_t bl_b = sbase + (uint32_t)((s * 4 + 3) * TSH * 2);

        #pragma unroll
        for (int ks = 0; ks < 2; ks++) {
            uint32_t ahf[2][4], alf[2][4], bhf[4][4], blf[4][4];
            #pragma unroll
            for (int i = 0; i < 2; i++) {
                int r = m0 + 16 * i + (lane & 15);
                uint32_t off = (uint32_t)((r * GPAD + ks * 16 + (lane >> 4) * 8) * 2);
                ldsm4(ahf[i], ah_b + off);
                ldsm4(alf[i], al_b + off);
            }
            #pragma unroll
            for (int j = 0; j < 4; j++) {
                int r = n0 + 16 * j + ((lane >> 4) * 8 + (lane & 7));
                uint32_t off = (uint32_t)((r * GPAD + ks * 16 + ((lane >> 3) & 1) * 8) * 2);
                ldsm4(bhf[j], bh_b + off);
                ldsm4(blf[j], bl_b + off);
            }
            #pragma unroll
            for (int i = 0; i < 2; i++)
                #pragma unroll
                for (int jj = 0; jj < 8; jj++) {
                    const uint32_t* b2h = &bhf[jj >> 1][(jj & 1) * 2];
                    const uint32_t* b2l = &blf[jj >> 1][(jj & 1) * 2];
                    mma_bf16(acc[i][jj], ahf[i], b2h);
                    mma_bf16(acc[i][jj], ahf[i], b2l);
                    mma_bf16(acc[i][jj], alf[i], b2h);
                }
        }
    }

    // ---- epilogue ----
    int g = lane >> 2, tg = lane & 3;
    #pragma unroll
    for (int i = 0; i < 2; i++) {
        #pragma unroll
        for (int jj = 0; jj < 8; jj++) {
            int col = colBase + n0 + 8 * jj + 2 * tg;
            #pragma unroll
            for (int h = 0; h < 2; h++) {
                int row = rowBase + m0 + 16 * i + g + 8 * h;
                if (row >= M) continue;
                float v0 = acc[i][jj][2 * h + 0];
                float v1 = acc[i][jj][2 * h + 1];
                if (bias) {
                    if (col < N)     v0 += bias[col];
                    if (col + 1 < N) v1 += bias[col + 1];
                }
                if (relu) { v0 = fmaxf(v0, 0.f); v1 = fmaxf(v1, 0.f); }
                float* dst = C + (size_t)row * N + col;
                if (vec2N && col + 1 < N) {
                    *(float2*)dst = make_float2(v0, v1);
                } else {
                    if (col < N)     dst[0] = v0;
                    if (col + 1 < N) dst[1] = v1;
                }
            }
        }
    }
}

// ---------------- tiled flash attention (fp32, 64q x 32k tiles) ----------------
__global__ __launch_bounds__(256)
void attn_tile_kernel(const float* __restrict__ q,
                      const float* __restrict__ k,
                      const float* __restrict__ v,
                      float* __restrict__ y)
{
    int qt = blockIdx.x;
    int h  = blockIdx.y;
    int b  = blockIdx.z;
    int tid = threadIdx.x;  // 256

    __shared__ float Qs[64][65];
    __shared__ float Ks[32][65];
    __shared__ float Vs[32][65];
    __shared__ float Ss[64][33];
    __shared__ float rowm[64], rowl[64], rowa[64];

    size_t headbase = (size_t)b * TLEN * DMODEL + (size_t)h * HDIM;
    int q0 = qt * 64;

    {
        int r = tid >> 2, c0 = (tid & 3) * 16;
        const float* src = q + headbase + (size_t)(q0 + r) * DMODEL + c0;
        #pragma unroll
        for (int i = 0; i < 4; i++) {
            float4 t4 = *(const float4*)(src + 4 * i);
            Qs[r][c0 + 4 * i + 0] = t4.x;
            Qs[r][c0 + 4 * i + 1] = t4.y;
            Qs[r][c0 + 4 * i + 2] = t4.z;
            Qs[r][c0 + 4 * i + 3] = t4.w;
        }
    }
    if (tid < 64) { rowm[tid] = -1e30f; rowl[tid] = 0.f; }

    float o[4][4];
    #pragma unroll
    for (int i = 0; i < 4; i++)
        #pragma unroll
        for (int j = 0; j < 4; j++) o[i][j] = 0.f;

    int tx = tid & 15, ty = tid >> 4;
    __syncthreads();

    for (int s0 = 0; s0 < q0 + 64; s0 += 32) {
        {
            int kr = tid >> 3, kc = (tid & 7) * 8;
            const float* ksrc = k + headbase + (size_t)(s0 + kr) * DMODEL + kc;
            const float* vsrc = v + headbase + (size_t)(s0 + kr) * DMODEL + kc;
            #pragma unroll
            for (int i = 0; i < 2; i++) {
                float4 t4 = *(const float4*)(ksrc + 4 * i);
                Ks[kr][kc + 4 * i + 0] = t4.x; Ks[kr][kc + 4 * i + 1] = t4.y;
                Ks[kr][kc + 4 * i + 2] = t4.z; Ks[kr][kc + 4 * i + 3] = t4.w;
                float4 u4 = *(const float4*)(vsrc + 4 * i);
                Vs[kr][kc + 4 * i + 0] = u4.x; Vs[kr][kc + 4 * i + 1] = u4.y;
                Vs[kr][kc + 4 * i + 2] = u4.z; Vs[kr][kc + 4 * i + 3] = u4.w;
            }
        }
        __syncthreads();

        float accv[4][2];
        #pragma unroll
        for (int i = 0; i < 4; i++) { accv[i][0] = 0.f; accv[i][1] = 0.f; }
        for (int d = 0; d < 64; d++) {
            float bv0 = Ks[tx][d], bv1 = Ks[tx + 16][d];
            #pragma unroll
            for (int i = 0; i < 4; i++) {
                float av = Qs[ty + 16 * i][d];
                accv[i][0] += av * bv0;
                accv[i][1] += av * bv1;
            }
        }
        #pragma unroll
        for (int i = 0; i < 4; i++)
            #pragma unroll
            for (int jj = 0; jj < 2; jj++) {
                int r = ty + 16 * i, cc = tx + 16 * jj;
                int gq = q0 + r, gs = s0 + cc;
                Ss[r][cc] = (gs <= gq) ? accv[i][jj] * 0.125f : -1e30f;
            }
        __syncthreads();

        if (tid < 64) {
            float mo = rowm[tid];
            float mx = mo;
            #pragma unroll 8
            for (int cc = 0; cc < 32; cc++) mx = fmaxf(mx, Ss[tid][cc]);
            float alpha = __expf(mo - mx);
            float sum = 0.f;
            #pragma unroll 8
            for (int cc = 0; cc < 32; cc++) {
                float p = __expf(Ss[tid][cc] - mx);
                Ss[tid][cc] = p;
                sum += p;
            }
            rowl[tid] = rowl[tid] * alpha + sum;
            rowm[tid] = mx;
            rowa[tid] = alpha;
        }
        __syncthreads();

        #pragma unroll
        for (int i = 0; i < 4; i++) {
            float al = rowa[ty + 16 * i];
            #pragma unroll
            for (int jj = 0; jj < 4; jj++) o[i][jj] *= al;
        }
        for (int cc = 0; cc < 32; cc++) {
            float p0 = Ss[ty][cc], p1 = Ss[ty + 16][cc];
            float p2 = Ss[ty + 32][cc], p3 = Ss[ty + 48][cc];
            #pragma unroll
            for (int jj = 0; jj < 4; jj++) {
                float vv = Vs[cc][tx + 16 * jj];
                o[0][jj] += p0 * vv;
                o[1][jj] += p1 * vv;
                o[2][jj] += p2 * vv;
                o[3][jj] += p3 * vv;
            }
        }
        __syncthreads();
    }

    #pragma unroll
    for (int i = 0; i < 4; i++) {
        int r = ty + 16 * i;
        float inv = 1.f / rowl[r];
        #pragma unroll
        for (int jj = 0; jj < 4; jj++) {
            int cc = tx + 16 * jj;
            y[headbase + (size_t)(q0 + r) * DMODEL + cc] = o[i][jj] * inv;
        }
    }
}

// ---------------- residual + layernorm ----------------
__global__ void resln_kernel(const float* __restrict__ xin,
                             const float* __restrict__ res,
                             const float* __restrict__ gamma,
                             const float* __restrict__ beta,
                             float* __restrict__ xout)
{
    int row = blockIdx.x;
    int tid = threadIdx.x;   // 256
    __shared__ float red[256];

    float vals[3];
    float s1 = 0.f;
    #pragma unroll
    for (int i = 0; i < 3; i++) {
        int cidx = tid + i * 256;
        float vv = xin[(size_t)row * DMODEL + cidx] + res[(size_t)row * DMODEL + cidx];
        vals[i] = vv;
        s1 += vv;
    }
    red[tid] = s1;
    __syncthreads();
    for (int off = 128; off > 0; off >>= 1) {
        if (tid < off) red[tid] += red[tid + off];
        __syncthreads();
    }
    float mu = red[0] * (1.f / DMODEL);
    __syncthreads();

    float s2 = 0.f;
    #pragma unroll
    for (int i = 0; i < 3; i++) {
        float dv = vals[i] - mu;
        s2 += dv * dv;
    }
    red[tid] = s2;
    __syncthreads();
    for (int off = 128; off > 0; off >>= 1) {
        if (tid < off) red[tid] += red[tid + off];
        __syncthreads();
    }
    float inv = rsqrtf(red[0] * (1.f / DMODEL) + LNEPS);
    __syncthreads();

    #pragma unroll
    for (int i = 0; i < 3; i++) {
        int cidx = tid + i * 256;
        xout[(size_t)row * DMODEL + cidx] = (vals[i] - mu) * inv * gamma[cidx] + beta[cidx];
    }
}

// ---------------- cross-entropy ----------------
__global__ void loss_row_kernel(const float* __restrict__ logits,
                                const int* __restrict__ tgt,
                                float* __restrict__ rowloss)
{
    int row = blockIdx.x;
    int tid = threadIdx.x;   // 256
    const float* lr = logits + (size_t)row * VOCAB;
    __shared__ float red[256];

    float m = -1e30f;
    for (int cc = tid; cc < VOCAB; cc += 256) m = fmaxf(m, lr[cc]);
    red[tid] = m;
    __syncthreads();
    for (int off = 128; off > 0; off >>= 1) {
        if (tid < off) red[tid] = fmaxf(red[tid], red[tid + off]);
        __syncthreads();
    }
    float M = red[0];
    __syncthreads();

    float s = 0.f;
    for (int cc = tid; cc < VOCAB; cc += 256) s += __expf(lr[cc] - M);
    red[tid] = s;
    __syncthreads();
    for (int off = 128; off > 0; off >>= 1) {
        if (tid < off) red[tid] += red[tid + off];
        __syncthreads();
    }
    if (tid == 0)
        rowloss[row] = -(lr[tgt[row]] - M - logf(red[0]));
}

__global__ void loss_final_kernel(const float* __restrict__ rowloss,
                                  float* __restrict__ out)
{
    int tid = threadIdx.x;   // 256
    __shared__ float red[256];
    float s = 0.f;
    for (int i = tid; i < BT; i += 256) s += rowloss[i];
    red[tid] = s;
    __syncthreads();
    for (int off = 128; off > 0; off >>= 1) {
        if (tid < off) red[tid] += red[tid + off];
        __syncthreads();
    }
    if (tid == 0) out[0] = red[0] * (1.f / BT);
}

// ---------------- host orchestration ----------------
struct Scratch {
    float *x, *q, *k, *v, *y, *ff, *rl;
    __nv_bfloat16 *ah, *al, *bh, *bl;
};

static inline void split_launch(const float* A, __nv_bfloat16* hi, __nv_bfloat16* lo, int n)
{
    int n4 = n / 4;
    split_kernel<<<(n4 + 255) / 256, 256>>>(A, hi, lo, n4);
}

static inline void convT_launch(const float* B, __nv_bfloat16* Th, __nv_bfloat16* Tl, int K, int N)
{
    dim3 grid((N + 31) / 32, K / 32);
    convT_kernel<<<grid, dim3(32, 8)>>>(B, Th, Tl, K, N);
}

static inline void gemm_launch(const Scratch& s, const float* bias, float* C,
                               int M, int N, int K, int relu)
{
    dim3 grid((N + 127) / 128, (M + 127) / 128);
    gemm_bf16_kernel<<<grid, 256, GSMEM_BYTES>>>(s.ah, s.al, s.bh, s.bl, bias, C, M, N, K, relu);
}

extern "C" void kernel_launch(void* const* d_in, const int* in_sizes, int n_in,
                              void* d_out, int out_size)
{
    const int*   idx     = (const int*)  d_in[0];
    const int*   targets = (const int*)  d_in[1];
    const float* tok_emb = (const float*)d_in[2];
    const float* pos_emb = (const float*)d_in[3];
    const float* Wq      = (const float*)d_in[4];
    const float* Wk      = (const float*)d_in[5];
    const float* Wv      = (const float*)d_in[6];
    const float* ln1_g   = (const float*)d_in[7];
    const float* ln1_b   = (const float*)d_in[8];
    const float* W1      = (const float*)d_in[9];
    const float* b1      = (const float*)d_in[10];
    const float* W2      = (const float*)d_in[11];
    const float* b2      = (const float*)d_in[12];
    const float* ln2_g   = (const float*)d_in[13];
    const float* ln2_b   = (const float*)d_in[14];
    const float* head_w  = (const float*)d_in[15];
    const float* head_b  = (const float*)d_in[16];

    cudaFuncSetAttribute(gemm_bf16_kernel,
                         cudaFuncAttributeMaxDynamicSharedMemorySize, GSMEM_BYTES);

    Scratch s;
    void* p;
    cudaGetSymbolAddress(&p, g_x);  s.x  = (float*)p;
    cudaGetSymbolAddress(&p, g_q);  s.q  = (float*)p;
    cudaGetSymbolAddress(&p, g_k);  s.k  = (float*)p;
    cudaGetSymbolAddress(&p, g_v);  s.v  = (float*)p;
    cudaGetSymbolAddress(&p, g_y);  s.y  = (float*)p;
    cudaGetSymbolAddress(&p, g_ff); s.ff = (float*)p;
    cudaGetSymbolAddress(&p, g_rowloss); s.rl = (float*)p;
    cudaGetSymbolAddress(&p, g_ah); s.ah = (__nv_bfloat16*)p;
    cudaGetSymbolAddress(&p, g_al); s.al = (__nv_bfloat16*)p;
    cudaGetSymbolAddress(&p, g_bh); s.bh = (__nv_bfloat16*)p;
    cudaGetSymbolAddress(&p, g_bl); s.bl = (__nv_bfloat16*)p;

    float* out = (float*)d_out;
    size_t logits_n = (size_t)BT * VOCAB;

    embed_kernel<<<(BT * DMODEL + 255) / 256, 256>>>(idx, tok_emb, pos_emb, s.x);

    for (int l = 0; l < NLAYER; l++) {
        const float* wq = Wq + (size_t)l * DMODEL * DMODEL;
        const float* wk = Wk + (size_t)l * DMODEL * DMODEL;
        const float* wv = Wv + (size_t)l * DMODEL * DMODEL;

        split_launch(s.x, s.ah, s.al, BT * DMODEL);
        convT_launch(wq, s.bh, s.bl, DMODEL, DMODEL);
        gemm_launch(s, nullptr, s.q, BT, DMODEL, DMODEL, 0);
        convT_launch(wk, s.bh, s.bl, DMODEL, DMODEL);
        gemm_launch(s, nullptr, s.k, BT, DMODEL, DMODEL, 0);
        convT_launch(wv, s.bh, s.bl, DMODEL, DMODEL);
        gemm_launch(s, nullptr, s.v, BT, DMODEL, DMODEL, 0);

        attn_tile_kernel<<<dim3(TLEN / 64, NHEAD, BATCH), 256>>>(s.q, s.k, s.v, s.y);

        resln_kernel<<<BT, 256>>>(s.y, s.x, ln1_g + (size_t)l * DMODEL,
                                  ln1_b + (size_t)l * DMODEL, s.x);

        split_launch(s.x, s.ah, s.al, BT * DMODEL);
        convT_launch(W1 + (size_t)l * DMODEL * FFDIM, s.bh, s.bl, DMODEL, FFDIM);
        gemm_launch(s, b1 + (size_t)l * FFDIM, s.ff, BT, FFDIM, DMODEL, 1);

        split_launch(s.ff, s.ah, s.al, BT * FFDIM);
        convT_launch(W2 + (size_t)l * FFDIM * DMODEL, s.bh, s.bl, FFDIM, DMODEL);
        gemm_launch(s, b2 + (size_t)l * DMODEL, s.y, BT, DMODEL, FFDIM, 0);

        resln_kernel<<<BT, 256>>>(s.y, s.x, ln2_g + (size_t)l * DMODEL,
                                  ln2_b + (size_t)l * DMODEL, s.x);
    }

    // lm head
    split_launch(s.x, s.ah, s.al, BT * DMODEL);
    convT_launch(head_w, s.bh, s.bl, DMODEL, VOCAB);
    gemm_launch(s, head_b, out, BT, VOCAB, DMODEL, 0);

    loss_row_kernel<<<BT, 256>>>(out, targets, s.rl);
    if ((size_t)out_size >= logits_n + 1)
        loss_final_kernel<<<1, 256>>>(s.rl, out + logits_n);
}

// round 10
// speedup vs baseline: 7.2720x; 1.1913x over previous
#include <cuda_runtime.h>
#include <cuda_bf16.h>
#include <math.h>
#include <stdint.h>

// ---------------- problem constants ----------------
#define VOCAB 50257
#define DMODEL 768
#define NHEAD 12
#define HDIM 64
#define TLEN 1024
#define NLAYER 6
#define BATCH 4
#define BT (BATCH * TLEN)     // 4096
#define FFDIM (4 * DMODEL)    // 3072
#define QKVLD (3 * DMODEL)    // 2304
#define LNEPS 1e-5f

// ---------------- scratch (device globals: alloc-free rule) ----------------
__device__ __align__(128) float g_x  [BT * DMODEL];
__device__ __align__(128) float g_y  [BT * DMODEL];
__device__ __align__(128) float g_qkv[BT * QKVLD];
__device__ __align__(128) float g_rowloss[BT];

// bf16 hi/lo activations: residual-stream inputs (K=768)
__device__ __align__(128) __nv_bfloat16 g_ah[BT * DMODEL];
__device__ __align__(128) __nv_bfloat16 g_al[BT * DMODEL];
// bf16 hi/lo FFN hidden (K=3072)
__device__ __align__(128) __nv_bfloat16 g_ch[BT * FFDIM];
__device__ __align__(128) __nv_bfloat16 g_cl[BT * FFDIM];
// bf16 hi/lo transposed weights (max 50257 x 768)
__device__ __align__(128) __nv_bfloat16 g_bh[(size_t)VOCAB * DMODEL];
__device__ __align__(128) __nv_bfloat16 g_bl[(size_t)VOCAB * DMODEL];

// ---------------- hi/lo split helper ----------------
__device__ __forceinline__ void split2(float v, __nv_bfloat16& h, __nv_bfloat16& l)
{
    h = __float2bfloat16_rn(v);
    l = __float2bfloat16_rn(v - __bfloat162float(h));
}

// ---------------- embedding (fused hi/lo split) ----------------
__global__ void embed_kernel(const int* __restrict__ idx,
                             const float* __restrict__ tok,
                             const float* __restrict__ pos,
                             float* __restrict__ x,
                             __nv_bfloat16* __restrict__ xh,
                             __nv_bfloat16* __restrict__ xl)
{
    int i = blockIdx.x * blockDim.x + threadIdx.x;
    if (i < BT * DMODEL) {
        int row = i / DMODEL;
        int d   = i - row * DMODEL;
        int t   = row % TLEN;
        float v = tok[(size_t)idx[row] * DMODEL + d] + pos[(size_t)t * DMODEL + d];
        x[i] = v;
        __nv_bfloat16 h, l;
        split2(v, h, l);
        xh[i] = h;
        xl[i] = l;
    }
}

// ---------------- weight convert + transpose: B[K][N] -> BT[N][K] bf16 hi/lo ----------------
__global__ void convT_kernel(const float* __restrict__ B,
                             __nv_bfloat16* __restrict__ Th,
                             __nv_bfloat16* __restrict__ Tl,
                             int K, int N)
{
    __shared__ float tile[32][33];
    int n0 = blockIdx.x * 32;
    int k0 = blockIdx.y * 32;
    int tx = threadIdx.x;    // 32
    int ty = threadIdx.y;    // 8
    #pragma unroll
    for (int i = 0; i < 4; i++) {
        int k = k0 + ty + 8 * i;
        int n = n0 + tx;
        tile[ty + 8 * i][tx] = (n < N) ? B[(size_t)k * N + n] : 0.f;
    }
    __syncthreads();
    #pragma unroll
    for (int i = 0; i < 4; i++) {
        int n = n0 + ty + 8 * i;
        int k = k0 + tx;
        if (n < N) {
            __nv_bfloat16 h, l;
            split2(tile[tx][ty + 8 * i], h, l);
            Th[(size_t)n * K + k] = h;
            Tl[(size_t)n * K + k] = l;
        }
    }
}

// ======== tensor-core GEMM: bf16 hi/lo 3-product, 3-stage cp.async, swizzled smem ========
// CTA tile 128x128, BK=32, 8 warps (4M x 2N, warp tile 32x64).
// Smem tile: 128 rows x 64B (32 halfs), chunk-XOR swizzle -> conflict-free ldmatrix,
// 16B-aligned cp.async. Stage = 4 arrays x 8KB = 32KB; 3 stages = 96KB -> 2 CTAs/SM.

#define TC_ARRB   8192u                 // bytes per array per stage
#define TC_STAGEB 32768u                // bytes per stage
#define GSMEM_BYTES (3 * TC_STAGEB)     // 98304 B

__device__ __forceinline__ uint32_t swoff(int row, int ch)
{
    return (uint32_t)(row * 64 + (((ch ^ (row >> 1)) & 3) << 4));
}

__device__ __forceinline__ void mma_bf16(float c[4], const uint32_t a[4], const uint32_t b[2])
{
    asm volatile(
        "mma.sync.aligned.m16n8k16.row.col.f32.bf16.bf16.f32 "
        "{%0,%1,%2,%3}, {%4,%5,%6,%7}, {%8,%9}, {%0,%1,%2,%3};\n"
        : "+f"(c[0]), "+f"(c[1]), "+f"(c[2]), "+f"(c[3])
        : "r"(a[0]), "r"(a[1]), "r"(a[2]), "r"(a[3]), "r"(b[0]), "r"(b[1]));
}

__device__ __forceinline__ void ldsm4(uint32_t r[4], uint32_t addr)
{
    asm volatile("ldmatrix.sync.aligned.m8n8.x4.shared.b16 {%0,%1,%2,%3}, [%4];\n"
                 : "=r"(r[0]), "=r"(r[1]), "=r"(r[2]), "=r"(r[3]) : "r"(addr));
}

// Load one stage (BK=32): 2048 x 16B chunks over 256 threads (8 each).
// Source addresses clamped in-bounds; OOB rows use src-size 0 (zero-fill).
__device__ __forceinline__ void gemm_load_stage(
    uint32_t sbase, int s, int kt, int tid,
    const __nv_bfloat16* Ah, const __nv_bfloat16* Al,
    const __nv_bfloat16* Bh, const __nv_bfloat16* Bl,
    int rowBase, int colBase, int M, int N, int K)
{
    #pragma unroll
    for (int j = 0; j < 8; j++) {
        int c   = tid + j * 256;
        int arr = c >> 9;          // 0:Ah 1:Al 2:Bh 3:Bl
        int cc  = c & 511;
        int row = cc >> 2;
        int ch  = cc & 3;
        const __nv_bfloat16* bp = (arr == 0) ? Ah : (arr == 1) ? Al
                                 : (arr == 2) ? Bh : Bl;
        bool isB = (arr >= 2);
        int lim  = isB ? N : M;
        int grow = (isB ? colBase : rowBase) + row;
        int grow_c = (grow < lim) ? grow : (lim - 1);
        const void* gptr = bp + (size_t)grow_c * K + kt * 32 + ch * 8;
        uint32_t daddr = sbase + (uint32_t)s * TC_STAGEB + (uint32_t)arr * TC_ARRB
                       + swoff(row, ch);
        int sz = (grow < lim) ? 16 : 0;
        asm volatile("cp.async.cg.shared.global [%0], [%1], 16, %2;\n"
                     :: "r"(daddr), "l"(gptr), "r"(sz));
    }
    asm volatile("cp.async.commit_group;\n" ::);
}

__global__ __launch_bounds__(256, 2)
void gemm_bf16_kernel(const __nv_bfloat16* __restrict__ Ah,
                      const __nv_bfloat16* __restrict__ Al,
                      const __nv_bfloat16* __restrict__ Bh,
                      const __nv_bfloat16* __restrict__ Bl,
                      const float* __restrict__ bias,
                      float* __restrict__ C,
                      __nv_bfloat16* __restrict__ Chi,   // if non-null: write hi/lo instead of fp32
                      __nv_bfloat16* __restrict__ Clo,
                      int M, int N, int K, int relu)
{
    extern __shared__ __nv_bfloat16 smem[];
    uint32_t sbase = (uint32_t)__cvta_generic_to_shared(smem);

    int tid  = threadIdx.x;
    int warp = tid >> 5;
    int lane = tid & 31;
    int m0 = (warp >> 1) * 32;
    int n0 = (warp & 1) * 64;
    int rowBase = blockIdx.y * 128;
    int colBase = blockIdx.x * 128;
    int KT = K / 32;

    bool vec2N = ((N & 1) == 0);

    float acc[2][8][4];
    #pragma unroll
    for (int i = 0; i < 2; i++)
        #pragma unroll
        for (int j = 0; j < 8; j++)
            #pragma unroll
            for (int r = 0; r < 4; r++) acc[i][j][r] = 0.f;

    gemm_load_stage(sbase, 0, 0, tid, Ah, Al, Bh, Bl, rowBase, colBase, M, N, K);
    gemm_load_stage(sbase, 1, 1, tid, Ah, Al, Bh, Bl, rowBase, colBase, M, N, K);

    for (int kt = 0; kt < KT; kt++) {
        if (kt < KT - 1) asm volatile("cp.async.wait_group 1;\n" ::);
        else             asm volatile("cp.async.wait_group 0;\n" ::);
        __syncthreads();

        if (kt + 2 < KT)
            gemm_load_stage(sbase, (kt + 2) % 3, kt + 2, tid,
                            Ah, Al, Bh, Bl, rowBase, colBase, M, N, K);

        int s = kt % 3;
        uint32_t ah_b = sbase + (uint32_t)s * TC_STAGEB + 0 * TC_ARRB;
        uint32_t al_b = sbase + (uint32_t)s * TC_STAGEB + 1 * TC_ARRB;
        uint32_t bh_b = sbase + (uint32_t)s * TC_STAGEB + 2 * TC_ARRB;
        uint32_t bl_b = sbase + (uint32_t)s * TC_STAGEB + 3 * TC_ARRB;

        #pragma unroll
        for (int ks = 0; ks < 2; ks++) {
            uint32_t ahf[2][4], alf[2][4], bhf[4][4], blf[4][4];
            #pragma unroll
            for (int i = 0; i < 2; i++) {
                int r = m0 + 16 * i + (lane & 15);
                uint32_t off = swoff(r, ks * 2 + (lane >> 4));
                ldsm4(ahf[i], ah_b + off);
                ldsm4(alf[i], al_b + off);
            }
            #pragma unroll
            for (int j = 0; j < 4; j++) {
                int r = n0 + 16 * j + ((lane >> 4) * 8 + (lane & 7));
                uint32_t off = swoff(r, ks * 2 + ((lane >> 3) & 1));
                ldsm4(bhf[j], bh_b + off);
                ldsm4(blf[j], bl_b + off);
            }
            #pragma unroll
            for (int i = 0; i < 2; i++)
                #pragma unroll
                for (int jj = 0; jj < 8; jj++) {
                    const uint32_t* b2h = &bhf[jj >> 1][(jj & 1) * 2];
                    const uint32_t* b2l = &blf[jj >> 1][(jj & 1) * 2];
                    mma_bf16(acc[i][jj], ahf[i], b2h);
                    mma_bf16(acc[i][jj], ahf[i], b2l);
                    mma_bf16(acc[i][jj], alf[i], b2h);
                }
        }
    }

    // ---- epilogue ----
    int g = lane >> 2, tg = lane & 3;
    #pragma unroll
    for (int i = 0; i < 2; i++) {
        #pragma unroll
        for (int jj = 0; jj < 8; jj++) {
            int col = colBase + n0 + 8 * jj + 2 * tg;
            #pragma unroll
            for (int h = 0; h < 2; h++) {
                int row = rowBase + m0 + 16 * i + g + 8 * h;
                if (row >= M) continue;
                float v0 = acc[i][jj][2 * h + 0];
                float v1 = acc[i][jj][2 * h + 1];
                if (bias) {
                    if (col < N)     v0 += bias[col];
                    if (col + 1 < N) v1 += bias[col + 1];
                }
                if (relu) { v0 = fmaxf(v0, 0.f); v1 = fmaxf(v1, 0.f); }
                if (Chi) {
                    // split output mode (N even, col pairs in-bounds for our shapes)
                    if (col + 1 < N) {
                        __nv_bfloat16 p0h, p0l, p1h, p1l;
                        split2(v0, p0h, p0l);
                        split2(v1, p1h, p1l);
                        __nv_bfloat16 ph[2] = {p0h, p1h};
                        __nv_bfloat16 pl[2] = {p0l, p1l};
                        *(uint32_t*)(Chi + (size_t)row * N + col) = *(uint32_t*)ph;
                        *(uint32_t*)(Clo + (size_t)row * N + col) = *(uint32_t*)pl;
                    } else if (col < N) {
                        __nv_bfloat16 hh, ll;
                        split2(v0, hh, ll);
                        Chi[(size_t)row * N + col] = hh;
                        Clo[(size_t)row * N + col] = ll;
                    }
                } else {
                    float* dst = C + (size_t)row * N + col;
                    if (vec2N && col + 1 < N) {
                        *(float2*)dst = make_float2(v0, v1);
                    } else {
                        if (col < N)     dst[0] = v0;
                        if (col + 1 < N) dst[1] = v1;
                    }
                }
            }
        }
    }
}

// ---------------- tiled flash attention (fp32, fused strided QKV) ----------------
__global__ __launch_bounds__(256)
void attn_tile_kernel(const float* __restrict__ qkv,
                      float* __restrict__ y)
{
    int qt = blockIdx.x;
    int h  = blockIdx.y;
    int b  = blockIdx.z;
    int tid = threadIdx.x;  // 256

    __shared__ float Qs[64][65];
    __shared__ float Ks[32][65];
    __shared__ float Vs[32][65];
    __shared__ float Ss[64][33];
    __shared__ float rowm[64], rowl[64], rowa[64];

    size_t headq = (size_t)b * TLEN * QKVLD + (size_t)h * HDIM;
    size_t heady = (size_t)b * TLEN * DMODEL + (size_t)h * HDIM;
    int q0 = qt * 64;

    {
        int r = tid >> 2, c0 = (tid & 3) * 16;
        const float* src = qkv + headq + (size_t)(q0 + r) * QKVLD + c0;
        #pragma unroll
        for (int i = 0; i < 4; i++) {
            float4 t4 = *(const float4*)(src + 4 * i);
            Qs[r][c0 + 4 * i + 0] = t4.x;
            Qs[r][c0 + 4 * i + 1] = t4.y;
            Qs[r][c0 + 4 * i + 2] = t4.z;
            Qs[r][c0 + 4 * i + 3] = t4.w;
        }
    }
    if (tid < 64) { rowm[tid] = -1e30f; rowl[tid] = 0.f; }

    float o[4][4];
    #pragma unroll
    for (int i = 0; i < 4; i++)
        #pragma unroll
        for (int j = 0; j < 4; j++) o[i][j] = 0.f;

    int tx = tid & 15, ty = tid >> 4;
    __syncthreads();

    for (int s0 = 0; s0 < q0 + 64; s0 += 32) {
        {
            int kr = tid >> 3, kc = (tid & 7) * 8;
            const float* ksrc = qkv + headq + DMODEL     + (size_t)(s0 + kr) * QKVLD + kc;
            const float* vsrc = qkv + headq + 2 * DMODEL + (size_t)(s0 + kr) * QKVLD + kc;
            #pragma unroll
            for (int i = 0; i < 2; i++) {
                float4 t4 = *(const float4*)(ksrc + 4 * i);
                Ks[kr][kc + 4 * i + 0] = t4.x; Ks[kr][kc + 4 * i + 1] = t4.y;
                Ks[kr][kc + 4 * i + 2] = t4.z; Ks[kr][kc + 4 * i + 3] = t4.w;
                float4 u4 = *(const float4*)(vsrc + 4 * i);
                Vs[kr][kc + 4 * i + 0] = u4.x; Vs[kr][kc + 4 * i + 1] = u4.y;
                Vs[kr][kc + 4 * i + 2] = u4.z; Vs[kr][kc + 4 * i + 3] = u4.w;
            }
        }
        __syncthreads();

        float accv[4][2];
        #pragma unroll
        for (int i = 0; i < 4; i++) { accv[i][0] = 0.f; accv[i][1] = 0.f; }
        for (int d = 0; d < 64; d++) {
            float bv0 = Ks[tx][d], bv1 = Ks[tx + 16][d];
            #pragma unroll
            for (int i = 0; i < 4; i++) {
                float av = Qs[ty + 16 * i][d];
                accv[i][0] += av * bv0;
                accv[i][1] += av * bv1;
            }
        }
        #pragma unroll
        for (int i = 0; i < 4; i++)
            #pragma unroll
            for (int jj = 0; jj < 2; jj++) {
                int r = ty + 16 * i, cc = tx + 16 * jj;
                int gq = q0 + r, gs = s0 + cc;
                Ss[r][cc] = (gs <= gq) ? accv[i][jj] * 0.125f : -1e30f;
            }
        __syncthreads();

        if (tid < 64) {
            float mo = rowm[tid];
            float mx = mo;
            #pragma unroll 8
            for (int cc = 0; cc < 32; cc++) mx = fmaxf(mx, Ss[tid][cc]);
            float alpha = __expf(mo - mx);
            float sum = 0.f;
            #pragma unroll 8
            for (int cc = 0; cc < 32; cc++) {
                float p = __expf(Ss[tid][cc] - mx);
                Ss[tid][cc] = p;
                sum += p;
            }
            rowl[tid] = rowl[tid] * alpha + sum;
            rowm[tid] = mx;
            rowa[tid] = alpha;
        }
        __syncthreads();

        #pragma unroll
        for (int i = 0; i < 4; i++) {
            float al = rowa[ty + 16 * i];
            #pragma unroll
            for (int jj = 0; jj < 4; jj++) o[i][jj] *= al;
        }
        for (int cc = 0; cc < 32; cc++) {
            float p0 = Ss[ty][cc], p1 = Ss[ty + 16][cc];
            float p2 = Ss[ty + 32][cc], p3 = Ss[ty + 48][cc];
            #pragma unroll
            for (int jj = 0; jj < 4; jj++) {
                float vv = Vs[cc][tx + 16 * jj];
                o[0][jj] += p0 * vv;
                o[1][jj] += p1 * vv;
                o[2][jj] += p2 * vv;
                o[3][jj] += p3 * vv;
            }
        }
        __syncthreads();
    }

    #pragma unroll
    for (int i = 0; i < 4; i++) {
        int r = ty + 16 * i;
        float inv = 1.f / rowl[r];
        #pragma unroll
        for (int jj = 0; jj < 4; jj++) {
            int cc = tx + 16 * jj;
            y[heady + (size_t)(q0 + r) * DMODEL + cc] = o[i][jj] * inv;
        }
    }
}

// ---------------- residual + layernorm (fused hi/lo split) ----------------
__global__ void resln_kernel(const float* __restrict__ xin,
                             const float* __restrict__ res,
                             const float* __restrict__ gamma,
                             const float* __restrict__ beta,
                             float* __restrict__ xout,
                             __nv_bfloat16* __restrict__ xh,
                             __nv_bfloat16* __restrict__ xl)
{
    int row = blockIdx.x;
    int tid = threadIdx.x;   // 256
    __shared__ float red[256];

    float vals[3];
    float s1 = 0.f;
    #pragma unroll
    for (int i = 0; i < 3; i++) {
        int cidx = tid + i * 256;
        float vv = xin[(size_t)row * DMODEL + cidx] + res[(size_t)row * DMODEL + cidx];
        vals[i] = vv;
        s1 += vv;
    }
    red[tid] = s1;
    __syncthreads();
    for (int off = 128; off > 0; off >>= 1) {
        if (tid < off) red[tid] += red[tid + off];
        __syncthreads();
    }
    float mu = red[0] * (1.f / DMODEL);
    __syncthreads();

    float s2 = 0.f;
    #pragma unroll
    for (int i = 0; i < 3; i++) {
        float dv = vals[i] - mu;
        s2 += dv * dv;
    }
    red[tid] = s2;
    __syncthreads();
    for (int off = 128; off > 0; off >>= 1) {
        if (tid < off) red[tid] += red[tid + off];
        __syncthreads();
    }
    float inv = rsqrtf(red[0] * (1.f / DMODEL) + LNEPS);
    __syncthreads();

    #pragma unroll
    for (int i = 0; i < 3; i++) {
        int cidx = tid + i * 256;
        float v = (vals[i] - mu) * inv * gamma[cidx] + beta[cidx];
        xout[(size_t)row * DMODEL + cidx] = v;
        __nv_bfloat16 h, l;
        split2(v, h, l);
        xh[(size_t)row * DMODEL + cidx] = h;
        xl[(size_t)row * DMODEL + cidx] = l;
    }
}

// ---------------- cross-entropy ----------------
__global__ void loss_row_kernel(const float* __restrict__ logits,
                                const int* __restrict__ tgt,
                                float* __restrict__ rowloss)
{
    int row = blockIdx.x;
    int tid = threadIdx.x;   // 256
    const float* lr = logits + (size_t)row * VOCAB;
    __shared__ float red[256];

    float m = -1e30f;
    for (int cc = tid; cc < VOCAB; cc += 256) m = fmaxf(m, lr[cc]);
    red[tid] = m;
    __syncthreads();
    for (int off = 128; off > 0; off >>= 1) {
        if (tid < off) red[tid] = fmaxf(red[tid], red[tid + off]);
        __syncthreads();
    }
    float M = red[0];
    __syncthreads();

    float s = 0.f;
    for (int cc = tid; cc < VOCAB; cc += 256) s += __expf(lr[cc] - M);
    red[tid] = s;
    __syncthreads();
    for (int off = 128; off > 0; off >>= 1) {
        if (tid < off) red[tid] += red[tid + off];
        __syncthreads();
    }
    if (tid == 0)
        rowloss[row] = -(lr[tgt[row]] - M - logf(red[0]));
}

__global__ void loss_final_kernel(const float* __restrict__ rowloss,
                                  float* __restrict__ out)
{
    int tid = threadIdx.x;   // 256
    __shared__ float red[256];
    float s = 0.f;
    for (int i = tid; i < BT; i += 256) s += rowloss[i];
    red[tid] = s;
    __syncthreads();
    for (int off = 128; off > 0; off >>= 1) {
        if (tid < off) red[tid] += red[tid + off];
        __syncthreads();
    }
    if (tid == 0) out[0] = red[0] * (1.f / BT);
}

// ---------------- host orchestration ----------------
struct Scratch {
    float *x, *y, *qkv, *rl;
    __nv_bfloat16 *ah, *al, *ch, *cl, *bh, *bl;
};

static inline void convT_launch(const float* B, __nv_bfloat16* Th, __nv_bfloat16* Tl, int K, int N)
{
    dim3 grid((N + 31) / 32, K / 32);
    convT_kernel<<<grid, dim3(32, 8)>>>(B, Th, Tl, K, N);
}

static inline void gemm_launch(const __nv_bfloat16* Ah, const __nv_bfloat16* Al,
                               const __nv_bfloat16* Bh, const __nv_bfloat16* Bl,
                               const float* bias, float* C,
                               __nv_bfloat16* Chi, __nv_bfloat16* Clo,
                               int M, int N, int K, int relu)
{
    dim3 grid((N + 127) / 128, (M + 127) / 128);
    gemm_bf16_kernel<<<grid, 256, GSMEM_BYTES>>>(Ah, Al, Bh, Bl, bias, C, Chi, Clo,
                                                 M, N, K, relu);
}

extern "C" void kernel_launch(void* const* d_in, const int* in_sizes, int n_in,
                              void* d_out, int out_size)
{
    const int*   idx     = (const int*)  d_in[0];
    const int*   targets = (const int*)  d_in[1];
    const float* tok_emb = (const float*)d_in[2];
    const float* pos_emb = (const float*)d_in[3];
    const float* Wq      = (const float*)d_in[4];
    const float* Wk      = (const float*)d_in[5];
    const float* Wv      = (const float*)d_in[6];
    const float* ln1_g   = (const float*)d_in[7];
    const float* ln1_b   = (const float*)d_in[8];
    const float* W1      = (const float*)d_in[9];
    const float* b1      = (const float*)d_in[10];
    const float* W2      = (const float*)d_in[11];
    const float* b2      = (const float*)d_in[12];
    const float* ln2_g   = (const float*)d_in[13];
    const float* ln2_b   = (const float*)d_in[14];
    const float* head_w  = (const float*)d_in[15];
    const float* head_b  = (const float*)d_in[16];

    cudaFuncSetAttribute(gemm_bf16_kernel,
                         cudaFuncAttributeMaxDynamicSharedMemorySize, GSMEM_BYTES);

    Scratch s;
    void* p;
    cudaGetSymbolAddress(&p, g_x);   s.x   = (float*)p;
    cudaGetSymbolAddress(&p, g_y);   s.y   = (float*)p;
    cudaGetSymbolAddress(&p, g_qkv); s.qkv = (float*)p;
    cudaGetSymbolAddress(&p, g_rowloss); s.rl = (float*)p;
    cudaGetSymbolAddress(&p, g_ah);  s.ah  = (__nv_bfloat16*)p;
    cudaGetSymbolAddress(&p, g_al);  s.al  = (__nv_bfloat16*)p;
    cudaGetSymbolAddress(&p, g_ch);  s.ch  = (__nv_bfloat16*)p;
    cudaGetSymbolAddress(&p, g_cl);  s.cl  = (__nv_bfloat16*)p;
    cudaGetSymbolAddress(&p, g_bh);  s.bh  = (__nv_bfloat16*)p;
    cudaGetSymbolAddress(&p, g_bl);  s.bl  = (__nv_bfloat16*)p;

    float* out = (float*)d_out;
    size_t logits_n = (size_t)BT * VOCAB;

    embed_kernel<<<(BT * DMODEL + 255) / 256, 256>>>(idx, tok_emb, pos_emb,
                                                     s.x, s.ah, s.al);

    for (int l = 0; l < NLAYER; l++) {
        const float* wq = Wq + (size_t)l * DMODEL * DMODEL;
        const float* wk = Wk + (size_t)l * DMODEL * DMODEL;
        const float* wv = Wv + (size_t)l * DMODEL * DMODEL;

        // fused QKV weights: BT rows [0,768)=Q, [768,1536)=K, [1536,2304)=V
        convT_launch(wq, s.bh,                               s.bl,                               DMODEL, DMODEL);
        convT_launch(wk, s.bh + (size_t)DMODEL * DMODEL,     s.bl + (size_t)DMODEL * DMODEL,     DMODEL, DMODEL);
        convT_launch(wv, s.bh + (size_t)2 * DMODEL * DMODEL, s.bl + (size_t)2 * DMODEL * DMODEL, DMODEL, DMODEL);
        gemm_launch(s.ah, s.al, s.bh, s.bl, nullptr, s.qkv, nullptr, nullptr,
                    BT, QKVLD, DMODEL, 0);

        attn_tile_kernel<<<dim3(TLEN / 64, NHEAD, BATCH), 256>>>(s.qkv, s.y);

        resln_kernel<<<BT, 256>>>(s.y, s.x, ln1_g + (size_t)l * DMODEL,
                                  ln1_b + (size_t)l * DMODEL, s.x, s.ah, s.al);

        // FFN up: output written directly as bf16 hi/lo (relu fused)
        convT_launch(W1 + (size_t)l * DMODEL * FFDIM, s.bh, s.bl, DMODEL, FFDIM);
        gemm_launch(s.ah, s.al, s.bh, s.bl, b1 + (size_t)l * FFDIM, nullptr,
                    s.ch, s.cl, BT, FFDIM, DMODEL, 1);

        // FFN down
        convT_launch(W2 + (size_t)l * FFDIM * DMODEL, s.bh, s.bl, FFDIM, DMODEL);
        gemm_launch(s.ch, s.cl, s.bh, s.bl, b2 + (size_t)l * DMODEL, s.y,
                    nullptr, nullptr, BT, DMODEL, FFDIM, 0);

        resln_kernel<<<BT, 256>>>(s.y, s.x, ln2_g + (size_t)l * DMODEL,
                                  ln2_b + (size_t)l * DMODEL, s.x, s.ah, s.al);
    }

    // lm head (x hi/lo already in ah/al from last resln)
    convT_launch(head_w, s.bh, s.bl, DMODEL, VOCAB);
    gemm_launch(s.ah, s.al, s.bh, s.bl, head_b, out, nullptr, nullptr,
                BT, VOCAB, DMODEL, 0);

    loss_row_kernel<<<BT, 256>>>(out, targets, s.rl);
    if ((size_t)out_size >= logits_n + 1)
        loss_final_kernel<<<1, 256>>>(s.rl, out + logits_n);
}

// round 11
// speedup vs baseline: 7.9321x; 1.0908x over previous
#include <cuda_runtime.h>
#include <cuda_bf16.h>
#include <cuda_fp16.h>
#include <math.h>
#include <stdint.h>

// ---------------- problem constants ----------------
#define VOCAB 50257
#define DMODEL 768
#define NHEAD 12
#define HDIM 64
#define TLEN 1024
#define NLAYER 6
#define BATCH 4
#define BT (BATCH * TLEN)     // 4096
#define FFDIM (4 * DMODEL)    // 3072
#define QKVLD (3 * DMODEL)    // 2304
#define LNEPS 1e-5f

// ---------------- scratch (device globals: alloc-free rule) ----------------
__device__ __align__(128) float g_x  [BT * DMODEL];
__device__ __align__(128) float g_y  [BT * DMODEL];
__device__ __align__(128) float g_qkv[BT * QKVLD];
__device__ __align__(128) float g_rowloss[BT];

// bf16 hi/lo activations: residual-stream inputs (K=768)
__device__ __align__(128) __nv_bfloat16 g_ah[BT * DMODEL];
__device__ __align__(128) __nv_bfloat16 g_al[BT * DMODEL];
// bf16 hi/lo FFN hidden (K=3072)
__device__ __align__(128) __nv_bfloat16 g_ch[BT * FFDIM];
__device__ __align__(128) __nv_bfloat16 g_cl[BT * FFDIM];
// bf16 hi/lo transposed weights (max 50257 x 768); reused as fp16 hi/lo for head
__device__ __align__(128) __nv_bfloat16 g_bh[(size_t)VOCAB * DMODEL];
__device__ __align__(128) __nv_bfloat16 g_bl[(size_t)VOCAB * DMODEL];
// fp16 activations for head GEMM
__device__ __align__(128) __half g_fh[BT * DMODEL];

// ---------------- split helpers ----------------
__device__ __forceinline__ void split2(float v, __nv_bfloat16& h, __nv_bfloat16& l)
{
    h = __float2bfloat16_rn(v);
    l = __float2bfloat16_rn(v - __bfloat162float(h));
}
__device__ __forceinline__ void split2h(float v, __half& h, __half& l)
{
    h = __float2half_rn(v);
    l = __float2half_rn(v - __half2float(h));
}

// ---------------- embedding (fused hi/lo split) ----------------
__global__ void embed_kernel(const int* __restrict__ idx,
                             const float* __restrict__ tok,
                             const float* __restrict__ pos,
                             float* __restrict__ x,
                             __nv_bfloat16* __restrict__ xh,
                             __nv_bfloat16* __restrict__ xl)
{
    int i = blockIdx.x * blockDim.x + threadIdx.x;
    if (i < BT * DMODEL) {
        int row = i / DMODEL;
        int d   = i - row * DMODEL;
        int t   = row % TLEN;
        float v = tok[(size_t)idx[row] * DMODEL + d] + pos[(size_t)t * DMODEL + d];
        x[i] = v;
        __nv_bfloat16 h, l;
        split2(v, h, l);
        xh[i] = h;
        xl[i] = l;
    }
}

// ---------------- fp32 -> fp16 convert (head activations) ----------------
__global__ void conv_f16_kernel(const float* __restrict__ A,
                                __half* __restrict__ H, int n4)
{
    int i = blockIdx.x * blockDim.x + threadIdx.x;
    if (i < n4) {
        float4 v = *(const float4*)(A + 4 * (size_t)i);
        __half h[4];
        h[0] = __float2half_rn(v.x); h[1] = __float2half_rn(v.y);
        h[2] = __float2half_rn(v.z); h[3] = __float2half_rn(v.w);
        *(uint2*)(H + 4 * (size_t)i) = *(uint2*)h;
    }
}

// ---------------- weight convert + transpose: bf16 hi/lo ----------------
__global__ void convT_kernel(const float* __restrict__ B,
                             __nv_bfloat16* __restrict__ Th,
                             __nv_bfloat16* __restrict__ Tl,
                             int K, int N)
{
    __shared__ float tile[32][33];
    int n0 = blockIdx.x * 32;
    int k0 = blockIdx.y * 32;
    int tx = threadIdx.x;    // 32
    int ty = threadIdx.y;    // 8
    #pragma unroll
    for (int i = 0; i < 4; i++) {
        int k = k0 + ty + 8 * i;
        int n = n0 + tx;
        tile[ty + 8 * i][tx] = (n < N) ? B[(size_t)k * N + n] : 0.f;
    }
    __syncthreads();
    #pragma unroll
    for (int i = 0; i < 4; i++) {
        int n = n0 + ty + 8 * i;
        int k = k0 + tx;
        if (n < N) {
            __nv_bfloat16 h, l;
            split2(tile[tx][ty + 8 * i], h, l);
            Th[(size_t)n * K + k] = h;
            Tl[(size_t)n * K + k] = l;
        }
    }
}

// ---------------- weight convert + transpose: fp16 hi/lo (head) ----------------
__global__ void convT_f16_kernel(const float* __restrict__ B,
                                 __half* __restrict__ Th,
                                 __half* __restrict__ Tl,
                                 int K, int N)
{
    __shared__ float tile[32][33];
    int n0 = blockIdx.x * 32;
    int k0 = blockIdx.y * 32;
    int tx = threadIdx.x;
    int ty = threadIdx.y;
    #pragma unroll
    for (int i = 0; i < 4; i++) {
        int k = k0 + ty + 8 * i;
        int n = n0 + tx;
        tile[ty + 8 * i][tx] = (n < N) ? B[(size_t)k * N + n] : 0.f;
    }
    __syncthreads();
    #pragma unroll
    for (int i = 0; i < 4; i++) {
        int n = n0 + ty + 8 * i;
        int k = k0 + tx;
        if (n < N) {
            __half h, l;
            split2h(tile[tx][ty + 8 * i], h, l);
            Th[(size_t)n * K + k] = h;
            Tl[(size_t)n * K + k] = l;
        }
    }
}

// ======== shared GEMM infrastructure ========
#define TC_ARRB   8192u                 // bytes per array per stage (128 rows x 64B)
#define TC_STAGEB (4 * TC_ARRB)         // bf16 kernel: 4 arrays
#define GSMEM_BYTES (3 * TC_STAGEB)     // 98304 B
#define TF_STAGEB (3 * TC_ARRB)         // f16 kernel: 3 arrays
#define FSMEM_BYTES (3 * TF_STAGEB)     // 73728 B

__device__ __forceinline__ uint32_t swoff(int row, int ch)
{
    return (uint32_t)(row * 64 + (((ch ^ (row >> 1)) & 3) << 4));
}

__device__ __forceinline__ void mma_bf16(float c[4], const uint32_t a[4], const uint32_t b[2])
{
    asm volatile(
        "mma.sync.aligned.m16n8k16.row.col.f32.bf16.bf16.f32 "
        "{%0,%1,%2,%3}, {%4,%5,%6,%7}, {%8,%9}, {%0,%1,%2,%3};\n"
        : "+f"(c[0]), "+f"(c[1]), "+f"(c[2]), "+f"(c[3])
        : "r"(a[0]), "r"(a[1]), "r"(a[2]), "r"(a[3]), "r"(b[0]), "r"(b[1]));
}

__device__ __forceinline__ void mma_f16(float c[4], const uint32_t a[4], const uint32_t b[2])
{
    asm volatile(
        "mma.sync.aligned.m16n8k16.row.col.f32.f16.f16.f32 "
        "{%0,%1,%2,%3}, {%4,%5,%6,%7}, {%8,%9}, {%0,%1,%2,%3};\n"
        : "+f"(c[0]), "+f"(c[1]), "+f"(c[2]), "+f"(c[3])
        : "r"(a[0]), "r"(a[1]), "r"(a[2]), "r"(a[3]), "r"(b[0]), "r"(b[1]));
}

__device__ __forceinline__ void ldsm4(uint32_t r[4], uint32_t addr)
{
    asm volatile("ldmatrix.sync.aligned.m8n8.x4.shared.b16 {%0,%1,%2,%3}, [%4];\n"
                 : "=r"(r[0]), "=r"(r[1]), "=r"(r[2]), "=r"(r[3]) : "r"(addr));
}

// ======== bf16 3-product GEMM (layers): 128x128, BK=32, 3-stage, 2 CTA/SM ========
__device__ __forceinline__ void gemm_load_stage(
    uint32_t sbase, int s, int kt, int tid,
    const __nv_bfloat16* Ah, const __nv_bfloat16* Al,
    const __nv_bfloat16* Bh, const __nv_bfloat16* Bl,
    int rowBase, int colBase, int M, int N, int K)
{
    #pragma unroll
    for (int j = 0; j < 8; j++) {
        int c   = tid + j * 256;
        int arr = c >> 9;          // 0:Ah 1:Al 2:Bh 3:Bl
        int cc  = c & 511;
        int row = cc >> 2;
        int ch  = cc & 3;
        const __nv_bfloat16* bp = (arr == 0) ? Ah : (arr == 1) ? Al
                                 : (arr == 2) ? Bh : Bl;
        bool isB = (arr >= 2);
        int lim  = isB ? N : M;
        int grow = (isB ? colBase : rowBase) + row;
        int grow_c = (grow < lim) ? grow : (lim - 1);
        const void* gptr = bp + (size_t)grow_c * K + kt * 32 + ch * 8;
        uint32_t daddr = sbase + (uint32_t)s * TC_STAGEB + (uint32_t)arr * TC_ARRB
                       + swoff(row, ch);
        int sz = (grow < lim) ? 16 : 0;
        asm volatile("cp.async.cg.shared.global [%0], [%1], 16, %2;\n"
                     :: "r"(daddr), "l"(gptr), "r"(sz));
    }
    asm volatile("cp.async.commit_group;\n" ::);
}

__global__ __launch_bounds__(256, 2)
void gemm_bf16_kernel(const __nv_bfloat16* __restrict__ Ah,
                      const __nv_bfloat16* __restrict__ Al,
                      const __nv_bfloat16* __restrict__ Bh,
                      const __nv_bfloat16* __restrict__ Bl,
                      const float* __restrict__ bias,
                      float* __restrict__ C,
                      __nv_bfloat16* __restrict__ Chi,
                      __nv_bfloat16* __restrict__ Clo,
                      int M, int N, int K, int relu)
{
    extern __shared__ __nv_bfloat16 smem[];
    uint32_t sbase = (uint32_t)__cvta_generic_to_shared(smem);

    int tid  = threadIdx.x;
    int warp = tid >> 5;
    int lane = tid & 31;
    int m0 = (warp >> 1) * 32;
    int n0 = (warp & 1) * 64;
    int rowBase = blockIdx.y * 128;
    int colBase = blockIdx.x * 128;
    int KT = K / 32;

    bool vec2N = ((N & 1) == 0);

    float acc[2][8][4];
    #pragma unroll
    for (int i = 0; i < 2; i++)
        #pragma unroll
        for (int j = 0; j < 8; j++)
            #pragma unroll
            for (int r = 0; r < 4; r++) acc[i][j][r] = 0.f;

    gemm_load_stage(sbase, 0, 0, tid, Ah, Al, Bh, Bl, rowBase, colBase, M, N, K);
    gemm_load_stage(sbase, 1, 1, tid, Ah, Al, Bh, Bl, rowBase, colBase, M, N, K);

    for (int kt = 0; kt < KT; kt++) {
        if (kt < KT - 1) asm volatile("cp.async.wait_group 1;\n" ::);
        else             asm volatile("cp.async.wait_group 0;\n" ::);
        __syncthreads();

        if (kt + 2 < KT)
            gemm_load_stage(sbase, (kt + 2) % 3, kt + 2, tid,
                            Ah, Al, Bh, Bl, rowBase, colBase, M, N, K);

        int s = kt % 3;
        uint32_t ah_b = sbase + (uint32_t)s * TC_STAGEB + 0 * TC_ARRB;
        uint32_t al_b = sbase + (uint32_t)s * TC_STAGEB + 1 * TC_ARRB;
        uint32_t bh_b = sbase + (uint32_t)s * TC_STAGEB + 2 * TC_ARRB;
        uint32_t bl_b = sbase + (uint32_t)s * TC_STAGEB + 3 * TC_ARRB;

        #pragma unroll
        for (int ks = 0; ks < 2; ks++) {
            uint32_t ahf[2][4], alf[2][4], bhf[4][4], blf[4][4];
            #pragma unroll
            for (int i = 0; i < 2; i++) {
                int r = m0 + 16 * i + (lane & 15);
                uint32_t off = swoff(r, ks * 2 + (lane >> 4));
                ldsm4(ahf[i], ah_b + off);
                ldsm4(alf[i], al_b + off);
            }
            #pragma unroll
            for (int j = 0; j < 4; j++) {
                int r = n0 + 16 * j + ((lane >> 4) * 8 + (lane & 7));
                uint32_t off = swoff(r, ks * 2 + ((lane >> 3) & 1));
                ldsm4(bhf[j], bh_b + off);
                ldsm4(blf[j], bl_b + off);
            }
            // product-major order: dependent MMAs on same acc are 16 apart
            #pragma unroll
            for (int i = 0; i < 2; i++)
                #pragma unroll
                for (int jj = 0; jj < 8; jj++)
                    mma_bf16(acc[i][jj], ahf[i], &bhf[jj >> 1][(jj & 1) * 2]);
            #pragma unroll
            for (int i = 0; i < 2; i++)
                #pragma unroll
                for (int jj = 0; jj < 8; jj++)
                    mma_bf16(acc[i][jj], ahf[i], &blf[jj >> 1][(jj & 1) * 2]);
            #pragma unroll
            for (int i = 0; i < 2; i++)
                #pragma unroll
                for (int jj = 0; jj < 8; jj++)
                    mma_bf16(acc[i][jj], alf[i], &bhf[jj >> 1][(jj & 1) * 2]);
        }
    }

    int g = lane >> 2, tg = lane & 3;
    #pragma unroll
    for (int i = 0; i < 2; i++) {
        #pragma unroll
        for (int jj = 0; jj < 8; jj++) {
            int col = colBase + n0 + 8 * jj + 2 * tg;
            #pragma unroll
            for (int h = 0; h < 2; h++) {
                int row = rowBase + m0 + 16 * i + g + 8 * h;
                if (row >= M) continue;
                float v0 = acc[i][jj][2 * h + 0];
                float v1 = acc[i][jj][2 * h + 1];
                if (bias) {
                    if (col < N)     v0 += bias[col];
                    if (col + 1 < N) v1 += bias[col + 1];
                }
                if (relu) { v0 = fmaxf(v0, 0.f); v1 = fmaxf(v1, 0.f); }
                if (Chi) {
                    if (col + 1 < N) {
                        __nv_bfloat16 p0h, p0l, p1h, p1l;
                        split2(v0, p0h, p0l);
                        split2(v1, p1h, p1l);
                        __nv_bfloat16 ph[2] = {p0h, p1h};
                        __nv_bfloat16 pl[2] = {p0l, p1l};
                        *(uint32_t*)(Chi + (size_t)row * N + col) = *(uint32_t*)ph;
                        *(uint32_t*)(Clo + (size_t)row * N + col) = *(uint32_t*)pl;
                    } else if (col < N) {
                        __nv_bfloat16 hh, ll;
                        split2(v0, hh, ll);
                        Chi[(size_t)row * N + col] = hh;
                        Clo[(size_t)row * N + col] = ll;
                    }
                } else {
                    float* dst = C + (size_t)row * N + col;
                    if (vec2N && col + 1 < N) {
                        *(float2*)dst = make_float2(v0, v1);
                    } else {
                        if (col < N)     dst[0] = v0;
                        if (col + 1 < N) dst[1] = v1;
                    }
                }
            }
        }
    }
}

// ======== fp16 2-product GEMM (head): A single f16, B hi/lo f16 ========
__device__ __forceinline__ void gemm_load_stage_f16(
    uint32_t sbase, int s, int kt, int tid,
    const __half* Ah, const __half* Bh, const __half* Bl,
    int rowBase, int colBase, int M, int N, int K)
{
    #pragma unroll
    for (int j = 0; j < 6; j++) {
        int c   = tid + j * 256;
        int arr = c >> 9;          // 0:Ah 1:Bh 2:Bl
        int cc  = c & 511;
        int row = cc >> 2;
        int ch  = cc & 3;
        const __half* bp = (arr == 0) ? Ah : (arr == 1) ? Bh : Bl;
        bool isB = (arr >= 1);
        int lim  = isB ? N : M;
        int grow = (isB ? colBase : rowBase) + row;
        int grow_c = (grow < lim) ? grow : (lim - 1);
        const void* gptr = bp + (size_t)grow_c * K + kt * 32 + ch * 8;
        uint32_t daddr = sbase + (uint32_t)s * TF_STAGEB + (uint32_t)arr * TC_ARRB
                       + swoff(row, ch);
        int sz = (grow < lim) ? 16 : 0;
        asm volatile("cp.async.cg.shared.global [%0], [%1], 16, %2;\n"
                     :: "r"(daddr), "l"(gptr), "r"(sz));
    }
    asm volatile("cp.async.commit_group;\n" ::);
}

__global__ __launch_bounds__(256, 2)
void gemm_f16_kernel(const __half* __restrict__ Ah,
                     const __half* __restrict__ Bh,
                     const __half* __restrict__ Bl,
                     const float* __restrict__ bias,
                     float* __restrict__ C,
                     int M, int N, int K)
{
    extern __shared__ __nv_bfloat16 smem[];
    uint32_t sbase = (uint32_t)__cvta_generic_to_shared(smem);

    int tid  = threadIdx.x;
    int warp = tid >> 5;
    int lane = tid & 31;
    int m0 = (warp >> 1) * 32;
    int n0 = (warp & 1) * 64;
    int rowBase = blockIdx.y * 128;
    int colBase = blockIdx.x * 128;
    int KT = K / 32;

    bool vec2N = ((N & 1) == 0);

    float acc[2][8][4];
    #pragma unroll
    for (int i = 0; i < 2; i++)
        #pragma unroll
        for (int j = 0; j < 8; j++)
            #pragma unroll
            for (int r = 0; r < 4; r++) acc[i][j][r] = 0.f;

    gemm_load_stage_f16(sbase, 0, 0, tid, Ah, Bh, Bl, rowBase, colBase, M, N, K);
    gemm_load_stage_f16(sbase, 1, 1, tid, Ah, Bh, Bl, rowBase, colBase, M, N, K);

    for (int kt = 0; kt < KT; kt++) {
        if (kt < KT - 1) asm volatile("cp.async.wait_group 1;\n" ::);
        else             asm volatile("cp.async.wait_group 0;\n" ::);
        __syncthreads();

        if (kt + 2 < KT)
            gemm_load_stage_f16(sbase, (kt + 2) % 3, kt + 2, tid,
                                Ah, Bh, Bl, rowBase, colBase, M, N, K);

        int s = kt % 3;
        uint32_t ah_b = sbase + (uint32_t)s * TF_STAGEB + 0 * TC_ARRB;
        uint32_t bh_b = sbase + (uint32_t)s * TF_STAGEB + 1 * TC_ARRB;
        uint32_t bl_b = sbase + (uint32_t)s * TF_STAGEB + 2 * TC_ARRB;

        #pragma unroll
        for (int ks = 0; ks < 2; ks++) {
            uint32_t ahf[2][4], bhf[4][4], blf[4][4];
            #pragma unroll
            for (int i = 0; i < 2; i++) {
                int r = m0 + 16 * i + (lane & 15);
                uint32_t off = swoff(r, ks * 2 + (lane >> 4));
                ldsm4(ahf[i], ah_b + off);
            }
            #pragma unroll
            for (int j = 0; j < 4; j++) {
                int r = n0 + 16 * j + ((lane >> 4) * 8 + (lane & 7));
                uint32_t off = swoff(r, ks * 2 + ((lane >> 3) & 1));
                ldsm4(bhf[j], bh_b + off);
                ldsm4(blf[j], bl_b + off);
            }
            #pragma unroll
            for (int i = 0; i < 2; i++)
                #pragma unroll
                for (int jj = 0; jj < 8; jj++)
                    mma_f16(acc[i][jj], ahf[i], &bhf[jj >> 1][(jj & 1) * 2]);
            #pragma unroll
            for (int i = 0; i < 2; i++)
                #pragma unroll
                for (int jj = 0; jj < 8; jj++)
                    mma_f16(acc[i][jj], ahf[i], &blf[jj >> 1][(jj & 1) * 2]);
        }
    }

    int g = lane >> 2, tg = lane & 3;
    #pragma unroll
    for (int i = 0; i < 2; i++) {
        #pragma unroll
        for (int jj = 0; jj < 8; jj++) {
            int col = colBase + n0 + 8 * jj + 2 * tg;
            #pragma unroll
            for (int h = 0; h < 2; h++) {
                int row = rowBase + m0 + 16 * i + g + 8 * h;
                if (row >= M) continue;
                float v0 = acc[i][jj][2 * h + 0];
                float v1 = acc[i][jj][2 * h + 1];
                if (bias) {
                    if (col < N)     v0 += bias[col];
                    if (col + 1 < N) v1 += bias[col + 1];
                }
                float* dst = C + (size_t)row * N + col;
                if (vec2N && col + 1 < N) {
                    *(float2*)dst = make_float2(v0, v1);
                } else {
                    if (col < N)     dst[0] = v0;
                    if (col + 1 < N) dst[1] = v1;
                }
            }
        }
    }
}

// ---------------- tiled flash attention (fp32, fused strided QKV) ----------------
__global__ __launch_bounds__(256)
void attn_tile_kernel(const float* __restrict__ qkv,
                      float* __restrict__ y)
{
    int qt = blockIdx.x;
    int h  = blockIdx.y;
    int b  = blockIdx.z;
    int tid = threadIdx.x;  // 256

    __shared__ float Qs[64][65];
    __shared__ float Ks[32][65];
    __shared__ float Vs[32][65];
    __shared__ float Ss[64][33];
    __shared__ float rowm[64], rowl[64], rowa[64];

    size_t headq = (size_t)b * TLEN * QKVLD + (size_t)h * HDIM;
    size_t heady = (size_t)b * TLEN * DMODEL + (size_t)h * HDIM;
    int q0 = qt * 64;

    {
        int r = tid >> 2, c0 = (tid & 3) * 16;
        const float* src = qkv + headq + (size_t)(q0 + r) * QKVLD + c0;
        #pragma unroll
        for (int i = 0; i < 4; i++) {
            float4 t4 = *(const float4*)(src + 4 * i);
            Qs[r][c0 + 4 * i + 0] = t4.x;
            Qs[r][c0 + 4 * i + 1] = t4.y;
            Qs[r][c0 + 4 * i + 2] = t4.z;
            Qs[r][c0 + 4 * i + 3] = t4.w;
        }
    }
    if (tid < 64) { rowm[tid] = -1e30f; rowl[tid] = 0.f; }

    float o[4][4];
    #pragma unroll
    for (int i = 0; i < 4; i++)
        #pragma unroll
        for (int j = 0; j < 4; j++) o[i][j] = 0.f;

    int tx = tid & 15, ty = tid >> 4;
    __syncthreads();

    for (int s0 = 0; s0 < q0 + 64; s0 += 32) {
        {
            int kr = tid >> 3, kc = (tid & 7) * 8;
            const float* ksrc = qkv + headq + DMODEL     + (size_t)(s0 + kr) * QKVLD + kc;
            const float* vsrc = qkv + headq + 2 * DMODEL + (size_t)(s0 + kr) * QKVLD + kc;
            #pragma unroll
            for (int i = 0; i < 2; i++) {
                float4 t4 = *(const float4*)(ksrc + 4 * i);
                Ks[kr][kc + 4 * i + 0] = t4.x; Ks[kr][kc + 4 * i + 1] = t4.y;
                Ks[kr][kc + 4 * i + 2] = t4.z; Ks[kr][kc + 4 * i + 3] = t4.w;
                float4 u4 = *(const float4*)(vsrc + 4 * i);
                Vs[kr][kc + 4 * i + 0] = u4.x; Vs[kr][kc + 4 * i + 1] = u4.y;
                Vs[kr][kc + 4 * i + 2] = u4.z; Vs[kr][kc + 4 * i + 3] = u4.w;
            }
        }
        __syncthreads();

        float accv[4][2];
        #pragma unroll
        for (int i = 0; i < 4; i++) { accv[i][0] = 0.f; accv[i][1] = 0.f; }
        for (int d = 0; d < 64; d++) {
            float bv0 = Ks[tx][d], bv1 = Ks[tx + 16][d];
            #pragma unroll
            for (int i = 0; i < 4; i++) {
                float av = Qs[ty + 16 * i][d];
                accv[i][0] += av * bv0;
                accv[i][1] += av * bv1;
            }
        }
        #pragma unroll
        for (int i = 0; i < 4; i++)
            #pragma unroll
            for (int jj = 0; jj < 2; jj++) {
                int r = ty + 16 * i, cc = tx + 16 * jj;
                int gq = q0 + r, gs = s0 + cc;
                Ss[r][cc] = (gs <= gq) ? accv[i][jj] * 0.125f : -1e30f;
            }
        __syncthreads();

        if (tid < 64) {
            float mo = rowm[tid];
            float mx = mo;
            #pragma unroll 8
            for (int cc = 0; cc < 32; cc++) mx = fmaxf(mx, Ss[tid][cc]);
            float alpha = __expf(mo - mx);
            float sum = 0.f;
            #pragma unroll 8
            for (int cc = 0; cc < 32; cc++) {
                float p = __expf(Ss[tid][cc] - mx);
                Ss[tid][cc] = p;
                sum += p;
            }
            rowl[tid] = rowl[tid] * alpha + sum;
            rowm[tid] = mx;
            rowa[tid] = alpha;
        }
        __syncthreads();

        #pragma unroll
        for (int i = 0; i < 4; i++) {
            float al = rowa[ty + 16 * i];
            #pragma unroll
            for (int jj = 0; jj < 4; jj++) o[i][jj] *= al;
        }
        for (int cc = 0; cc < 32; cc++) {
            float p0 = Ss[ty][cc], p1 = Ss[ty + 16][cc];
            float p2 = Ss[ty + 32][cc], p3 = Ss[ty + 48][cc];
            #pragma unroll
            for (int jj = 0; jj < 4; jj++) {
                float vv = Vs[cc][tx + 16 * jj];
                o[0][jj] += p0 * vv;
                o[1][jj] += p1 * vv;
                o[2][jj] += p2 * vv;
                o[3][jj] += p3 * vv;
            }
        }
        __syncthreads();
    }

    #pragma unroll
    for (int i = 0; i < 4; i++) {
        int r = ty + 16 * i;
        float inv = 1.f / rowl[r];
        #pragma unroll
        for (int jj = 0; jj < 4; jj++) {
            int cc = tx + 16 * jj;
            y[heady + (size_t)(q0 + r) * DMODEL + cc] = o[i][jj] * inv;
        }
    }
}

// ---------------- residual + layernorm (fused hi/lo split) ----------------
__global__ void resln_kernel(const float* __restrict__ xin,
                             const float* __restrict__ res,
                             const float* __restrict__ gamma,
                             const float* __restrict__ beta,
                             float* __restrict__ xout,
                             __nv_bfloat16* __restrict__ xh,
                             __nv_bfloat16* __restrict__ xl)
{
    int row = blockIdx.x;
    int tid = threadIdx.x;   // 256
    __shared__ float red[256];

    float vals[3];
    float s1 = 0.f;
    #pragma unroll
    for (int i = 0; i < 3; i++) {
        int cidx = tid + i * 256;
        float vv = xin[(size_t)row * DMODEL + cidx] + res[(size_t)row * DMODEL + cidx];
        vals[i] = vv;
        s1 += vv;
    }
    red[tid] = s1;
    __syncthreads();
    for (int off = 128; off > 0; off >>= 1) {
        if (tid < off) red[tid] += red[tid + off];
        __syncthreads();
    }
    float mu = red[0] * (1.f / DMODEL);
    __syncthreads();

    float s2 = 0.f;
    #pragma unroll
    for (int i = 0; i < 3; i++) {
        float dv = vals[i] - mu;
        s2 += dv * dv;
    }
    red[tid] = s2;
    __syncthreads();
    for (int off = 128; off > 0; off >>= 1) {
        if (tid < off) red[tid] += red[tid + off];
        __syncthreads();
    }
    float inv = rsqrtf(red[0] * (1.f / DMODEL) + LNEPS);
    __syncthreads();

    #pragma unroll
    for (int i = 0; i < 3; i++) {
        int cidx = tid + i * 256;
        float v = (vals[i] - mu) * inv * gamma[cidx] + beta[cidx];
        xout[(size_t)row * DMODEL + cidx] = v;
        __nv_bfloat16 h, l;
        split2(v, h, l);
        xh[(size_t)row * DMODEL + cidx] = h;
        xl[(size_t)row * DMODEL + cidx] = l;
    }
}

// ---------------- cross-entropy: one-pass online logsumexp ----------------
__global__ void loss_row_kernel(const float* __restrict__ logits,
                                const int* __restrict__ tgt,
                                float* __restrict__ rowloss)
{
    int row = blockIdx.x;
    int tid = threadIdx.x;   // 256
    const float* lr = logits + (size_t)row * VOCAB;
    __shared__ float sm[256], ss[256];

    float m = -1e30f, s = 0.f;
    for (int cc = tid; cc < VOCAB; cc += 256) {
        float v = lr[cc];
        if (v > m) { s = s * __expf(m - v) + 1.f; m = v; }
        else       { s += __expf(v - m); }
    }
    sm[tid] = m; ss[tid] = s;
    __syncthreads();
    for (int off = 128; off > 0; off >>= 1) {
        if (tid < off) {
            float m2 = sm[tid + off], s2 = ss[tid + off];
            float m1 = sm[tid],       s1 = ss[tid];
            float mm = fmaxf(m1, m2);
            sm[tid] = mm;
            ss[tid] = s1 * __expf(m1 - mm) + s2 * __expf(m2 - mm);
        }
        __syncthreads();
    }
    if (tid == 0)
        rowloss[row] = -(lr[tgt[row]] - sm[0] - logf(ss[0]));
}

__global__ void loss_final_kernel(const float* __restrict__ rowloss,
                                  float* __restrict__ out)
{
    int tid = threadIdx.x;   // 256
    __shared__ float red[256];
    float s = 0.f;
    for (int i = tid; i < BT; i += 256) s += rowloss[i];
    red[tid] = s;
    __syncthreads();
    for (int off = 128; off > 0; off >>= 1) {
        if (tid < off) red[tid] += red[tid + off];
        __syncthreads();
    }
    if (tid == 0) out[0] = red[0] * (1.f / BT);
}

// ---------------- host orchestration ----------------
static inline void convT_launch(const float* B, __nv_bfloat16* Th, __nv_bfloat16* Tl, int K, int N)
{
    dim3 grid((N + 31) / 32, K / 32);
    convT_kernel<<<grid, dim3(32, 8)>>>(B, Th, Tl, K, N);
}

static inline void gemm_launch(const __nv_bfloat16* Ah, const __nv_bfloat16* Al,
                               const __nv_bfloat16* Bh, const __nv_bfloat16* Bl,
                               const float* bias, float* C,
                               __nv_bfloat16* Chi, __nv_bfloat16* Clo,
                               int M, int N, int K, int relu)
{
    dim3 grid((N + 127) / 128, (M + 127) / 128);
    gemm_bf16_kernel<<<grid, 256, GSMEM_BYTES>>>(Ah, Al, Bh, Bl, bias, C, Chi, Clo,
                                                 M, N, K, relu);
}

extern "C" void kernel_launch(void* const* d_in, const int* in_sizes, int n_in,
                              void* d_out, int out_size)
{
    const int*   idx     = (const int*)  d_in[0];
    const int*   targets = (const int*)  d_in[1];
    const float* tok_emb = (const float*)d_in[2];
    const float* pos_emb = (const float*)d_in[3];
    const float* Wq      = (const float*)d_in[4];
    const float* Wk      = (const float*)d_in[5];
    const float* Wv      = (const float*)d_in[6];
    const float* ln1_g   = (const float*)d_in[7];
    const float* ln1_b   = (const float*)d_in[8];
    const float* W1      = (const float*)d_in[9];
    const float* b1      = (const float*)d_in[10];
    const float* W2      = (const float*)d_in[11];
    const float* b2      = (const float*)d_in[12];
    const float* ln2_g   = (const float*)d_in[13];
    const float* ln2_b   = (const float*)d_in[14];
    const float* head_w  = (const float*)d_in[15];
    const float* head_b  = (const float*)d_in[16];

    cudaFuncSetAttribute(gemm_bf16_kernel,
                         cudaFuncAttributeMaxDynamicSharedMemorySize, GSMEM_BYTES);
    cudaFuncSetAttribute(gemm_f16_kernel,
                         cudaFuncAttributeMaxDynamicSharedMemorySize, FSMEM_BYTES);

    void* p;
    float *x, *y, *qkv, *rl;
    __nv_bfloat16 *ah, *al, *ch, *cl, *bh, *bl;
    __half *fh;
    cudaGetSymbolAddress(&p, g_x);   x   = (float*)p;
    cudaGetSymbolAddress(&p, g_y);   y   = (float*)p;
    cudaGetSymbolAddress(&p, g_qkv); qkv = (float*)p;
    cudaGetSymbolAddress(&p, g_rowloss); rl = (float*)p;
    cudaGetSymbolAddress(&p, g_ah);  ah  = (__nv_bfloat16*)p;
    cudaGetSymbolAddress(&p, g_al);  al  = (__nv_bfloat16*)p;
    cudaGetSymbolAddress(&p, g_ch);  ch  = (__nv_bfloat16*)p;
    cudaGetSymbolAddress(&p, g_cl);  cl  = (__nv_bfloat16*)p;
    cudaGetSymbolAddress(&p, g_bh);  bh  = (__nv_bfloat16*)p;
    cudaGetSymbolAddress(&p, g_bl);  bl  = (__nv_bfloat16*)p;
    cudaGetSymbolAddress(&p, g_fh);  fh  = (__half*)p;

    float* out = (float*)d_out;
    size_t logits_n = (size_t)BT * VOCAB;

    embed_kernel<<<(BT * DMODEL + 255) / 256, 256>>>(idx, tok_emb, pos_emb,
                                                     x, ah, al);

    for (int l = 0; l < NLAYER; l++) {
        const float* wq = Wq + (size_t)l * DMODEL * DMODEL;
        const float* wk = Wk + (size_t)l * DMODEL * DMODEL;
        const float* wv = Wv + (size_t)l * DMODEL * DMODEL;

        convT_launch(wq, bh,                               bl,                               DMODEL, DMODEL);
        convT_launch(wk, bh + (size_t)DMODEL * DMODEL,     bl + (size_t)DMODEL * DMODEL,     DMODEL, DMODEL);
        convT_launch(wv, bh + (size_t)2 * DMODEL * DMODEL, bl + (size_t)2 * DMODEL * DMODEL, DMODEL, DMODEL);
        gemm_launch(ah, al, bh, bl, nullptr, qkv, nullptr, nullptr,
                    BT, QKVLD, DMODEL, 0);

        attn_tile_kernel<<<dim3(TLEN / 64, NHEAD, BATCH), 256>>>(qkv, y);

        resln_kernel<<<BT, 256>>>(y, x, ln1_g + (size_t)l * DMODEL,
                                  ln1_b + (size_t)l * DMODEL, x, ah, al);

        convT_launch(W1 + (size_t)l * DMODEL * FFDIM, bh, bl, DMODEL, FFDIM);
        gemm_launch(ah, al, bh, bl, b1 + (size_t)l * FFDIM, nullptr,
                    ch, cl, BT, FFDIM, DMODEL, 1);

        convT_launch(W2 + (size_t)l * FFDIM * DMODEL, bh, bl, FFDIM, DMODEL);
        gemm_launch(ch, cl, bh, bl, b2 + (size_t)l * DMODEL, y,
                    nullptr, nullptr, BT, DMODEL, FFDIM, 0);

        resln_kernel<<<BT, 256>>>(y, x, ln2_g + (size_t)l * DMODEL,
                                  ln2_b + (size_t)l * DMODEL, x, ah, al);
    }

    // ---- lm head: fp16 2-product (A single f16, B hi/lo f16) ----
    conv_f16_kernel<<<(BT * DMODEL / 4 + 255) / 256, 256>>>(x, fh, BT * DMODEL / 4);
    {
        dim3 grid((VOCAB + 31) / 32, DMODEL / 32);
        convT_f16_kernel<<<grid, dim3(32, 8)>>>(head_w, (__half*)bh, (__half*)bl,
                                                DMODEL, VOCAB);
    }
    {
        dim3 grid((VOCAB + 127) / 128, (BT + 127) / 128);
        gemm_f16_kernel<<<grid, 256, FSMEM_BYTES>>>(fh, (const __half*)bh, (const __half*)bl,
                                                    head_b, out, BT, VOCAB, DMODEL);
    }

    loss_row_kernel<<<BT, 256>>>(out, targets, rl);
    if ((size_t)out_size >= logits_n + 1)
        loss_final_kernel<<<1, 256>>>(rl, out + logits_n);
}

// round 13
// speedup vs baseline: 8.6820x; 1.0945x over previous
#include <cuda_runtime.h>
#include <cuda_bf16.h>
#include <cuda_fp16.h>
#include <math.h>
#include <stdint.h>

// ---------------- problem constants ----------------
#define VOCAB 50257
#define DMODEL 768
#define NHEAD 12
#define HDIM 64
#define TLEN 1024
#define NLAYER 6
#define BATCH 4
#define BT (BATCH * TLEN)     // 4096
#define FFDIM (4 * DMODEL)    // 3072
#define QKVLD (3 * DMODEL)    // 2304
#define LNEPS 1e-5f

// ---------------- scratch (device globals: alloc-free rule) ----------------
__device__ __align__(128) float g_x  [BT * DMODEL];
__device__ __align__(128) float g_y  [BT * DMODEL];
__device__ __align__(128) float g_qkv[BT * QKVLD];
__device__ __align__(128) float g_rowloss[BT];

// bf16 hi/lo activations: residual-stream inputs (K=768)
__device__ __align__(128) __nv_bfloat16 g_ah[BT * DMODEL];
__device__ __align__(128) __nv_bfloat16 g_al[BT * DMODEL];
// bf16 hi/lo FFN hidden (K=3072)
__device__ __align__(128) __nv_bfloat16 g_ch[BT * FFDIM];
__device__ __align__(128) __nv_bfloat16 g_cl[BT * FFDIM];
// bf16 hi/lo transposed weights (max 50257 x 768); reused as fp16 for head
__device__ __align__(128) __nv_bfloat16 g_bh[(size_t)VOCAB * DMODEL];
__device__ __align__(128) __nv_bfloat16 g_bl[(size_t)VOCAB * DMODEL];
// fp16 activations for head GEMM
__device__ __align__(128) __half g_fh[BT * DMODEL];

// ---------------- split helpers ----------------
__device__ __forceinline__ void split2(float v, __nv_bfloat16& h, __nv_bfloat16& l)
{
    h = __float2bfloat16_rn(v);
    l = __float2bfloat16_rn(v - __bfloat162float(h));
}

// ---------------- embedding (fused hi/lo split) ----------------
__global__ void embed_kernel(const int* __restrict__ idx,
                             const float* __restrict__ tok,
                             const float* __restrict__ pos,
                             float* __restrict__ x,
                             __nv_bfloat16* __restrict__ xh,
                             __nv_bfloat16* __restrict__ xl)
{
    int i = blockIdx.x * blockDim.x + threadIdx.x;
    if (i < BT * DMODEL) {
        int row = i / DMODEL;
        int d   = i - row * DMODEL;
        int t   = row % TLEN;
        float v = tok[(size_t)idx[row] * DMODEL + d] + pos[(size_t)t * DMODEL + d];
        x[i] = v;
        __nv_bfloat16 h, l;
        split2(v, h, l);
        xh[i] = h;
        xl[i] = l;
    }
}

// ---------------- fp32 -> fp16 convert (head activations) ----------------
__global__ void conv_f16_kernel(const float* __restrict__ A,
                                __half* __restrict__ H, int n4)
{
    int i = blockIdx.x * blockDim.x + threadIdx.x;
    if (i < n4) {
        float4 v = *(const float4*)(A + 4 * (size_t)i);
        __half h[4];
        h[0] = __float2half_rn(v.x); h[1] = __float2half_rn(v.y);
        h[2] = __float2half_rn(v.z); h[3] = __float2half_rn(v.w);
        *(uint2*)(H + 4 * (size_t)i) = *(uint2*)h;
    }
}

// ---------------- weight convert + transpose: bf16 hi/lo ----------------
__global__ void convT_kernel(const float* __restrict__ B,
                             __nv_bfloat16* __restrict__ Th,
                             __nv_bfloat16* __restrict__ Tl,
                             int K, int N)
{
    __shared__ float tile[32][33];
    int n0 = blockIdx.x * 32;
    int k0 = blockIdx.y * 32;
    int tx = threadIdx.x;    // 32
    int ty = threadIdx.y;    // 8
    #pragma unroll
    for (int i = 0; i < 4; i++) {
        int k = k0 + ty + 8 * i;
        int n = n0 + tx;
        tile[ty + 8 * i][tx] = (n < N) ? B[(size_t)k * N + n] : 0.f;
    }
    __syncthreads();
    #pragma unroll
    for (int i = 0; i < 4; i++) {
        int n = n0 + ty + 8 * i;
        int k = k0 + tx;
        if (n < N) {
            __nv_bfloat16 h, l;
            split2(tile[tx][ty + 8 * i], h, l);
            Th[(size_t)n * K + k] = h;
            Tl[(size_t)n * K + k] = l;
        }
    }
}

// ---------------- weight convert + transpose: fp16 single (head) ----------------
__global__ void convT_f16_kernel(const float* __restrict__ B,
                                 __half* __restrict__ Th,
                                 int K, int N)
{
    __shared__ float tile[32][33];
    int n0 = blockIdx.x * 32;
    int k0 = blockIdx.y * 32;
    int tx = threadIdx.x;
    int ty = threadIdx.y;
    #pragma unroll
    for (int i = 0; i < 4; i++) {
        int k = k0 + ty + 8 * i;
        int n = n0 + tx;
        tile[ty + 8 * i][tx] = (n < N) ? B[(size_t)k * N + n] : 0.f;
    }
    __syncthreads();
    #pragma unroll
    for (int i = 0; i < 4; i++) {
        int n = n0 + ty + 8 * i;
        int k = k0 + tx;
        if (n < N)
            Th[(size_t)n * K + k] = __float2half_rn(tile[tx][ty + 8 * i]);
    }
}

// ======== shared GEMM infrastructure ========
#define TC_ARRB   8192u                 // bytes per array per stage (128 rows x 64B)
#define TC_STAGEB (4 * TC_ARRB)         // bf16 kernel: 4 arrays
#define GSMEM_BYTES (3 * TC_STAGEB)     // 98304 B
#define TF_STAGEB (2 * TC_ARRB)         // f16 kernel: 2 arrays (A, B)
#define FSMEM_BYTES (3 * TF_STAGEB)     // 49152 B

__device__ __forceinline__ uint32_t swoff(int row, int ch)
{
    return (uint32_t)(row * 64 + (((ch ^ (row >> 1)) & 3) << 4));
}

__device__ __forceinline__ void mma_bf16(float c[4], const uint32_t a[4], const uint32_t b[2])
{
    asm volatile(
        "mma.sync.aligned.m16n8k16.row.col.f32.bf16.bf16.f32 "
        "{%0,%1,%2,%3}, {%4,%5,%6,%7}, {%8,%9}, {%0,%1,%2,%3};\n"
        : "+f"(c[0]), "+f"(c[1]), "+f"(c[2]), "+f"(c[3])
        : "r"(a[0]), "r"(a[1]), "r"(a[2]), "r"(a[3]), "r"(b[0]), "r"(b[1]));
}

__device__ __forceinline__ void mma_f16(float c[4], const uint32_t a[4], const uint32_t b[2])
{
    asm volatile(
        "mma.sync.aligned.m16n8k16.row.col.f32.f16.f16.f32 "
        "{%0,%1,%2,%3}, {%4,%5,%6,%7}, {%8,%9}, {%0,%1,%2,%3};\n"
        : "+f"(c[0]), "+f"(c[1]), "+f"(c[2]), "+f"(c[3])
        : "r"(a[0]), "r"(a[1]), "r"(a[2]), "r"(a[3]), "r"(b[0]), "r"(b[1]));
}

__device__ __forceinline__ void ldsm4(uint32_t r[4], uint32_t addr)
{
    asm volatile("ldmatrix.sync.aligned.m8n8.x4.shared.b16 {%0,%1,%2,%3}, [%4];\n"
                 : "=r"(r[0]), "=r"(r[1]), "=r"(r[2]), "=r"(r[3]) : "r"(addr));
}

// ======== bf16 3-product GEMM (layers): 128x128, BK=32, 3-stage, 2 CTA/SM ========
__device__ __forceinline__ void gemm_load_stage(
    uint32_t sbase, int s, int kt, int tid,
    const __nv_bfloat16* Ah, const __nv_bfloat16* Al,
    const __nv_bfloat16* Bh, const __nv_bfloat16* Bl,
    int rowBase, int colBase, int M, int N, int K)
{
    #pragma unroll
    for (int j = 0; j < 8; j++) {
        int c   = tid + j * 256;
        int arr = c >> 9;          // 0:Ah 1:Al 2:Bh 3:Bl
        int cc  = c & 511;
        int row = cc >> 2;
        int ch  = cc & 3;
        const __nv_bfloat16* bp = (arr == 0) ? Ah : (arr == 1) ? Al
                                 : (arr == 2) ? Bh : Bl;
        bool isB = (arr >= 2);
        int lim  = isB ? N : M;
        int grow = (isB ? colBase : rowBase) + row;
        int grow_c = (grow < lim) ? grow : (lim - 1);
        const void* gptr = bp + (size_t)grow_c * K + kt * 32 + ch * 8;
        uint32_t daddr = sbase + (uint32_t)s * TC_STAGEB + (uint32_t)arr * TC_ARRB
                       + swoff(row, ch);
        int sz = (grow < lim) ? 16 : 0;
        asm volatile("cp.async.cg.shared.global [%0], [%1], 16, %2;\n"
                     :: "r"(daddr), "l"(gptr), "r"(sz));
    }
    asm volatile("cp.async.commit_group;\n" ::);
}

__global__ __launch_bounds__(256, 2)
void gemm_bf16_kernel(const __nv_bfloat16* __restrict__ Ah,
                      const __nv_bfloat16* __restrict__ Al,
                      const __nv_bfloat16* __restrict__ Bh,
                      const __nv_bfloat16* __restrict__ Bl,
                      const float* __restrict__ bias,
                      float* __restrict__ C,
                      __nv_bfloat16* __restrict__ Chi,
                      __nv_bfloat16* __restrict__ Clo,
                      int M, int N, int K, int relu)
{
    extern __shared__ __nv_bfloat16 smem[];
    uint32_t sbase = (uint32_t)__cvta_generic_to_shared(smem);

    int tid  = threadIdx.x;
    int warp = tid >> 5;
    int lane = tid & 31;
    int m0 = (warp >> 1) * 32;
    int n0 = (warp & 1) * 64;
    int rowBase = blockIdx.y * 128;
    int colBase = blockIdx.x * 128;
    int KT = K / 32;

    bool vec2N = ((N & 1) == 0);

    float acc[2][8][4];
    #pragma unroll
    for (int i = 0; i < 2; i++)
        #pragma unroll
        for (int j = 0; j < 8; j++)
            #pragma unroll
            for (int r = 0; r < 4; r++) acc[i][j][r] = 0.f;

    gemm_load_stage(sbase, 0, 0, tid, Ah, Al, Bh, Bl, rowBase, colBase, M, N, K);
    gemm_load_stage(sbase, 1, 1, tid, Ah, Al, Bh, Bl, rowBase, colBase, M, N, K);

    for (int kt = 0; kt < KT; kt++) {
        if (kt < KT - 1) asm volatile("cp.async.wait_group 1;\n" ::);
        else             asm volatile("cp.async.wait_group 0;\n" ::);
        __syncthreads();

        if (kt + 2 < KT)
            gemm_load_stage(sbase, (kt + 2) % 3, kt + 2, tid,
                            Ah, Al, Bh, Bl, rowBase, colBase, M, N, K);

        int s = kt % 3;
        uint32_t ah_b = sbase + (uint32_t)s * TC_STAGEB + 0 * TC_ARRB;
        uint32_t al_b = sbase + (uint32_t)s * TC_STAGEB + 1 * TC_ARRB;
        uint32_t bh_b = sbase + (uint32_t)s * TC_STAGEB + 2 * TC_ARRB;
        uint32_t bl_b = sbase + (uint32_t)s * TC_STAGEB + 3 * TC_ARRB;

        #pragma unroll
        for (int ks = 0; ks < 2; ks++) {
            uint32_t ahf[2][4], alf[2][4], bhf[4][4], blf[4][4];
            #pragma unroll
            for (int i = 0; i < 2; i++) {
                int r = m0 + 16 * i + (lane & 15);
                uint32_t off = swoff(r, ks * 2 + (lane >> 4));
                ldsm4(ahf[i], ah_b + off);
                ldsm4(alf[i], al_b + off);
            }
            #pragma unroll
            for (int j = 0; j < 4; j++) {
                int r = n0 + 16 * j + ((lane >> 4) * 8 + (lane & 7));
                uint32_t off = swoff(r, ks * 2 + ((lane >> 3) & 1));
                ldsm4(bhf[j], bh_b + off);
                ldsm4(blf[j], bl_b + off);
            }
            #pragma unroll
            for (int i = 0; i < 2; i++)
                #pragma unroll
                for (int jj = 0; jj < 8; jj++)
                    mma_bf16(acc[i][jj], ahf[i], &bhf[jj >> 1][(jj & 1) * 2]);
            #pragma unroll
            for (int i = 0; i < 2; i++)
                #pragma unroll
                for (int jj = 0; jj < 8; jj++)
                    mma_bf16(acc[i][jj], ahf[i], &blf[jj >> 1][(jj & 1) * 2]);
            #pragma unroll
            for (int i = 0; i < 2; i++)
                #pragma unroll
                for (int jj = 0; jj < 8; jj++)
                    mma_bf16(acc[i][jj], alf[i], &bhf[jj >> 1][(jj & 1) * 2]);
        }
    }

    int g = lane >> 2, tg = lane & 3;
    #pragma unroll
    for (int i = 0; i < 2; i++) {
        #pragma unroll
        for (int jj = 0; jj < 8; jj++) {
            int col = colBase + n0 + 8 * jj + 2 * tg;
            #pragma unroll
            for (int h = 0; h < 2; h++) {
                int row = rowBase + m0 + 16 * i + g + 8 * h;
                if (row >= M) continue;
                float v0 = acc[i][jj][2 * h + 0];
                float v1 = acc[i][jj][2 * h + 1];
                if (bias) {
                    if (col < N)     v0 += bias[col];
                    if (col + 1 < N) v1 += bias[col + 1];
                }
                if (relu) { v0 = fmaxf(v0, 0.f); v1 = fmaxf(v1, 0.f); }
                if (Chi) {
                    if (col + 1 < N) {
                        __nv_bfloat16 p0h, p0l, p1h, p1l;
                        split2(v0, p0h, p0l);
                        split2(v1, p1h, p1l);
                        __nv_bfloat16 ph[2] = {p0h, p1h};
                        __nv_bfloat16 pl[2] = {p0l, p1l};
                        *(uint32_t*)(Chi + (size_t)row * N + col) = *(uint32_t*)ph;
                        *(uint32_t*)(Clo + (size_t)row * N + col) = *(uint32_t*)pl;
                    } else if (col < N) {
                        __nv_bfloat16 hh, ll;
                        split2(v0, hh, ll);
                        Chi[(size_t)row * N + col] = hh;
                        Clo[(size_t)row * N + col] = ll;
                    }
                } else {
                    float* dst = C + (size_t)row * N + col;
                    if (vec2N && col + 1 < N) {
                        *(float2*)dst = make_float2(v0, v1);
                    } else {
                        if (col < N)     dst[0] = v0;
                        if (col + 1 < N) dst[1] = v1;
                    }
                }
            }
        }
    }
}

// ======== fp16 single-product GEMM (head): A f16, B f16 ========
__device__ __forceinline__ void gemm_load_stage_f16(
    uint32_t sbase, int s, int kt, int tid,
    const __half* Ah, const __half* Bh,
    int rowBase, int colBase, int M, int N, int K)
{
    #pragma unroll
    for (int j = 0; j < 4; j++) {
        int c   = tid + j * 256;
        int arr = c >> 9;          // 0:A 1:B
        int cc  = c & 511;
        int row = cc >> 2;
        int ch  = cc & 3;
        const __half* bp = (arr == 0) ? Ah : Bh;
        bool isB = (arr >= 1);
        int lim  = isB ? N : M;
        int grow = (isB ? colBase : rowBase) + row;
        int grow_c = (grow < lim) ? grow : (lim - 1);
        const void* gptr = bp + (size_t)grow_c * K + kt * 32 + ch * 8;
        uint32_t daddr = sbase + (uint32_t)s * TF_STAGEB + (uint32_t)arr * TC_ARRB
                       + swoff(row, ch);
        int sz = (grow < lim) ? 16 : 0;
        asm volatile("cp.async.cg.shared.global [%0], [%1], 16, %2;\n"
                     :: "r"(daddr), "l"(gptr), "r"(sz));
    }
    asm volatile("cp.async.commit_group;\n" ::);
}

__global__ __launch_bounds__(256, 2)
void gemm_f16_kernel(const __half* __restrict__ Ah,
                     const __half* __restrict__ Bh,
                     const float* __restrict__ bias,
                     float* __restrict__ C,
                     int M, int N, int K)
{
    extern __shared__ __nv_bfloat16 smem[];
    uint32_t sbase = (uint32_t)__cvta_generic_to_shared(smem);

    int tid  = threadIdx.x;
    int warp = tid >> 5;
    int lane = tid & 31;
    int m0 = (warp >> 1) * 32;
    int n0 = (warp & 1) * 64;
    int rowBase = blockIdx.y * 128;
    int colBase = blockIdx.x * 128;
    int KT = K / 32;

    bool vec2N = ((N & 1) == 0);

    float acc[2][8][4];
    #pragma unroll
    for (int i = 0; i < 2; i++)
        #pragma unroll
        for (int j = 0; j < 8; j++)
            #pragma unroll
            for (int r = 0; r < 4; r++) acc[i][j][r] = 0.f;

    gemm_load_stage_f16(sbase, 0, 0, tid, Ah, Bh, rowBase, colBase, M, N, K);
    gemm_load_stage_f16(sbase, 1, 1, tid, Ah, Bh, rowBase, colBase, M, N, K);

    for (int kt = 0; kt < KT; kt++) {
        if (kt < KT - 1) asm volatile("cp.async.wait_group 1;\n" ::);
        else             asm volatile("cp.async.wait_group 0;\n" ::);
        __syncthreads();

        if (kt + 2 < KT)
            gemm_load_stage_f16(sbase, (kt + 2) % 3, kt + 2, tid,
                                Ah, Bh, rowBase, colBase, M, N, K);

        int s = kt % 3;
        uint32_t ah_b = sbase + (uint32_t)s * TF_STAGEB + 0 * TC_ARRB;
        uint32_t bh_b = sbase + (uint32_t)s * TF_STAGEB + 1 * TC_ARRB;

        #pragma unroll
        for (int ks = 0; ks < 2; ks++) {
            uint32_t ahf[2][4], bhf[4][4];
            #pragma unroll
            for (int i = 0; i < 2; i++) {
                int r = m0 + 16 * i + (lane & 15);
                uint32_t off = swoff(r, ks * 2 + (lane >> 4));
                ldsm4(ahf[i], ah_b + off);
            }
            #pragma unroll
            for (int j = 0; j < 4; j++) {
                int r = n0 + 16 * j + ((lane >> 4) * 8 + (lane & 7));
                uint32_t off = swoff(r, ks * 2 + ((lane >> 3) & 1));
                ldsm4(bhf[j], bh_b + off);
            }
            #pragma unroll
            for (int i = 0; i < 2; i++)
                #pragma unroll
                for (int jj = 0; jj < 8; jj++)
                    mma_f16(acc[i][jj], ahf[i], &bhf[jj >> 1][(jj & 1) * 2]);
        }
    }

    int g = lane >> 2, tg = lane & 3;
    #pragma unroll
    for (int i = 0; i < 2; i++) {
        #pragma unroll
        for (int jj = 0; jj < 8; jj++) {
            int col = colBase + n0 + 8 * jj + 2 * tg;
            #pragma unroll
            for (int h = 0; h < 2; h++) {
                int row = rowBase + m0 + 16 * i + g + 8 * h;
                if (row >= M) continue;
                float v0 = acc[i][jj][2 * h + 0];
                float v1 = acc[i][jj][2 * h + 1];
                if (bias) {
                    if (col < N)     v0 += bias[col];
                    if (col + 1 < N) v1 += bias[col + 1];
                }
                float* dst = C + (size_t)row * N + col;
                if (vec2N && col + 1 < N) {
                    *(float2*)dst = make_float2(v0, v1);
                } else {
                    if (col < N)     dst[0] = v0;
                    if (col + 1 < N) dst[1] = v1;
                }
            }
        }
    }
}

// ---------------- tiled flash attention (fp32, fused strided QKV) ----------------
__global__ __launch_bounds__(256)
void attn_tile_kernel(const float* __restrict__ qkv,
                      float* __restrict__ y)
{
    int qt = blockIdx.x;
    int h  = blockIdx.y;
    int b  = blockIdx.z;
    int tid = threadIdx.x;  // 256

    __shared__ float Qs[64][65];
    __shared__ float Ks[32][65];
    __shared__ float Vs[32][65];
    __shared__ float Ss[64][33];
    __shared__ float rowm[64], rowl[64], rowa[64];

    size_t headq = (size_t)b * TLEN * QKVLD + (size_t)h * HDIM;
    size_t heady = (size_t)b * TLEN * DMODEL + (size_t)h * HDIM;
    int q0 = qt * 64;

    {
        int r = tid >> 2, c0 = (tid & 3) * 16;
        const float* src = qkv + headq + (size_t)(q0 + r) * QKVLD + c0;
        #pragma unroll
        for (int i = 0; i < 4; i++) {
            float4 t4 = *(const float4*)(src + 4 * i);
            Qs[r][c0 + 4 * i + 0] = t4.x;
            Qs[r][c0 + 4 * i + 1] = t4.y;
            Qs[r][c0 + 4 * i + 2] = t4.z;
            Qs[r][c0 + 4 * i + 3] = t4.w;
        }
    }
    if (tid < 64) { rowm[tid] = -1e30f; rowl[tid] = 0.f; }

    float o[4][4];
    #pragma unroll
    for (int i = 0; i < 4; i++)
        #pragma unroll
        for (int j = 0; j < 4; j++) o[i][j] = 0.f;

    int tx = tid & 15, ty = tid >> 4;
    __syncthreads();

    for (int s0 = 0; s0 < q0 + 64; s0 += 32) {
        {
            int kr = tid >> 3, kc = (tid & 7) * 8;
            const float* ksrc = qkv + headq + DMODEL     + (size_t)(s0 + kr) * QKVLD + kc;
            const float* vsrc = qkv + headq + 2 * DMODEL + (size_t)(s0 + kr) * QKVLD + kc;
            #pragma unroll
            for (int i = 0; i < 2; i++) {
                float4 t4 = *(const float4*)(ksrc + 4 * i);
                Ks[kr][kc + 4 * i + 0] = t4.x; Ks[kr][kc + 4 * i + 1] = t4.y;
                Ks[kr][kc + 4 * i + 2] = t4.z; Ks[kr][kc + 4 * i + 3] = t4.w;
                float4 u4 = *(const float4*)(vsrc + 4 * i);
                Vs[kr][kc + 4 * i + 0] = u4.x; Vs[kr][kc + 4 * i + 1] = u4.y;
                Vs[kr][kc + 4 * i + 2] = u4.z; Vs[kr][kc + 4 * i + 3] = u4.w;
            }
        }
        __syncthreads();

        float accv[4][2];
        #pragma unroll
        for (int i = 0; i < 4; i++) { accv[i][0] = 0.f; accv[i][1] = 0.f; }
        for (int d = 0; d < 64; d++) {
            float bv0 = Ks[tx][d], bv1 = Ks[tx + 16][d];
            #pragma unroll
            for (int i = 0; i < 4; i++) {
                float av = Qs[ty + 16 * i][d];
                accv[i][0] += av * bv0;
                accv[i][1] += av * bv1;
            }
        }
        #pragma unroll
        for (int i = 0; i < 4; i++)
            #pragma unroll
            for (int jj = 0; jj < 2; jj++) {
                int r = ty + 16 * i, cc = tx + 16 * jj;
                int gq = q0 + r, gs = s0 + cc;
                Ss[r][cc] = (gs <= gq) ? accv[i][jj] * 0.125f : -1e30f;
            }
        __syncthreads();

        if (tid < 64) {
            float mo = rowm[tid];
            float mx = mo;
            #pragma unroll 8
            for (int cc = 0; cc < 32; cc++) mx = fmaxf(mx, Ss[tid][cc]);
            float alpha = __expf(mo - mx);
            float sum = 0.f;
            #pragma unroll 8
            for (int cc = 0; cc < 32; cc++) {
                float p = __expf(Ss[tid][cc] - mx);
                Ss[tid][cc] = p;
                sum += p;
            }
            rowl[tid] = rowl[tid] * alpha + sum;
            rowm[tid] = mx;
            rowa[tid] = alpha;
        }
        __syncthreads();

        #pragma unroll
        for (int i = 0; i < 4; i++) {
            float al = rowa[ty + 16 * i];
            #pragma unroll
            for (int jj = 0; jj < 4; jj++) o[i][jj] *= al;
        }
        for (int cc = 0; cc < 32; cc++) {
            float p0 = Ss[ty][cc], p1 = Ss[ty + 16][cc];
            float p2 = Ss[ty + 32][cc], p3 = Ss[ty + 48][cc];
            #pragma unroll
            for (int jj = 0; jj < 4; jj++) {
                float vv = Vs[cc][tx + 16 * jj];
                o[0][jj] += p0 * vv;
                o[1][jj] += p1 * vv;
                o[2][jj] += p2 * vv;
                o[3][jj] += p3 * vv;
            }
        }
        __syncthreads();
    }

    #pragma unroll
    for (int i = 0; i < 4; i++) {
        int r = ty + 16 * i;
        float inv = 1.f / rowl[r];
        #pragma unroll
        for (int jj = 0; jj < 4; jj++) {
            int cc = tx + 16 * jj;
            y[heady + (size_t)(q0 + r) * DMODEL + cc] = o[i][jj] * inv;
        }
    }
}

// ---------------- residual + layernorm (fused hi/lo split) ----------------
__global__ void resln_kernel(const float* __restrict__ xin,
                             const float* __restrict__ res,
                             const float* __restrict__ gamma,
                             const float* __restrict__ beta,
                             float* __restrict__ xout,
                             __nv_bfloat16* __restrict__ xh,
                             __nv_bfloat16* __restrict__ xl)
{
    int row = blockIdx.x;
    int tid = threadIdx.x;   // 256
    __shared__ float red[256];

    float vals[3];
    float s1 = 0.f;
    #pragma unroll
    for (int i = 0; i < 3; i++) {
        int cidx = tid + i * 256;
        float vv = xin[(size_t)row * DMODEL + cidx] + res[(size_t)row * DMODEL + cidx];
        vals[i] = vv;
        s1 += vv;
    }
    red[tid] = s1;
    __syncthreads();
    for (int off = 128; off > 0; off >>= 1) {
        if (tid < off) red[tid] += red[tid + off];
        __syncthreads();
    }
    float mu = red[0] * (1.f / DMODEL);
    __syncthreads();

    float s2 = 0.f;
    #pragma unroll
    for (int i = 0; i < 3; i++) {
        float dv = vals[i] - mu;
        s2 += dv * dv;
    }
    red[tid] = s2;
    __syncthreads();
    for (int off = 128; off > 0; off >>= 1) {
        if (tid < off) red[tid] += red[tid + off];
        __syncthreads();
    }
    float inv = rsqrtf(red[0] * (1.f / DMODEL) + LNEPS);
    __syncthreads();

    #pragma unroll
    for (int i = 0; i < 3; i++) {
        int cidx = tid + i * 256;
        float v = (vals[i] - mu) * inv * gamma[cidx] + beta[cidx];
        xout[(size_t)row * DMODEL + cidx] = v;
        __nv_bfloat16 h, l;
        split2(v, h, l);
        xh[(size_t)row * DMODEL + cidx] = h;
        xl[(size_t)row * DMODEL + cidx] = l;
    }
}

// ---------------- cross-entropy: one-pass online logsumexp ----------------
__global__ void loss_row_kernel(const float* __restrict__ logits,
                                const int* __restrict__ tgt,
                                float* __restrict__ rowloss)
{
    int row = blockIdx.x;
    int tid = threadIdx.x;   // 256
    const float* lr = logits + (size_t)row * VOCAB;
    __shared__ float sm[256], ss[256];

    float m = -1e30f, s = 0.f;
    for (int cc = tid; cc < VOCAB; cc += 256) {
        float v = lr[cc];
        if (v > m) { s = s * __expf(m - v) + 1.f; m = v; }
        else       { s += __expf(v - m); }
    }
    sm[tid] = m; ss[tid] = s;
    __syncthreads();
    for (int off = 128; off > 0; off >>= 1) {
        if (tid < off) {
            float m2 = sm[tid + off], s2 = ss[tid + off];
            float m1 = sm[tid],       s1 = ss[tid];
            float mm = fmaxf(m1, m2);
            sm[tid] = mm;
            ss[tid] = s1 * __expf(m1 - mm) + s2 * __expf(m2 - mm);
        }
        __syncthreads();
    }
    if (tid == 0)
        rowloss[row] = -(lr[tgt[row]] - sm[0] - logf(ss[0]));
}

__global__ void loss_final_kernel(const float* __restrict__ rowloss,
                                  float* __restrict__ out)
{
    int tid = threadIdx.x;   // 256
    __shared__ float red[256];
    float s = 0.f;
    for (int i = tid; i < BT; i += 256) s += rowloss[i];
    red[tid] = s;
    __syncthreads();
    for (int off = 128; off > 0; off >>= 1) {
        if (tid < off) red[tid] += red[tid + off];
        __syncthreads();
    }
    if (tid == 0) out[0] = red[0] * (1.f / BT);
}

// ---------------- host orchestration ----------------
static inline void convT_launch(const float* B, __nv_bfloat16* Th, __nv_bfloat16* Tl, int K, int N)
{
    dim3 grid((N + 31) / 32, K / 32);
    convT_kernel<<<grid, dim3(32, 8)>>>(B, Th, Tl, K, N);
}

static inline void gemm_launch(const __nv_bfloat16* Ah, const __nv_bfloat16* Al,
                               const __nv_bfloat16* Bh, const __nv_bfloat16* Bl,
                               const float* bias, float* C,
                               __nv_bfloat16* Chi, __nv_bfloat16* Clo,
                               int M, int N, int K, int relu)
{
    dim3 grid((N + 127) / 128, (M + 127) / 128);
    gemm_bf16_kernel<<<grid, 256, GSMEM_BYTES>>>(Ah, Al, Bh, Bl, bias, C, Chi, Clo,
                                                 M, N, K, relu);
}

extern "C" void kernel_launch(void* const* d_in, const int* in_sizes, int n_in,
                              void* d_out, int out_size)
{
    const int*   idx     = (const int*)  d_in[0];
    const int*   targets = (const int*)  d_in[1];
    const float* tok_emb = (const float*)d_in[2];
    const float* pos_emb = (const float*)d_in[3];
    const float* Wq      = (const float*)d_in[4];
    const float* Wk      = (const float*)d_in[5];
    const float* Wv      = (const float*)d_in[6];
    const float* ln1_g   = (const float*)d_in[7];
    const float* ln1_b   = (const float*)d_in[8];
    const float* W1      = (const float*)d_in[9];
    const float* b1      = (const float*)d_in[10];
    const float* W2      = (const float*)d_in[11];
    const float* b2      = (const float*)d_in[12];
    const float* ln2_g   = (const float*)d_in[13];
    const float* ln2_b   = (const float*)d_in[14];
    const float* head_w  = (const float*)d_in[15];
    const float* head_b  = (const float*)d_in[16];

    cudaFuncSetAttribute(gemm_bf16_kernel,
                         cudaFuncAttributeMaxDynamicSharedMemorySize, GSMEM_BYTES);
    cudaFuncSetAttribute(gemm_f16_kernel,
                         cudaFuncAttributeMaxDynamicSharedMemorySize, FSMEM_BYTES);

    void* p;
    float *x, *y, *qkv, *rl;
    __nv_bfloat16 *ah, *al, *ch, *cl, *bh, *bl;
    __half *fh;
    cudaGetSymbolAddress(&p, g_x);   x   = (float*)p;
    cudaGetSymbolAddress(&p, g_y);   y   = (float*)p;
    cudaGetSymbolAddress(&p, g_qkv); qkv = (float*)p;
    cudaGetSymbolAddress(&p, g_rowloss); rl = (float*)p;
    cudaGetSymbolAddress(&p, g_ah);  ah  = (__nv_bfloat16*)p;
    cudaGetSymbolAddress(&p, g_al);  al  = (__nv_bfloat16*)p;
    cudaGetSymbolAddress(&p, g_ch);  ch  = (__nv_bfloat16*)p;
    cudaGetSymbolAddress(&p, g_cl);  cl  = (__nv_bfloat16*)p;
    cudaGetSymbolAddress(&p, g_bh);  bh  = (__nv_bfloat16*)p;
    cudaGetSymbolAddress(&p, g_bl);  bl  = (__nv_bfloat16*)p;
    cudaGetSymbolAddress(&p, g_fh);  fh  = (__half*)p;

    float* out = (float*)d_out;
    size_t logits_n = (size_t)BT * VOCAB;

    embed_kernel<<<(BT * DMODEL + 255) / 256, 256>>>(idx, tok_emb, pos_emb,
                                                     x, ah, al);

    for (int l = 0; l < NLAYER; l++) {
        const float* wq = Wq + (size_t)l * DMODEL * DMODEL;
        const float* wk = Wk + (size_t)l * DMODEL * DMODEL;
        const float* wv = Wv + (size_t)l * DMODEL * DMODEL;

        convT_launch(wq, bh,                               bl,                               DMODEL, DMODEL);
        convT_launch(wk, bh + (size_t)DMODEL * DMODEL,     bl + (size_t)DMODEL * DMODEL,     DMODEL, DMODEL);
        convT_launch(wv, bh + (size_t)2 * DMODEL * DMODEL, bl + (size_t)2 * DMODEL * DMODEL, DMODEL, DMODEL);
        gemm_launch(ah, al, bh, bl, nullptr, qkv, nullptr, nullptr,
                    BT, QKVLD, DMODEL, 0);

        attn_tile_kernel<<<dim3(TLEN / 64, NHEAD, BATCH), 256>>>(qkv, y);

        resln_kernel<<<BT, 256>>>(y, x, ln1_g + (size_t)l * DMODEL,
                                  ln1_b + (size_t)l * DMODEL, x, ah, al);

        convT_launch(W1 + (size_t)l * DMODEL * FFDIM, bh, bl, DMODEL, FFDIM);
        gemm_launch(ah, al, bh, bl, b1 + (size_t)l * FFDIM, nullptr,
                    ch, cl, BT, FFDIM, DMODEL, 1);

        convT_launch(W2 + (size_t)l * FFDIM * DMODEL, bh, bl, FFDIM, DMODEL);
        gemm_launch(ch, cl, bh, bl, b2 + (size_t)l * DMODEL, y,
                    nullptr, nullptr, BT, DMODEL, FFDIM, 0);

        resln_kernel<<<BT, 256>>>(y, x, ln2_g + (size_t)l * DMODEL,
                                  ln2_b + (size_t)l * DMODEL, x, ah, al);
    }

    // ---- lm head: fp16 single-product (A f16, B f16-hi only) ----
    conv_f16_kernel<<<(BT * DMODEL / 4 + 255) / 256, 256>>>(x, fh, BT * DMODEL / 4);
    {
        dim3 grid((VOCAB + 31) / 32, DMODEL / 32);
        convT_f16_kernel<<<grid, dim3(32, 8)>>>(head_w, (__half*)bh, DMODEL, VOCAB);
    }
    {
        dim3 grid((VOCAB + 127) / 128, (BT + 127) / 128);
        gemm_f16_kernel<<<grid, 256, FSMEM_BYTES>>>(fh, (const __half*)bh,
                                                    head_b, out, BT, VOCAB, DMODEL);
    }

    loss_row_kernel<<<BT, 256>>>(out, targets, rl);
    if ((size_t)out_size >= logits_n + 1)
        loss_final_kernel<<<1, 256>>>(rl, out + logits_n);
}

// round 14
// speedup vs baseline: 10.8507x; 1.2498x over previous
#include <cuda_runtime.h>
#include <cuda_bf16.h>
#include <cuda_fp16.h>
#include <math.h>
#include <stdint.h>

// ---------------- problem constants ----------------
#define VOCAB 50257
#define DMODEL 768
#define NHEAD 12
#define HDIM 64
#define TLEN 1024
#define NLAYER 6
#define BATCH 4
#define BT (BATCH * TLEN)     // 4096
#define FFDIM (4 * DMODEL)    // 3072
#define QKVLD (3 * DMODEL)    // 2304
#define LNEPS 1e-5f

// ---------------- scratch (device globals: alloc-free rule) ----------------
__device__ __align__(128) float g_x  [BT * DMODEL];
__device__ __align__(128) float g_y  [BT * DMODEL];
__device__ __align__(128) float g_qkv[BT * QKVLD];
__device__ __align__(128) float g_rowloss[BT];

__device__ __align__(128) __nv_bfloat16 g_ah[BT * DMODEL];
__device__ __align__(128) __nv_bfloat16 g_al[BT * DMODEL];
__device__ __align__(128) __nv_bfloat16 g_ch[BT * FFDIM];
__device__ __align__(128) __nv_bfloat16 g_cl[BT * FFDIM];
__device__ __align__(128) __nv_bfloat16 g_bh[(size_t)VOCAB * DMODEL];
__device__ __align__(128) __nv_bfloat16 g_bl[(size_t)VOCAB * DMODEL];
__device__ __align__(128) __half g_fh[BT * DMODEL];

// ---------------- split helpers ----------------
__device__ __forceinline__ void split2(float v, __nv_bfloat16& h, __nv_bfloat16& l)
{
    h = __float2bfloat16_rn(v);
    l = __float2bfloat16_rn(v - __bfloat162float(h));
}
__device__ __forceinline__ void split2h(float v, __half& h, __half& l)
{
    h = __float2half_rn(v);
    l = __float2half_rn(v - __half2float(h));
}

// ---------------- embedding (fused hi/lo split) ----------------
__global__ void embed_kernel(const int* __restrict__ idx,
                             const float* __restrict__ tok,
                             const float* __restrict__ pos,
                             float* __restrict__ x,
                             __nv_bfloat16* __restrict__ xh,
                             __nv_bfloat16* __restrict__ xl)
{
    int i = blockIdx.x * blockDim.x + threadIdx.x;
    if (i < BT * DMODEL) {
        int row = i / DMODEL;
        int d   = i - row * DMODEL;
        int t   = row % TLEN;
        float v = tok[(size_t)idx[row] * DMODEL + d] + pos[(size_t)t * DMODEL + d];
        x[i] = v;
        __nv_bfloat16 h, l;
        split2(v, h, l);
        xh[i] = h;
        xl[i] = l;
    }
}

// ---------------- fp32 -> fp16 convert (head activations) ----------------
__global__ void conv_f16_kernel(const float* __restrict__ A,
                                __half* __restrict__ H, int n4)
{
    int i = blockIdx.x * blockDim.x + threadIdx.x;
    if (i < n4) {
        float4 v = *(const float4*)(A + 4 * (size_t)i);
        __half h[4];
        h[0] = __float2half_rn(v.x); h[1] = __float2half_rn(v.y);
        h[2] = __float2half_rn(v.z); h[3] = __float2half_rn(v.w);
        *(uint2*)(H + 4 * (size_t)i) = *(uint2*)h;
    }
}

// ---------------- weight convert + transpose: bf16 hi/lo ----------------
__global__ void convT_kernel(const float* __restrict__ B,
                             __nv_bfloat16* __restrict__ Th,
                             __nv_bfloat16* __restrict__ Tl,
                             int K, int N)
{
    __shared__ float tile[32][33];
    int n0 = blockIdx.x * 32;
    int k0 = blockIdx.y * 32;
    int tx = threadIdx.x;    // 32
    int ty = threadIdx.y;    // 8
    #pragma unroll
    for (int i = 0; i < 4; i++) {
        int k = k0 + ty + 8 * i;
        int n = n0 + tx;
        tile[ty + 8 * i][tx] = (n < N) ? B[(size_t)k * N + n] : 0.f;
    }
    __syncthreads();
    #pragma unroll
    for (int i = 0; i < 4; i++) {
        int n = n0 + ty + 8 * i;
        int k = k0 + tx;
        if (n < N) {
            __nv_bfloat16 h, l;
            split2(tile[tx][ty + 8 * i], h, l);
            Th[(size_t)n * K + k] = h;
            Tl[(size_t)n * K + k] = l;
        }
    }
}

// ---------------- weight convert + transpose: fp16 single (head) ----------------
__global__ void convT_f16_kernel(const float* __restrict__ B,
                                 __half* __restrict__ Th,
                                 int K, int N)
{
    __shared__ float tile[32][33];
    int n0 = blockIdx.x * 32;
    int k0 = blockIdx.y * 32;
    int tx = threadIdx.x;
    int ty = threadIdx.y;
    #pragma unroll
    for (int i = 0; i < 4; i++) {
        int k = k0 + ty + 8 * i;
        int n = n0 + tx;
        tile[ty + 8 * i][tx] = (n < N) ? B[(size_t)k * N + n] : 0.f;
    }
    __syncthreads();
    #pragma unroll
    for (int i = 0; i < 4; i++) {
        int n = n0 + ty + 8 * i;
        int k = k0 + tx;
        if (n < N)
            Th[(size_t)n * K + k] = __float2half_rn(tile[tx][ty + 8 * i]);
    }
}

// ======== shared GEMM infrastructure ========
#define TC_ARRB   8192u
#define TC_STAGEB (4 * TC_ARRB)
#define GSMEM_BYTES (3 * TC_STAGEB)     // 98304
#define TF_STAGEB (2 * TC_ARRB)
#define FSMEM_BYTES (3 * TF_STAGEB)     // 49152

__device__ __forceinline__ uint32_t swoff(int row, int ch)
{
    return (uint32_t)(row * 64 + (((ch ^ (row >> 1)) & 3) << 4));
}

__device__ __forceinline__ void mma_bf16(float c[4], const uint32_t a[4], const uint32_t b[2])
{
    asm volatile(
        "mma.sync.aligned.m16n8k16.row.col.f32.bf16.bf16.f32 "
        "{%0,%1,%2,%3}, {%4,%5,%6,%7}, {%8,%9}, {%0,%1,%2,%3};\n"
        : "+f"(c[0]), "+f"(c[1]), "+f"(c[2]), "+f"(c[3])
        : "r"(a[0]), "r"(a[1]), "r"(a[2]), "r"(a[3]), "r"(b[0]), "r"(b[1]));
}

__device__ __forceinline__ void mma_f16(float c[4], const uint32_t a[4], const uint32_t b[2])
{
    asm volatile(
        "mma.sync.aligned.m16n8k16.row.col.f32.f16.f16.f32 "
        "{%0,%1,%2,%3}, {%4,%5,%6,%7}, {%8,%9}, {%0,%1,%2,%3};\n"
        : "+f"(c[0]), "+f"(c[1]), "+f"(c[2]), "+f"(c[3])
        : "r"(a[0]), "r"(a[1]), "r"(a[2]), "r"(a[3]), "r"(b[0]), "r"(b[1]));
}

__device__ __forceinline__ void ldsm4(uint32_t r[4], uint32_t addr)
{
    asm volatile("ldmatrix.sync.aligned.m8n8.x4.shared.b16 {%0,%1,%2,%3}, [%4];\n"
                 : "=r"(r[0]), "=r"(r[1]), "=r"(r[2]), "=r"(r[3]) : "r"(addr));
}

// ======== bf16 3-product GEMM (layers) ========
__device__ __forceinline__ void gemm_load_stage(
    uint32_t sbase, int s, int kt, int tid,
    const __nv_bfloat16* Ah, const __nv_bfloat16* Al,
    const __nv_bfloat16* Bh, const __nv_bfloat16* Bl,
    int rowBase, int colBase, int M, int N, int K)
{
    #pragma unroll
    for (int j = 0; j < 8; j++) {
        int c   = tid + j * 256;
        int arr = c >> 9;
        int cc  = c & 511;
        int row = cc >> 2;
        int ch  = cc & 3;
        const __nv_bfloat16* bp = (arr == 0) ? Ah : (arr == 1) ? Al
                                 : (arr == 2) ? Bh : Bl;
        bool isB = (arr >= 2);
        int lim  = isB ? N : M;
        int grow = (isB ? colBase : rowBase) + row;
        int grow_c = (grow < lim) ? grow : (lim - 1);
        const void* gptr = bp + (size_t)grow_c * K + kt * 32 + ch * 8;
        uint32_t daddr = sbase + (uint32_t)s * TC_STAGEB + (uint32_t)arr * TC_ARRB
                       + swoff(row, ch);
        int sz = (grow < lim) ? 16 : 0;
        asm volatile("cp.async.cg.shared.global [%0], [%1], 16, %2;\n"
                     :: "r"(daddr), "l"(gptr), "r"(sz));
    }
    asm volatile("cp.async.commit_group;\n" ::);
}

__global__ __launch_bounds__(256, 2)
void gemm_bf16_kernel(const __nv_bfloat16* __restrict__ Ah,
                      const __nv_bfloat16* __restrict__ Al,
                      const __nv_bfloat16* __restrict__ Bh,
                      const __nv_bfloat16* __restrict__ Bl,
                      const float* __restrict__ bias,
                      float* __restrict__ C,
                      __nv_bfloat16* __restrict__ Chi,
                      __nv_bfloat16* __restrict__ Clo,
                      int M, int N, int K, int relu)
{
    extern __shared__ __nv_bfloat16 smem[];
    uint32_t sbase = (uint32_t)__cvta_generic_to_shared(smem);

    int tid  = threadIdx.x;
    int warp = tid >> 5;
    int lane = tid & 31;
    int m0 = (warp >> 1) * 32;
    int n0 = (warp & 1) * 64;
    int rowBase = blockIdx.y * 128;
    int colBase = blockIdx.x * 128;
    int KT = K / 32;

    bool vec2N = ((N & 1) == 0);

    float acc[2][8][4];
    #pragma unroll
    for (int i = 0; i < 2; i++)
        #pragma unroll
        for (int j = 0; j < 8; j++)
            #pragma unroll
            for (int r = 0; r < 4; r++) acc[i][j][r] = 0.f;

    gemm_load_stage(sbase, 0, 0, tid, Ah, Al, Bh, Bl, rowBase, colBase, M, N, K);
    gemm_load_stage(sbase, 1, 1, tid, Ah, Al, Bh, Bl, rowBase, colBase, M, N, K);

    for (int kt = 0; kt < KT; kt++) {
        if (kt < KT - 1) asm volatile("cp.async.wait_group 1;\n" ::);
        else             asm volatile("cp.async.wait_group 0;\n" ::);
        __syncthreads();

        if (kt + 2 < KT)
            gemm_load_stage(sbase, (kt + 2) % 3, kt + 2, tid,
                            Ah, Al, Bh, Bl, rowBase, colBase, M, N, K);

        int s = kt % 3;
        uint32_t ah_b = sbase + (uint32_t)s * TC_STAGEB + 0 * TC_ARRB;
        uint32_t al_b = sbase + (uint32_t)s * TC_STAGEB + 1 * TC_ARRB;
        uint32_t bh_b = sbase + (uint32_t)s * TC_STAGEB + 2 * TC_ARRB;
        uint32_t bl_b = sbase + (uint32_t)s * TC_STAGEB + 3 * TC_ARRB;

        #pragma unroll
        for (int ks = 0; ks < 2; ks++) {
            uint32_t ahf[2][4], alf[2][4], bhf[4][4], blf[4][4];
            #pragma unroll
            for (int i = 0; i < 2; i++) {
                int r = m0 + 16 * i + (lane & 15);
                uint32_t off = swoff(r, ks * 2 + (lane >> 4));
                ldsm4(ahf[i], ah_b + off);
                ldsm4(alf[i], al_b + off);
            }
            #pragma unroll
            for (int j = 0; j < 4; j++) {
                int r = n0 + 16 * j + ((lane >> 4) * 8 + (lane & 7));
                uint32_t off = swoff(r, ks * 2 + ((lane >> 3) & 1));
                ldsm4(bhf[j], bh_b + off);
                ldsm4(blf[j], bl_b + off);
            }
            #pragma unroll
            for (int i = 0; i < 2; i++)
                #pragma unroll
                for (int jj = 0; jj < 8; jj++)
                    mma_bf16(acc[i][jj], ahf[i], &bhf[jj >> 1][(jj & 1) * 2]);
            #pragma unroll
            for (int i = 0; i < 2; i++)
                #pragma unroll
                for (int jj = 0; jj < 8; jj++)
                    mma_bf16(acc[i][jj], ahf[i], &blf[jj >> 1][(jj & 1) * 2]);
            #pragma unroll
            for (int i = 0; i < 2; i++)
                #pragma unroll
                for (int jj = 0; jj < 8; jj++)
                    mma_bf16(acc[i][jj], alf[i], &bhf[jj >> 1][(jj & 1) * 2]);
        }
    }

    int g = lane >> 2, tg = lane & 3;
    #pragma unroll
    for (int i = 0; i < 2; i++) {
        #pragma unroll
        for (int jj = 0; jj < 8; jj++) {
            int col = colBase + n0 + 8 * jj + 2 * tg;
            #pragma unroll
            for (int h = 0; h < 2; h++) {
                int row = rowBase + m0 + 16 * i + g + 8 * h;
                if (row >= M) continue;
                float v0 = acc[i][jj][2 * h + 0];
                float v1 = acc[i][jj][2 * h + 1];
                if (bias) {
                    if (col < N)     v0 += bias[col];
                    if (col + 1 < N) v1 += bias[col + 1];
                }
                if (relu) { v0 = fmaxf(v0, 0.f); v1 = fmaxf(v1, 0.f); }
                if (Chi) {
                    if (col + 1 < N) {
                        __nv_bfloat16 p0h, p0l, p1h, p1l;
                        split2(v0, p0h, p0l);
                        split2(v1, p1h, p1l);
                        __nv_bfloat16 ph[2] = {p0h, p1h};
                        __nv_bfloat16 pl[2] = {p0l, p1l};
                        *(uint32_t*)(Chi + (size_t)row * N + col) = *(uint32_t*)ph;
                        *(uint32_t*)(Clo + (size_t)row * N + col) = *(uint32_t*)pl;
                    } else if (col < N) {
                        __nv_bfloat16 hh, ll;
                        split2(v0, hh, ll);
                        Chi[(size_t)row * N + col] = hh;
                        Clo[(size_t)row * N + col] = ll;
                    }
                } else {
                    float* dst = C + (size_t)row * N + col;
                    if (vec2N && col + 1 < N) {
                        *(float2*)dst = make_float2(v0, v1);
                    } else {
                        if (col < N)     dst[0] = v0;
                        if (col + 1 < N) dst[1] = v1;
                    }
                }
            }
        }
    }
}

// ======== fp16 single-product GEMM (head) ========
__device__ __forceinline__ void gemm_load_stage_f16(
    uint32_t sbase, int s, int kt, int tid,
    const __half* Ah, const __half* Bh,
    int rowBase, int colBase, int M, int N, int K)
{
    #pragma unroll
    for (int j = 0; j < 4; j++) {
        int c   = tid + j * 256;
        int arr = c >> 9;
        int cc  = c & 511;
        int row = cc >> 2;
        int ch  = cc & 3;
        const __half* bp = (arr == 0) ? Ah : Bh;
        bool isB = (arr >= 1);
        int lim  = isB ? N : M;
        int grow = (isB ? colBase : rowBase) + row;
        int grow_c = (grow < lim) ? grow : (lim - 1);
        const void* gptr = bp + (size_t)grow_c * K + kt * 32 + ch * 8;
        uint32_t daddr = sbase + (uint32_t)s * TF_STAGEB + (uint32_t)arr * TC_ARRB
                       + swoff(row, ch);
        int sz = (grow < lim) ? 16 : 0;
        asm volatile("cp.async.cg.shared.global [%0], [%1], 16, %2;\n"
                     :: "r"(daddr), "l"(gptr), "r"(sz));
    }
    asm volatile("cp.async.commit_group;\n" ::);
}

__global__ __launch_bounds__(256, 2)
void gemm_f16_kernel(const __half* __restrict__ Ah,
                     const __half* __restrict__ Bh,
                     const float* __restrict__ bias,
                     float* __restrict__ C,
                     int M, int N, int K)
{
    extern __shared__ __nv_bfloat16 smem[];
    uint32_t sbase = (uint32_t)__cvta_generic_to_shared(smem);

    int tid  = threadIdx.x;
    int warp = tid >> 5;
    int lane = tid & 31;
    int m0 = (warp >> 1) * 32;
    int n0 = (warp & 1) * 64;
    int rowBase = blockIdx.y * 128;
    int colBase = blockIdx.x * 128;
    int KT = K / 32;

    bool vec2N = ((N & 1) == 0);

    float acc[2][8][4];
    #pragma unroll
    for (int i = 0; i < 2; i++)
        #pragma unroll
        for (int j = 0; j < 8; j++)
            #pragma unroll
            for (int r = 0; r < 4; r++) acc[i][j][r] = 0.f;

    gemm_load_stage_f16(sbase, 0, 0, tid, Ah, Bh, rowBase, colBase, M, N, K);
    gemm_load_stage_f16(sbase, 1, 1, tid, Ah, Bh, rowBase, colBase, M, N, K);

    for (int kt = 0; kt < KT; kt++) {
        if (kt < KT - 1) asm volatile("cp.async.wait_group 1;\n" ::);
        else             asm volatile("cp.async.wait_group 0;\n" ::);
        __syncthreads();

        if (kt + 2 < KT)
            gemm_load_stage_f16(sbase, (kt + 2) % 3, kt + 2, tid,
                                Ah, Bh, rowBase, colBase, M, N, K);

        int s = kt % 3;
        uint32_t ah_b = sbase + (uint32_t)s * TF_STAGEB + 0 * TC_ARRB;
        uint32_t bh_b = sbase + (uint32_t)s * TF_STAGEB + 1 * TC_ARRB;

        #pragma unroll
        for (int ks = 0; ks < 2; ks++) {
            uint32_t ahf[2][4], bhf[4][4];
            #pragma unroll
            for (int i = 0; i < 2; i++) {
                int r = m0 + 16 * i + (lane & 15);
                uint32_t off = swoff(r, ks * 2 + (lane >> 4));
                ldsm4(ahf[i], ah_b + off);
            }
            #pragma unroll
            for (int j = 0; j < 4; j++) {
                int r = n0 + 16 * j + ((lane >> 4) * 8 + (lane & 7));
                uint32_t off = swoff(r, ks * 2 + ((lane >> 3) & 1));
                ldsm4(bhf[j], bh_b + off);
            }
            #pragma unroll
            for (int i = 0; i < 2; i++)
                #pragma unroll
                for (int jj = 0; jj < 8; jj++)
                    mma_f16(acc[i][jj], ahf[i], &bhf[jj >> 1][(jj & 1) * 2]);
        }
    }

    int g = lane >> 2, tg = lane & 3;
    #pragma unroll
    for (int i = 0; i < 2; i++) {
        #pragma unroll
        for (int jj = 0; jj < 8; jj++) {
            int col = colBase + n0 + 8 * jj + 2 * tg;
            #pragma unroll
            for (int h = 0; h < 2; h++) {
                int row = rowBase + m0 + 16 * i + g + 8 * h;
                if (row >= M) continue;
                float v0 = acc[i][jj][2 * h + 0];
                float v1 = acc[i][jj][2 * h + 1];
                if (bias) {
                    if (col < N)     v0 += bias[col];
                    if (col + 1 < N) v1 += bias[col + 1];
                }
                float* dst = C + (size_t)row * N + col;
                if (vec2N && col + 1 < N) {
                    *(float2*)dst = make_float2(v0, v1);
                } else {
                    if (col < N)     dst[0] = v0;
                    if (col + 1 < N) dst[1] = v1;
                }
            }
        }
    }
}

// ======== tensor-core flash attention (fp16 hi/lo 3-product, 64q x 64k tiles) ========
// Smem byte layout (each f16 array = 2 segs x 64 rows x 64B = 8KB):
#define AQH 0u
#define AQL 8192u
#define AKH 16384u
#define AKL 24576u
#define AVH 32768u
#define AVL 40960u
#define APH 49152u
#define APL 57344u
#define ASS 65536u                          // fp32 S: 64 x 65
#define ATT_SMEM (65536 + 64 * 65 * 4)      // 82176 B

__global__ __launch_bounds__(256)
void attn_mma_kernel(const float* __restrict__ qkv,
                     float* __restrict__ y)
{
    extern __shared__ char asmem[];
    __shared__ float rowm[64], rowl[64], rowa[64];
    uint32_t sb = (uint32_t)__cvta_generic_to_shared(asmem);

    int tid  = threadIdx.x;
    int warp = tid >> 5;
    int lane = tid & 31;
    int g  = lane >> 2;
    int tg = lane & 3;
    int m0 = (warp >> 1) * 16;      // q rows of this warp
    int n0 = (warp & 1) * 32;       // keys (QK) / dims (PV) of this warp

    int qt = blockIdx.x;
    int h  = blockIdx.y;
    int b  = blockIdx.z;
    size_t headq = (size_t)b * TLEN * QKVLD + (size_t)h * HDIM;
    size_t heady = (size_t)b * TLEN * DMODEL + (size_t)h * HDIM;
    int q0 = qt * 64;

    // ---- load + convert Q tile (once) ----
    {
        int r  = tid >> 2;
        int c0 = (tid & 3) * 16;
        const float* src = qkv + headq + (size_t)(q0 + r) * QKVLD;
        #pragma unroll
        for (int i = 0; i < 4; i++) {
            int d = c0 + 4 * i;
            float4 v = *(const float4*)(src + d);
            const float* vv = &v.x;
            __half hh[4], ll[4];
            #pragma unroll
            for (int q = 0; q < 4; q++) split2h(vv[q], hh[q], ll[q]);
            uint32_t off = (uint32_t)((d >> 5) * 4096) + swoff(r, (d & 31) >> 3) + (d & 7) * 2;
            *(uint2*)(asmem + AQH + off) = *(uint2*)hh;
            *(uint2*)(asmem + AQL + off) = *(uint2*)ll;
        }
    }
    if (tid < 64) { rowm[tid] = -1e30f; rowl[tid] = 0.f; }

    float o[4][4];
    #pragma unroll
    for (int jj = 0; jj < 4; jj++)
        #pragma unroll
        for (int r = 0; r < 4; r++) o[jj][r] = 0.f;

    float* ssp = (float*)(asmem + ASS);
    int nt = qt + 1;

    for (int t = 0; t < nt; t++) {
        int s0 = t * 64;
        __syncthreads();   // protect K/V/P smem from prior PV reads

        // ---- load + convert K (row-major) and V (transposed) ----
        {
            int r  = tid >> 2;        // key row
            int c0 = (tid & 3) * 16;
            const float* ksrc = qkv + headq + DMODEL     + (size_t)(s0 + r) * QKVLD;
            const float* vsrc = qkv + headq + 2 * DMODEL + (size_t)(s0 + r) * QKVLD;
            uint32_t segk = (uint32_t)((r >> 5) * 4096);
            int kk = r & 31;
            #pragma unroll
            for (int i = 0; i < 4; i++) {
                int d = c0 + 4 * i;
                float4 kv = *(const float4*)(ksrc + d);
                const float* kvv = &kv.x;
                __half hh[4], ll[4];
                #pragma unroll
                for (int q = 0; q < 4; q++) split2h(kvv[q], hh[q], ll[q]);
                uint32_t off = (uint32_t)((d >> 5) * 4096) + swoff(r, (d & 31) >> 3) + (d & 7) * 2;
                *(uint2*)(asmem + AKH + off) = *(uint2*)hh;
                *(uint2*)(asmem + AKL + off) = *(uint2*)ll;

                float4 vv4 = *(const float4*)(vsrc + d);
                const float* vvv = &vv4.x;
                #pragma unroll
                for (int q = 0; q < 4; q++) {
                    __half vh, vl;
                    split2h(vvv[q], vh, vl);
                    uint32_t off2 = segk + swoff(d + q, kk >> 3) + (kk & 7) * 2;
                    *(__half*)(asmem + AVH + off2) = vh;
                    *(__half*)(asmem + AVL + off2) = vl;
                }
            }
        }
        __syncthreads();

        // ---- S = Q K^T (3-product) ----
        float sacc[4][4];
        #pragma unroll
        for (int jj = 0; jj < 4; jj++)
            #pragma unroll
            for (int r = 0; r < 4; r++) sacc[jj][r] = 0.f;

        #pragma unroll
        for (int seg = 0; seg < 2; seg++) {
            #pragma unroll
            for (int ks = 0; ks < 2; ks++) {
                uint32_t ahf[4], alf[4], bhf[2][4], blf[2][4];
                {
                    int r = m0 + (lane & 15);
                    uint32_t off = (uint32_t)(seg * 4096) + swoff(r, ks * 2 + (lane >> 4));
                    ldsm4(ahf, sb + AQH + off);
                    ldsm4(alf, sb + AQL + off);
                }
                #pragma unroll
                for (int j = 0; j < 2; j++) {
                    int r = n0 + 16 * j + ((lane >> 4) * 8 + (lane & 7));
                    uint32_t off = (uint32_t)(seg * 4096) + swoff(r, ks * 2 + ((lane >> 3) & 1));
                    ldsm4(bhf[j], sb + AKH + off);
                    ldsm4(blf[j], sb + AKL + off);
                }
                #pragma unroll
                for (int jj = 0; jj < 4; jj++)
                    mma_f16(sacc[jj], ahf, &bhf[jj >> 1][(jj & 1) * 2]);
                #pragma unroll
                for (int jj = 0; jj < 4; jj++)
                    mma_f16(sacc[jj], ahf, &blf[jj >> 1][(jj & 1) * 2]);
                #pragma unroll
                for (int jj = 0; jj < 4; jj++)
                    mma_f16(sacc[jj], alf, &bhf[jj >> 1][(jj & 1) * 2]);
            }
        }
        // write S (scale + causal mask)
        #pragma unroll
        for (int jj = 0; jj < 4; jj++) {
            int cc = n0 + 8 * jj + 2 * tg;
            int r0 = m0 + g, r1 = m0 + g + 8;
            float v00 = sacc[jj][0] * 0.125f, v01 = sacc[jj][1] * 0.125f;
            float v10 = sacc[jj][2] * 0.125f, v11 = sacc[jj][3] * 0.125f;
            if (s0 + cc     > q0 + r0) v00 = -1e30f;
            if (s0 + cc + 1 > q0 + r0) v01 = -1e30f;
            if (s0 + cc     > q0 + r1) v10 = -1e30f;
            if (s0 + cc + 1 > q0 + r1) v11 = -1e30f;
            ssp[r0 * 65 + cc] = v00; ssp[r0 * 65 + cc + 1] = v01;
            ssp[r1 * 65 + cc] = v10; ssp[r1 * 65 + cc + 1] = v11;
        }
        __syncthreads();

        // ---- online softmax (4 threads per row) + P split ----
        {
            int row = tid >> 2;
            int qr  = tid & 3;
            int c0  = qr * 16;
            float mloc = -1e30f;
            #pragma unroll
            for (int i = 0; i < 16; i++)
                mloc = fmaxf(mloc, ssp[row * 65 + c0 + i]);
            mloc = fmaxf(mloc, __shfl_xor_sync(0xffffffffu, mloc, 1));
            mloc = fmaxf(mloc, __shfl_xor_sync(0xffffffffu, mloc, 2));
            float mo = rowm[row];
            float mx = fmaxf(mo, mloc);
            float alpha = __expf(mo - mx);
            float sloc = 0.f;
            #pragma unroll
            for (int i4 = 0; i4 < 4; i4++) {
                int d = c0 + 4 * i4;
                __half ph4[4], pl4[4];
                #pragma unroll
                for (int q = 0; q < 4; q++) {
                    float pp = __expf(ssp[row * 65 + d + q] - mx);
                    sloc += pp;
                    split2h(pp, ph4[q], pl4[q]);
                }
                uint32_t off = (uint32_t)((d >> 5) * 4096) + swoff(row, (d & 31) >> 3) + (d & 7) * 2;
                *(uint2*)(asmem + APH + off) = *(uint2*)ph4;
                *(uint2*)(asmem + APL + off) = *(uint2*)pl4;
            }
            sloc += __shfl_xor_sync(0xffffffffu, sloc, 1);
            sloc += __shfl_xor_sync(0xffffffffu, sloc, 2);
            if (qr == 0) {
                rowm[row] = mx;
                rowl[row] = rowl[row] * alpha + sloc;
                rowa[row] = alpha;
            }
        }
        __syncthreads();

        // ---- O = O*alpha + P V (3-product) ----
        {
            float a0 = rowa[m0 + g], a1 = rowa[m0 + g + 8];
            #pragma unroll
            for (int jj = 0; jj < 4; jj++) {
                o[jj][0] *= a0; o[jj][1] *= a0;
                o[jj][2] *= a1; o[jj][3] *= a1;
            }
            #pragma unroll
            for (int seg = 0; seg < 2; seg++) {
                #pragma unroll
                for (int ks = 0; ks < 2; ks++) {
                    uint32_t ahf[4], alf[4], bhf[2][4], blf[2][4];
                    {
                        int r = m0 + (lane & 15);
                        uint32_t off = (uint32_t)(seg * 4096) + swoff(r, ks * 2 + (lane >> 4));
                        ldsm4(ahf, sb + APH + off);
                        ldsm4(alf, sb + APL + off);
                    }
                    #pragma unroll
                    for (int j = 0; j < 2; j++) {
                        int r = n0 + 16 * j + ((lane >> 4) * 8 + (lane & 7));
                        uint32_t off = (uint32_t)(seg * 4096) + swoff(r, ks * 2 + ((lane >> 3) & 1));
                        ldsm4(bhf[j], sb + AVH + off);
                        ldsm4(blf[j], sb + AVL + off);
                    }
                    #pragma unroll
                    for (int jj = 0; jj < 4; jj++)
                        mma_f16(o[jj], ahf, &bhf[jj >> 1][(jj & 1) * 2]);
                    #pragma unroll
                    for (int jj = 0; jj < 4; jj++)
                        mma_f16(o[jj], ahf, &blf[jj >> 1][(jj & 1) * 2]);
                    #pragma unroll
                    for (int jj = 0; jj < 4; jj++)
                        mma_f16(o[jj], alf, &bhf[jj >> 1][(jj & 1) * 2]);
                }
            }
        }
    }

    // ---- final write ----
    {
        float inv0 = 1.f / rowl[m0 + g];
        float inv1 = 1.f / rowl[m0 + g + 8];
        #pragma unroll
        for (int jj = 0; jj < 4; jj++) {
            int dcol = n0 + 8 * jj + 2 * tg;
            float* p0 = y + heady + (size_t)(q0 + m0 + g) * DMODEL + dcol;
            float* p1 = y + heady + (size_t)(q0 + m0 + g + 8) * DMODEL + dcol;
            *(float2*)p0 = make_float2(o[jj][0] * inv0, o[jj][1] * inv0);
            *(float2*)p1 = make_float2(o[jj][2] * inv1, o[jj][3] * inv1);
        }
    }
}

// ---------------- residual + layernorm (fused hi/lo split) ----------------
__global__ void resln_kernel(const float* __restrict__ xin,
                             const float* __restrict__ res,
                             const float* __restrict__ gamma,
                             const float* __restrict__ beta,
                             float* __restrict__ xout,
                             __nv_bfloat16* __restrict__ xh,
                             __nv_bfloat16* __restrict__ xl)
{
    int row = blockIdx.x;
    int tid = threadIdx.x;   // 256
    __shared__ float red[256];

    float vals[3];
    float s1 = 0.f;
    #pragma unroll
    for (int i = 0; i < 3; i++) {
        int cidx = tid + i * 256;
        float vv = xin[(size_t)row * DMODEL + cidx] + res[(size_t)row * DMODEL + cidx];
        vals[i] = vv;
        s1 += vv;
    }
    red[tid] = s1;
    __syncthreads();
    for (int off = 128; off > 0; off >>= 1) {
        if (tid < off) red[tid] += red[tid + off];
        __syncthreads();
    }
    float mu = red[0] * (1.f / DMODEL);
    __syncthreads();

    float s2 = 0.f;
    #pragma unroll
    for (int i = 0; i < 3; i++) {
        float dv = vals[i] - mu;
        s2 += dv * dv;
    }
    red[tid] = s2;
    __syncthreads();
    for (int off = 128; off > 0; off >>= 1) {
        if (tid < off) red[tid] += red[tid + off];
        __syncthreads();
    }
    float inv = rsqrtf(red[0] * (1.f / DMODEL) + LNEPS);
    __syncthreads();

    #pragma unroll
    for (int i = 0; i < 3; i++) {
        int cidx = tid + i * 256;
        float v = (vals[i] - mu) * inv * gamma[cidx] + beta[cidx];
        xout[(size_t)row * DMODEL + cidx] = v;
        __nv_bfloat16 h, l;
        split2(v, h, l);
        xh[(size_t)row * DMODEL + cidx] = h;
        xl[(size_t)row * DMODEL + cidx] = l;
    }
}

// ---------------- cross-entropy: one-pass online logsumexp ----------------
__global__ void loss_row_kernel(const float* __restrict__ logits,
                                const int* __restrict__ tgt,
                                float* __restrict__ rowloss)
{
    int row = blockIdx.x;
    int tid = threadIdx.x;   // 256
    const float* lr = logits + (size_t)row * VOCAB;
    __shared__ float sm[256], ss[256];

    float m = -1e30f, s = 0.f;
    for (int cc = tid; cc < VOCAB; cc += 256) {
        float v = lr[cc];
        if (v > m) { s = s * __expf(m - v) + 1.f; m = v; }
        else       { s += __expf(v - m); }
    }
    sm[tid] = m; ss[tid] = s;
    __syncthreads();
    for (int off = 128; off > 0; off >>= 1) {
        if (tid < off) {
            float m2 = sm[tid + off], s2 = ss[tid + off];
            float m1 = sm[tid],       s1 = ss[tid];
            float mm = fmaxf(m1, m2);
            sm[tid] = mm;
            ss[tid] = s1 * __expf(m1 - mm) + s2 * __expf(m2 - mm);
        }
        __syncthreads();
    }
    if (tid == 0)
        rowloss[row] = -(lr[tgt[row]] - sm[0] - logf(ss[0]));
}

__global__ void loss_final_kernel(const float* __restrict__ rowloss,
                                  float* __restrict__ out)
{
    int tid = threadIdx.x;   // 256
    __shared__ float red[256];
    float s = 0.f;
    for (int i = tid; i < BT; i += 256) s += rowloss[i];
    red[tid] = s;
    __syncthreads();
    for (int off = 128; off > 0; off >>= 1) {
        if (tid < off) red[tid] += red[tid + off];
        __syncthreads();
    }
    if (tid == 0) out[0] = red[0] * (1.f / BT);
}

// ---------------- host orchestration ----------------
static inline void convT_launch(const float* B, __nv_bfloat16* Th, __nv_bfloat16* Tl, int K, int N)
{
    dim3 grid((N + 31) / 32, K / 32);
    convT_kernel<<<grid, dim3(32, 8)>>>(B, Th, Tl, K, N);
}

static inline void gemm_launch(const __nv_bfloat16* Ah, const __nv_bfloat16* Al,
                               const __nv_bfloat16* Bh, const __nv_bfloat16* Bl,
                               const float* bias, float* C,
                               __nv_bfloat16* Chi, __nv_bfloat16* Clo,
                               int M, int N, int K, int relu)
{
    dim3 grid((N + 127) / 128, (M + 127) / 128);
    gemm_bf16_kernel<<<grid, 256, GSMEM_BYTES>>>(Ah, Al, Bh, Bl, bias, C, Chi, Clo,
                                                 M, N, K, relu);
}

extern "C" void kernel_launch(void* const* d_in, const int* in_sizes, int n_in,
                              void* d_out, int out_size)
{
    const int*   idx     = (const int*)  d_in[0];
    const int*   targets = (const int*)  d_in[1];
    const float* tok_emb = (const float*)d_in[2];
    const float* pos_emb = (const float*)d_in[3];
    const float* Wq      = (const float*)d_in[4];
    const float* Wk      = (const float*)d_in[5];
    const float* Wv      = (const float*)d_in[6];
    const float* ln1_g   = (const float*)d_in[7];
    const float* ln1_b   = (const float*)d_in[8];
    const float* W1      = (const float*)d_in[9];
    const float* b1      = (const float*)d_in[10];
    const float* W2      = (const float*)d_in[11];
    const float* b2      = (const float*)d_in[12];
    const float* ln2_g   = (const float*)d_in[13];
    const float* ln2_b   = (const float*)d_in[14];
    const float* head_w  = (const float*)d_in[15];
    const float* head_b  = (const float*)d_in[16];

    cudaFuncSetAttribute(gemm_bf16_kernel,
                         cudaFuncAttributeMaxDynamicSharedMemorySize, GSMEM_BYTES);
    cudaFuncSetAttribute(gemm_f16_kernel,
                         cudaFuncAttributeMaxDynamicSharedMemorySize, FSMEM_BYTES);
    cudaFuncSetAttribute(attn_mma_kernel,
                         cudaFuncAttributeMaxDynamicSharedMemorySize, ATT_SMEM);

    void* p;
    float *x, *y, *qkv, *rl;
    __nv_bfloat16 *ah, *al, *ch, *cl, *bh, *bl;
    __half *fh;
    cudaGetSymbolAddress(&p, g_x);   x   = (float*)p;
    cudaGetSymbolAddress(&p, g_y);   y   = (float*)p;
    cudaGetSymbolAddress(&p, g_qkv); qkv = (float*)p;
    cudaGetSymbolAddress(&p, g_rowloss); rl = (float*)p;
    cudaGetSymbolAddress(&p, g_ah);  ah  = (__nv_bfloat16*)p;
    cudaGetSymbolAddress(&p, g_al);  al  = (__nv_bfloat16*)p;
    cudaGetSymbolAddress(&p, g_ch);  ch  = (__nv_bfloat16*)p;
    cudaGetSymbolAddress(&p, g_cl);  cl  = (__nv_bfloat16*)p;
    cudaGetSymbolAddress(&p, g_bh);  bh  = (__nv_bfloat16*)p;
    cudaGetSymbolAddress(&p, g_bl);  bl  = (__nv_bfloat16*)p;
    cudaGetSymbolAddress(&p, g_fh);  fh  = (__half*)p;

    float* out = (float*)d_out;
    size_t logits_n = (size_t)BT * VOCAB;

    embed_kernel<<<(BT * DMODEL + 255) / 256, 256>>>(idx, tok_emb, pos_emb,
                                                     x, ah, al);

    for (int l = 0; l < NLAYER; l++) {
        const float* wq = Wq + (size_t)l * DMODEL * DMODEL;
        const float* wk = Wk + (size_t)l * DMODEL * DMODEL;
        const float* wv = Wv + (size_t)l * DMODEL * DMODEL;

        convT_launch(wq, bh,                               bl,                               DMODEL, DMODEL);
        convT_launch(wk, bh + (size_t)DMODEL * DMODEL,     bl + (size_t)DMODEL * DMODEL,     DMODEL, DMODEL);
        convT_launch(wv, bh + (size_t)2 * DMODEL * DMODEL, bl + (size_t)2 * DMODEL * DMODEL, DMODEL, DMODEL);
        gemm_launch(ah, al, bh, bl, nullptr, qkv, nullptr, nullptr,
                    BT, QKVLD, DMODEL, 0);

        attn_mma_kernel<<<dim3(TLEN / 64, NHEAD, BATCH), 256, ATT_SMEM>>>(qkv, y);

        resln_kernel<<<BT, 256>>>(y, x, ln1_g + (size_t)l * DMODEL,
                                  ln1_b + (size_t)l * DMODEL, x, ah, al);

        convT_launch(W1 + (size_t)l * DMODEL * FFDIM, bh, bl, DMODEL, FFDIM);
        gemm_launch(ah, al, bh, bl, b1 + (size_t)l * FFDIM, nullptr,
                    ch, cl, BT, FFDIM, DMODEL, 1);

        convT_launch(W2 + (size_t)l * FFDIM * DMODEL, bh, bl, FFDIM, DMODEL);
        gemm_launch(ch, cl, bh, bl, b2 + (size_t)l * DMODEL, y,
                    nullptr, nullptr, BT, DMODEL, FFDIM, 0);

        resln_kernel<<<BT, 256>>>(y, x, ln2_g + (size_t)l * DMODEL,
                                  ln2_b + (size_t)l * DMODEL, x, ah, al);
    }

    // ---- lm head: fp16 single-product ----
    conv_f16_kernel<<<(BT * DMODEL / 4 + 255) / 256, 256>>>(x, fh, BT * DMODEL / 4);
    {
        dim3 grid((VOCAB + 31) / 32, DMODEL / 32);
        convT_f16_kernel<<<grid, dim3(32, 8)>>>(head_w, (__half*)bh, DMODEL, VOCAB);
    }
    {
        dim3 grid((VOCAB + 127) / 128, (BT + 127) / 128);
        gemm_f16_kernel<<<grid, 256, FSMEM_BYTES>>>(fh, (const __half*)bh,
                                                    head_b, out, BT, VOCAB, DMODEL);
    }

    loss_row_kernel<<<BT, 256>>>(out, targets, rl);
    if ((size_t)out_size >= logits_n + 1)
        loss_final_kernel<<<1, 256>>>(rl, out + logits_n);
}

// round 15
// speedup vs baseline: 12.8761x; 1.1867x over previous
#include <cuda_runtime.h>
#include <cuda_bf16.h>
#include <cuda_fp16.h>
#include <math.h>
#include <stdint.h>

// ---------------- problem constants ----------------
#define VOCAB 50257
#define DMODEL 768
#define NHEAD 12
#define HDIM 64
#define TLEN 1024
#define NLAYER 6
#define BATCH 4
#define BT (BATCH * TLEN)     // 4096
#define FFDIM (4 * DMODEL)    // 3072
#define QKVLD (3 * DMODEL)    // 2304
#define LNEPS 1e-5f

// ---------------- scratch (device globals: alloc-free rule) ----------------
__device__ __align__(128) float g_x  [BT * DMODEL];
__device__ __align__(128) float g_y  [BT * DMODEL];
__device__ __align__(128) float g_qkv[BT * QKVLD];
__device__ __align__(128) float g_rowloss[BT];

// f16 activations: residual stream (single) and FFN hidden (single)
__device__ __align__(128) __half g_xf16[BT * DMODEL];
__device__ __align__(128) __half g_hf16[BT * FFDIM];
// f16 hi/lo transposed weights (hi sized for head; lo for layer weights)
__device__ __align__(128) __half g_wh[(size_t)VOCAB * DMODEL];
__device__ __align__(128) __half g_wl[(size_t)VOCAB * DMODEL];

// ---------------- split helper ----------------
__device__ __forceinline__ void split2h(float v, __half& h, __half& l)
{
    h = __float2half_rn(v);
    l = __float2half_rn(v - __half2float(h));
}

// ---------------- embedding (fused f16 convert) ----------------
__global__ void embed_kernel(const int* __restrict__ idx,
                             const float* __restrict__ tok,
                             const float* __restrict__ pos,
                             float* __restrict__ x,
                             __half* __restrict__ xf)
{
    int i = blockIdx.x * blockDim.x + threadIdx.x;
    if (i < BT * DMODEL) {
        int row = i / DMODEL;
        int d   = i - row * DMODEL;
        int t   = row % TLEN;
        float v = tok[(size_t)idx[row] * DMODEL + d] + pos[(size_t)t * DMODEL + d];
        x[i] = v;
        xf[i] = __float2half_rn(v);
    }
}

// ---------------- fast weight convert + transpose: fp32 [K][N] -> f16 hi(/lo) [N][K] ----------------
// Tile 32(n) x 128(k). Loads: 128B rows (float4 when N%4==0). Stores: 32B vectors.
__global__ void convT_f16_kernel(const float* __restrict__ B,
                                 __half* __restrict__ Th,
                                 __half* __restrict__ Tl,   // may be null
                                 int K, int N)
{
    __shared__ float tile[128][33];
    int n0 = blockIdx.x * 32;
    int k0 = blockIdx.y * 128;
    int tid = threadIdx.x;      // 256
    bool vec4N = ((N & 3) == 0);

    {
        int kr  = tid >> 1;
        int nc0 = (tid & 1) * 16;
        const float* src = B + (size_t)(k0 + kr) * N + n0 + nc0;
        #pragma unroll
        for (int i = 0; i < 4; i++) {
            int nc = nc0 + 4 * i;
            float4 v = make_float4(0.f, 0.f, 0.f, 0.f);
            float* vv = &v.x;
            if (vec4N && n0 + nc + 3 < N) {
                v = *(const float4*)(src + 4 * i);
            } else {
                #pragma unroll
                for (int q = 0; q < 4; q++)
                    if (n0 + nc + q < N) vv[q] = src[4 * i + q];
            }
            tile[kr][nc + 0] = v.x; tile[kr][nc + 1] = v.y;
            tile[kr][nc + 2] = v.z; tile[kr][nc + 3] = v.w;
        }
    }
    __syncthreads();
    {
        int nr = tid >> 3;
        int n  = n0 + nr;
        if (n < N) {
            int kc0 = (tid & 7) * 16;
            __half hh[16], ll[16];
            #pragma unroll
            for (int i = 0; i < 16; i++) {
                float v = tile[kc0 + i][nr];
                hh[i] = __float2half_rn(v);
                ll[i] = __float2half_rn(v - __half2float(hh[i]));
            }
            __half* dh = Th + (size_t)n * K + k0 + kc0;
            *(uint4*)dh       = *(uint4*)hh;
            *(uint4*)(dh + 8) = *(uint4*)(hh + 8);
            if (Tl) {
                __half* dl = Tl + (size_t)n * K + k0 + kc0;
                *(uint4*)dl       = *(uint4*)ll;
                *(uint4*)(dl + 8) = *(uint4*)(ll + 8);
            }
        }
    }
}

// ======== shared GEMM infrastructure ========
#define TC_ARRB   8192u
#define T2_STAGEB (3 * TC_ARRB)         // layer f16 2-product: 3 arrays
#define G2SMEM_BYTES (3 * T2_STAGEB)    // 73728
#define TF_STAGEB (2 * TC_ARRB)         // head f16 single: 2 arrays
#define FSMEM_BYTES (3 * TF_STAGEB)     // 49152

__device__ __forceinline__ uint32_t swoff(int row, int ch)
{
    return (uint32_t)(row * 64 + (((ch ^ (row >> 1)) & 3) << 4));
}

__device__ __forceinline__ void mma_f16(float c[4], const uint32_t a[4], const uint32_t b[2])
{
    asm volatile(
        "mma.sync.aligned.m16n8k16.row.col.f32.f16.f16.f32 "
        "{%0,%1,%2,%3}, {%4,%5,%6,%7}, {%8,%9}, {%0,%1,%2,%3};\n"
        : "+f"(c[0]), "+f"(c[1]), "+f"(c[2]), "+f"(c[3])
        : "r"(a[0]), "r"(a[1]), "r"(a[2]), "r"(a[3]), "r"(b[0]), "r"(b[1]));
}

__device__ __forceinline__ void ldsm4(uint32_t r[4], uint32_t addr)
{
    asm volatile("ldmatrix.sync.aligned.m8n8.x4.shared.b16 {%0,%1,%2,%3}, [%4];\n"
                 : "=r"(r[0]), "=r"(r[1]), "=r"(r[2]), "=r"(r[3]) : "r"(addr));
}

// ======== layer GEMM: fp16 2-product (A f16, B hi/lo f16), 128x128, BK=32 ========
__device__ __forceinline__ void gemm_load_stage2(
    uint32_t sbase, int s, int kt, int tid,
    const __half* A, const __half* Bh, const __half* Bl,
    int rowBase, int colBase, int M, int N, int K)
{
    #pragma unroll
    for (int j = 0; j < 6; j++) {
        int c   = tid + j * 256;
        int arr = c >> 9;          // 0:A 1:Bh 2:Bl
        int cc  = c & 511;
        int row = cc >> 2;
        int ch  = cc & 3;
        const __half* bp = (arr == 0) ? A : (arr == 1) ? Bh : Bl;
        bool isB = (arr >= 1);
        int lim  = isB ? N : M;
        int grow = (isB ? colBase : rowBase) + row;
        int grow_c = (grow < lim) ? grow : (lim - 1);
        const void* gptr = bp + (size_t)grow_c * K + kt * 32 + ch * 8;
        uint32_t daddr = sbase + (uint32_t)s * T2_STAGEB + (uint32_t)arr * TC_ARRB
                       + swoff(row, ch);
        int sz = (grow < lim) ? 16 : 0;
        asm volatile("cp.async.cg.shared.global [%0], [%1], 16, %2;\n"
                     :: "r"(daddr), "l"(gptr), "r"(sz));
    }
    asm volatile("cp.async.commit_group;\n" ::);
}

__global__ __launch_bounds__(256, 2)
void gemm_f16x2_kernel(const __half* __restrict__ A,
                       const __half* __restrict__ Bh,
                       const __half* __restrict__ Bl,
                       const float* __restrict__ bias,
                       float* __restrict__ C,        // fp32 out (if Cf16 null)
                       __half* __restrict__ Cf16,    // f16 out (+relu)
                       int M, int N, int K, int relu)
{
    extern __shared__ __nv_bfloat16 smem[];
    uint32_t sbase = (uint32_t)__cvta_generic_to_shared(smem);

    int tid  = threadIdx.x;
    int warp = tid >> 5;
    int lane = tid & 31;
    int m0 = (warp >> 1) * 32;
    int n0 = (warp & 1) * 64;
    int rowBase = blockIdx.y * 128;
    int colBase = blockIdx.x * 128;
    int KT = K / 32;

    float acc[2][8][4];
    #pragma unroll
    for (int i = 0; i < 2; i++)
        #pragma unroll
        for (int j = 0; j < 8; j++)
            #pragma unroll
            for (int r = 0; r < 4; r++) acc[i][j][r] = 0.f;

    gemm_load_stage2(sbase, 0, 0, tid, A, Bh, Bl, rowBase, colBase, M, N, K);
    gemm_load_stage2(sbase, 1, 1, tid, A, Bh, Bl, rowBase, colBase, M, N, K);

    for (int kt = 0; kt < KT; kt++) {
        if (kt < KT - 1) asm volatile("cp.async.wait_group 1;\n" ::);
        else             asm volatile("cp.async.wait_group 0;\n" ::);
        __syncthreads();

        if (kt + 2 < KT)
            gemm_load_stage2(sbase, (kt + 2) % 3, kt + 2, tid,
                             A, Bh, Bl, rowBase, colBase, M, N, K);

        int s = kt % 3;
        uint32_t a_b  = sbase + (uint32_t)s * T2_STAGEB + 0 * TC_ARRB;
        uint32_t bh_b = sbase + (uint32_t)s * T2_STAGEB + 1 * TC_ARRB;
        uint32_t bl_b = sbase + (uint32_t)s * T2_STAGEB + 2 * TC_ARRB;

        #pragma unroll
        for (int ks = 0; ks < 2; ks++) {
            uint32_t af[2][4], bhf[4][4], blf[4][4];
            #pragma unroll
            for (int i = 0; i < 2; i++) {
                int r = m0 + 16 * i + (lane & 15);
                uint32_t off = swoff(r, ks * 2 + (lane >> 4));
                ldsm4(af[i], a_b + off);
            }
            #pragma unroll
            for (int j = 0; j < 4; j++) {
                int r = n0 + 16 * j + ((lane >> 4) * 8 + (lane & 7));
                uint32_t off = swoff(r, ks * 2 + ((lane >> 3) & 1));
                ldsm4(bhf[j], bh_b + off);
                ldsm4(blf[j], bl_b + off);
            }
            #pragma unroll
            for (int i = 0; i < 2; i++)
                #pragma unroll
                for (int jj = 0; jj < 8; jj++)
                    mma_f16(acc[i][jj], af[i], &bhf[jj >> 1][(jj & 1) * 2]);
            #pragma unroll
            for (int i = 0; i < 2; i++)
                #pragma unroll
                for (int jj = 0; jj < 8; jj++)
                    mma_f16(acc[i][jj], af[i], &blf[jj >> 1][(jj & 1) * 2]);
        }
    }

    int g = lane >> 2, tg = lane & 3;
    #pragma unroll
    for (int i = 0; i < 2; i++) {
        #pragma unroll
        for (int jj = 0; jj < 8; jj++) {
            int col = colBase + n0 + 8 * jj + 2 * tg;
            #pragma unroll
            for (int h = 0; h < 2; h++) {
                int row = rowBase + m0 + 16 * i + g + 8 * h;
                if (row >= M) continue;
                float v0 = acc[i][jj][2 * h + 0];
                float v1 = acc[i][jj][2 * h + 1];
                if (bias) { v0 += bias[col]; v1 += bias[col + 1]; }
                if (relu) { v0 = fmaxf(v0, 0.f); v1 = fmaxf(v1, 0.f); }
                if (Cf16) {
                    __half hp[2] = { __float2half_rn(v0), __float2half_rn(v1) };
                    *(uint32_t*)(Cf16 + (size_t)row * N + col) = *(uint32_t*)hp;
                } else {
                    *(float2*)(C + (size_t)row * N + col) = make_float2(v0, v1);
                }
            }
        }
    }
}

// ======== head GEMM: fp16 single-product ========
__device__ __forceinline__ void gemm_load_stage_f16(
    uint32_t sbase, int s, int kt, int tid,
    const __half* Ah, const __half* Bh,
    int rowBase, int colBase, int M, int N, int K)
{
    #pragma unroll
    for (int j = 0; j < 4; j++) {
        int c   = tid + j * 256;
        int arr = c >> 9;
        int cc  = c & 511;
        int row = cc >> 2;
        int ch  = cc & 3;
        const __half* bp = (arr == 0) ? Ah : Bh;
        bool isB = (arr >= 1);
        int lim  = isB ? N : M;
        int grow = (isB ? colBase : rowBase) + row;
        int grow_c = (grow < lim) ? grow : (lim - 1);
        const void* gptr = bp + (size_t)grow_c * K + kt * 32 + ch * 8;
        uint32_t daddr = sbase + (uint32_t)s * TF_STAGEB + (uint32_t)arr * TC_ARRB
                       + swoff(row, ch);
        int sz = (grow < lim) ? 16 : 0;
        asm volatile("cp.async.cg.shared.global [%0], [%1], 16, %2;\n"
                     :: "r"(daddr), "l"(gptr), "r"(sz));
    }
    asm volatile("cp.async.commit_group;\n" ::);
}

__global__ __launch_bounds__(256, 2)
void gemm_f16_kernel(const __half* __restrict__ Ah,
                     const __half* __restrict__ Bh,
                     const float* __restrict__ bias,
                     float* __restrict__ C,
                     int M, int N, int K)
{
    extern __shared__ __nv_bfloat16 smem[];
    uint32_t sbase = (uint32_t)__cvta_generic_to_shared(smem);

    int tid  = threadIdx.x;
    int warp = tid >> 5;
    int lane = tid & 31;
    int m0 = (warp >> 1) * 32;
    int n0 = (warp & 1) * 64;
    int rowBase = blockIdx.y * 128;
    int colBase = blockIdx.x * 128;
    int KT = K / 32;

    bool vec2N = ((N & 1) == 0);

    float acc[2][8][4];
    #pragma unroll
    for (int i = 0; i < 2; i++)
        #pragma unroll
        for (int j = 0; j < 8; j++)
            #pragma unroll
            for (int r = 0; r < 4; r++) acc[i][j][r] = 0.f;

    gemm_load_stage_f16(sbase, 0, 0, tid, Ah, Bh, rowBase, colBase, M, N, K);
    gemm_load_stage_f16(sbase, 1, 1, tid, Ah, Bh, rowBase, colBase, M, N, K);

    for (int kt = 0; kt < KT; kt++) {
        if (kt < KT - 1) asm volatile("cp.async.wait_group 1;\n" ::);
        else             asm volatile("cp.async.wait_group 0;\n" ::);
        __syncthreads();

        if (kt + 2 < KT)
            gemm_load_stage_f16(sbase, (kt + 2) % 3, kt + 2, tid,
                                Ah, Bh, rowBase, colBase, M, N, K);

        int s = kt % 3;
        uint32_t ah_b = sbase + (uint32_t)s * TF_STAGEB + 0 * TC_ARRB;
        uint32_t bh_b = sbase + (uint32_t)s * TF_STAGEB + 1 * TC_ARRB;

        #pragma unroll
        for (int ks = 0; ks < 2; ks++) {
            uint32_t ahf[2][4], bhf[4][4];
            #pragma unroll
            for (int i = 0; i < 2; i++) {
                int r = m0 + 16 * i + (lane & 15);
                uint32_t off = swoff(r, ks * 2 + (lane >> 4));
                ldsm4(ahf[i], ah_b + off);
            }
            #pragma unroll
            for (int j = 0; j < 4; j++) {
                int r = n0 + 16 * j + ((lane >> 4) * 8 + (lane & 7));
                uint32_t off = swoff(r, ks * 2 + ((lane >> 3) & 1));
                ldsm4(bhf[j], bh_b + off);
            }
            #pragma unroll
            for (int i = 0; i < 2; i++)
                #pragma unroll
                for (int jj = 0; jj < 8; jj++)
                    mma_f16(acc[i][jj], ahf[i], &bhf[jj >> 1][(jj & 1) * 2]);
        }
    }

    int g = lane >> 2, tg = lane & 3;
    #pragma unroll
    for (int i = 0; i < 2; i++) {
        #pragma unroll
        for (int jj = 0; jj < 8; jj++) {
            int col = colBase + n0 + 8 * jj + 2 * tg;
            #pragma unroll
            for (int h = 0; h < 2; h++) {
                int row = rowBase + m0 + 16 * i + g + 8 * h;
                if (row >= M) continue;
                float v0 = acc[i][jj][2 * h + 0];
                float v1 = acc[i][jj][2 * h + 1];
                if (bias) {
                    if (col < N)     v0 += bias[col];
                    if (col + 1 < N) v1 += bias[col + 1];
                }
                float* dst = C + (size_t)row * N + col;
                if (vec2N && col + 1 < N) {
                    *(float2*)dst = make_float2(v0, v1);
                } else {
                    if (col < N)     dst[0] = v0;
                    if (col + 1 < N) dst[1] = v1;
                }
            }
        }
    }
}

// ======== tensor-core flash attention (fp16 hi/lo 3-product, 64q x 64k tiles) ========
#define AQH 0u
#define AQL 8192u
#define AKH 16384u
#define AKL 24576u
#define AVH 32768u
#define AVL 40960u
#define APH 49152u
#define APL 57344u
#define ASS 65536u
#define ATT_SMEM (65536 + 64 * 65 * 4)      // 82176 B

__global__ __launch_bounds__(256)
void attn_mma_kernel(const float* __restrict__ qkv,
                     float* __restrict__ y)
{
    extern __shared__ char asmem[];
    __shared__ float rowm[64], rowl[64], rowa[64];
    uint32_t sb = (uint32_t)__cvta_generic_to_shared(asmem);

    int tid  = threadIdx.x;
    int warp = tid >> 5;
    int lane = tid & 31;
    int g  = lane >> 2;
    int tg = lane & 3;
    int m0 = (warp >> 1) * 16;
    int n0 = (warp & 1) * 32;

    int qt = blockIdx.x;
    int h  = blockIdx.y;
    int b  = blockIdx.z;
    size_t headq = (size_t)b * TLEN * QKVLD + (size_t)h * HDIM;
    size_t heady = (size_t)b * TLEN * DMODEL + (size_t)h * HDIM;
    int q0 = qt * 64;

    {
        int r  = tid >> 2;
        int c0 = (tid & 3) * 16;
        const float* src = qkv + headq + (size_t)(q0 + r) * QKVLD;
        #pragma unroll
        for (int i = 0; i < 4; i++) {
            int d = c0 + 4 * i;
            float4 v = *(const float4*)(src + d);
            const float* vv = &v.x;
            __half hh[4], ll[4];
            #pragma unroll
            for (int q = 0; q < 4; q++) split2h(vv[q], hh[q], ll[q]);
            uint32_t off = (uint32_t)((d >> 5) * 4096) + swoff(r, (d & 31) >> 3) + (d & 7) * 2;
            *(uint2*)(asmem + AQH + off) = *(uint2*)hh;
            *(uint2*)(asmem + AQL + off) = *(uint2*)ll;
        }
    }
    if (tid < 64) { rowm[tid] = -1e30f; rowl[tid] = 0.f; }

    float o[4][4];
    #pragma unroll
    for (int jj = 0; jj < 4; jj++)
        #pragma unroll
        for (int r = 0; r < 4; r++) o[jj][r] = 0.f;

    float* ssp = (float*)(asmem + ASS);
    int nt = qt + 1;

    for (int t = 0; t < nt; t++) {
        int s0 = t * 64;
        __syncthreads();

        {
            int r  = tid >> 2;
            int c0 = (tid & 3) * 16;
            const float* ksrc = qkv + headq + DMODEL     + (size_t)(s0 + r) * QKVLD;
            const float* vsrc = qkv + headq + 2 * DMODEL + (size_t)(s0 + r) * QKVLD;
            uint32_t segk = (uint32_t)((r >> 5) * 4096);
            int kk = r & 31;
            #pragma unroll
            for (int i = 0; i < 4; i++) {
                int d = c0 + 4 * i;
                float4 kv = *(const float4*)(ksrc + d);
                const float* kvv = &kv.x;
                __half hh[4], ll[4];
                #pragma unroll
                for (int q = 0; q < 4; q++) split2h(kvv[q], hh[q], ll[q]);
                uint32_t off = (uint32_t)((d >> 5) * 4096) + swoff(r, (d & 31) >> 3) + (d & 7) * 2;
                *(uint2*)(asmem + AKH + off) = *(uint2*)hh;
                *(uint2*)(asmem + AKL + off) = *(uint2*)ll;

                float4 vv4 = *(const float4*)(vsrc + d);
                const float* vvv = &vv4.x;
                #pragma unroll
                for (int q = 0; q < 4; q++) {
                    __half vh, vl;
                    split2h(vvv[q], vh, vl);
                    uint32_t off2 = segk + swoff(d + q, kk >> 3) + (kk & 7) * 2;
                    *(__half*)(asmem + AVH + off2) = vh;
                    *(__half*)(asmem + AVL + off2) = vl;
                }
            }
        }
        __syncthreads();

        float sacc[4][4];
        #pragma unroll
        for (int jj = 0; jj < 4; jj++)
            #pragma unroll
            for (int r = 0; r < 4; r++) sacc[jj][r] = 0.f;

        #pragma unroll
        for (int seg = 0; seg < 2; seg++) {
            #pragma unroll
            for (int ks = 0; ks < 2; ks++) {
                uint32_t ahf[4], alf[4], bhf[2][4], blf[2][4];
                {
                    int r = m0 + (lane & 15);
                    uint32_t off = (uint32_t)(seg * 4096) + swoff(r, ks * 2 + (lane >> 4));
                    ldsm4(ahf, sb + AQH + off);
                    ldsm4(alf, sb + AQL + off);
                }
                #pragma unroll
                for (int j = 0; j < 2; j++) {
                    int r = n0 + 16 * j + ((lane >> 4) * 8 + (lane & 7));
                    uint32_t off = (uint32_t)(seg * 4096) + swoff(r, ks * 2 + ((lane >> 3) & 1));
                    ldsm4(bhf[j], sb + AKH + off);
                    ldsm4(blf[j], sb + AKL + off);
                }
                #pragma unroll
                for (int jj = 0; jj < 4; jj++)
                    mma_f16(sacc[jj], ahf, &bhf[jj >> 1][(jj & 1) * 2]);
                #pragma unroll
                for (int jj = 0; jj < 4; jj++)
                    mma_f16(sacc[jj], ahf, &blf[jj >> 1][(jj & 1) * 2]);
                #pragma unroll
                for (int jj = 0; jj < 4; jj++)
                    mma_f16(sacc[jj], alf, &bhf[jj >> 1][(jj & 1) * 2]);
            }
        }
        #pragma unroll
        for (int jj = 0; jj < 4; jj++) {
            int cc = n0 + 8 * jj + 2 * tg;
            int r0 = m0 + g, r1 = m0 + g + 8;
            float v00 = sacc[jj][0] * 0.125f, v01 = sacc[jj][1] * 0.125f;
            float v10 = sacc[jj][2] * 0.125f, v11 = sacc[jj][3] * 0.125f;
            if (s0 + cc     > q0 + r0) v00 = -1e30f;
            if (s0 + cc + 1 > q0 + r0) v01 = -1e30f;
            if (s0 + cc     > q0 + r1) v10 = -1e30f;
            if (s0 + cc + 1 > q0 + r1) v11 = -1e30f;
            ssp[r0 * 65 + cc] = v00; ssp[r0 * 65 + cc + 1] = v01;
            ssp[r1 * 65 + cc] = v10; ssp[r1 * 65 + cc + 1] = v11;
        }
        __syncthreads();

        {
            int row = tid >> 2;
            int qr  = tid & 3;
            int c0  = qr * 16;
            float mloc = -1e30f;
            #pragma unroll
            for (int i = 0; i < 16; i++)
                mloc = fmaxf(mloc, ssp[row * 65 + c0 + i]);
            mloc = fmaxf(mloc, __shfl_xor_sync(0xffffffffu, mloc, 1));
            mloc = fmaxf(mloc, __shfl_xor_sync(0xffffffffu, mloc, 2));
            float mo = rowm[row];
            float mx = fmaxf(mo, mloc);
            float alpha = __expf(mo - mx);
            float sloc = 0.f;
            #pragma unroll
            for (int i4 = 0; i4 < 4; i4++) {
                int d = c0 + 4 * i4;
                __half ph4[4], pl4[4];
                #pragma unroll
                for (int q = 0; q < 4; q++) {
                    float pp = __expf(ssp[row * 65 + d + q] - mx);
                    sloc += pp;
                    split2h(pp, ph4[q], pl4[q]);
                }
                uint32_t off = (uint32_t)((d >> 5) * 4096) + swoff(row, (d & 31) >> 3) + (d & 7) * 2;
                *(uint2*)(asmem + APH + off) = *(uint2*)ph4;
                *(uint2*)(asmem + APL + off) = *(uint2*)pl4;
            }
            sloc += __shfl_xor_sync(0xffffffffu, sloc, 1);
            sloc += __shfl_xor_sync(0xffffffffu, sloc, 2);
            if (qr == 0) {
                rowm[row] = mx;
                rowl[row] = rowl[row] * alpha + sloc;
                rowa[row] = alpha;
            }
        }
        __syncthreads();

        {
            float a0 = rowa[m0 + g], a1 = rowa[m0 + g + 8];
            #pragma unroll
            for (int jj = 0; jj < 4; jj++) {
                o[jj][0] *= a0; o[jj][1] *= a0;
                o[jj][2] *= a1; o[jj][3] *= a1;
            }
            #pragma unroll
            for (int seg = 0; seg < 2; seg++) {
                #pragma unroll
                for (int ks = 0; ks < 2; ks++) {
                    uint32_t ahf[4], alf[4], bhf[2][4], blf[2][4];
                    {
                        int r = m0 + (lane & 15);
                        uint32_t off = (uint32_t)(seg * 4096) + swoff(r, ks * 2 + (lane >> 4));
                        ldsm4(ahf, sb + APH + off);
                        ldsm4(alf, sb + APL + off);
                    }
                    #pragma unroll
                    for (int j = 0; j < 2; j++) {
                        int r = n0 + 16 * j + ((lane >> 4) * 8 + (lane & 7));
                        uint32_t off = (uint32_t)(seg * 4096) + swoff(r, ks * 2 + ((lane >> 3) & 1));
                        ldsm4(bhf[j], sb + AVH + off);
                        ldsm4(blf[j], sb + AVL + off);
                    }
                    #pragma unroll
                    for (int jj = 0; jj < 4; jj++)
                        mma_f16(o[jj], ahf, &bhf[jj >> 1][(jj & 1) * 2]);
                    #pragma unroll
                    for (int jj = 0; jj < 4; jj++)
                        mma_f16(o[jj], ahf, &blf[jj >> 1][(jj & 1) * 2]);
                    #pragma unroll
                    for (int jj = 0; jj < 4; jj++)
                        mma_f16(o[jj], alf, &bhf[jj >> 1][(jj & 1) * 2]);
                }
            }
        }
    }

    {
        float inv0 = 1.f / rowl[m0 + g];
        float inv1 = 1.f / rowl[m0 + g + 8];
        #pragma unroll
        for (int jj = 0; jj < 4; jj++) {
            int dcol = n0 + 8 * jj + 2 * tg;
            float* p0 = y + heady + (size_t)(q0 + m0 + g) * DMODEL + dcol;
            float* p1 = y + heady + (size_t)(q0 + m0 + g + 8) * DMODEL + dcol;
            *(float2*)p0 = make_float2(o[jj][0] * inv0, o[jj][1] * inv0);
            *(float2*)p1 = make_float2(o[jj][2] * inv1, o[jj][3] * inv1);
        }
    }
}

// ---------------- residual + layernorm (fused f16 convert) ----------------
__global__ void resln_kernel(const float* __restrict__ xin,
                             const float* __restrict__ res,
                             const float* __restrict__ gamma,
                             const float* __restrict__ beta,
                             float* __restrict__ xout,
                             __half* __restrict__ xf)
{
    int row = blockIdx.x;
    int tid = threadIdx.x;   // 256
    __shared__ float red[256];

    float vals[3];
    float s1 = 0.f;
    #pragma unroll
    for (int i = 0; i < 3; i++) {
        int cidx = tid + i * 256;
        float vv = xin[(size_t)row * DMODEL + cidx] + res[(size_t)row * DMODEL + cidx];
        vals[i] = vv;
        s1 += vv;
    }
    red[tid] = s1;
    __syncthreads();
    for (int off = 128; off > 0; off >>= 1) {
        if (tid < off) red[tid] += red[tid + off];
        __syncthreads();
    }
    float mu = red[0] * (1.f / DMODEL);
    __syncthreads();

    float s2 = 0.f;
    #pragma unroll
    for (int i = 0; i < 3; i++) {
        float dv = vals[i] - mu;
        s2 += dv * dv;
    }
    red[tid] = s2;
    __syncthreads();
    for (int off = 128; off > 0; off >>= 1) {
        if (tid < off) red[tid] += red[tid + off];
        __syncthreads();
    }
    float inv = rsqrtf(red[0] * (1.f / DMODEL) + LNEPS);
    __syncthreads();

    #pragma unroll
    for (int i = 0; i < 3; i++) {
        int cidx = tid + i * 256;
        float v = (vals[i] - mu) * inv * gamma[cidx] + beta[cidx];
        xout[(size_t)row * DMODEL + cidx] = v;
        xf[(size_t)row * DMODEL + cidx] = __float2half_rn(v);
    }
}

// ---------------- cross-entropy: one-pass online logsumexp ----------------
__global__ void loss_row_kernel(const float* __restrict__ logits,
                                const int* __restrict__ tgt,
                                float* __restrict__ rowloss)
{
    int row = blockIdx.x;
    int tid = threadIdx.x;   // 256
    const float* lr = logits + (size_t)row * VOCAB;
    __shared__ float sm[256], ss[256];

    float m = -1e30f, s = 0.f;
    for (int cc = tid; cc < VOCAB; cc += 256) {
        float v = lr[cc];
        if (v > m) { s = s * __expf(m - v) + 1.f; m = v; }
        else       { s += __expf(v - m); }
    }
    sm[tid] = m; ss[tid] = s;
    __syncthreads();
    for (int off = 128; off > 0; off >>= 1) {
        if (tid < off) {
            float m2 = sm[tid + off], s2 = ss[tid + off];
            float m1 = sm[tid],       s1 = ss[tid];
            float mm = fmaxf(m1, m2);
            sm[tid] = mm;
            ss[tid] = s1 * __expf(m1 - mm) + s2 * __expf(m2 - mm);
        }
        __syncthreads();
    }
    if (tid == 0)
        rowloss[row] = -(lr[tgt[row]] - sm[0] - logf(ss[0]));
}

__global__ void loss_final_kernel(const float* __restrict__ rowloss,
                                  float* __restrict__ out)
{
    int tid = threadIdx.x;   // 256
    __shared__ float red[256];
    float s = 0.f;
    for (int i = tid; i < BT; i += 256) s += rowloss[i];
    red[tid] = s;
    __syncthreads();
    for (int off = 128; off > 0; off >>= 1) {
        if (tid < off) red[tid] += red[tid + off];
        __syncthreads();
    }
    if (tid == 0) out[0] = red[0] * (1.f / BT);
}

// ---------------- host orchestration ----------------
static inline void convT_launch(const float* B, __half* Th, __half* Tl, int K, int N)
{
    dim3 grid((N + 31) / 32, K / 128);
    convT_f16_kernel<<<grid, 256>>>(B, Th, Tl, K, N);
}

static inline void gemm2_launch(const __half* A, const __half* Bh, const __half* Bl,
                                const float* bias, float* C, __half* Cf16,
                                int M, int N, int K, int relu)
{
    dim3 grid((N + 127) / 128, (M + 127) / 128);
    gemm_f16x2_kernel<<<grid, 256, G2SMEM_BYTES>>>(A, Bh, Bl, bias, C, Cf16,
                                                   M, N, K, relu);
}

extern "C" void kernel_launch(void* const* d_in, const int* in_sizes, int n_in,
                              void* d_out, int out_size)
{
    const int*   idx     = (const int*)  d_in[0];
    const int*   targets = (const int*)  d_in[1];
    const float* tok_emb = (const float*)d_in[2];
    const float* pos_emb = (const float*)d_in[3];
    const float* Wq      = (const float*)d_in[4];
    const float* Wk      = (const float*)d_in[5];
    const float* Wv      = (const float*)d_in[6];
    const float* ln1_g   = (const float*)d_in[7];
    const float* ln1_b   = (const float*)d_in[8];
    const float* W1      = (const float*)d_in[9];
    const float* b1      = (const float*)d_in[10];
    const float* W2      = (const float*)d_in[11];
    const float* b2      = (const float*)d_in[12];
    const float* ln2_g   = (const float*)d_in[13];
    const float* ln2_b   = (const float*)d_in[14];
    const float* head_w  = (const float*)d_in[15];
    const float* head_b  = (const float*)d_in[16];

    cudaFuncSetAttribute(gemm_f16x2_kernel,
                         cudaFuncAttributeMaxDynamicSharedMemorySize, G2SMEM_BYTES);
    cudaFuncSetAttribute(gemm_f16_kernel,
                         cudaFuncAttributeMaxDynamicSharedMemorySize, FSMEM_BYTES);
    cudaFuncSetAttribute(attn_mma_kernel,
                         cudaFuncAttributeMaxDynamicSharedMemorySize, ATT_SMEM);

    void* p;
    float *x, *y, *qkv, *rl;
    __half *xf, *hf, *wh, *wl;
    cudaGetSymbolAddress(&p, g_x);    x   = (float*)p;
    cudaGetSymbolAddress(&p, g_y);    y   = (float*)p;
    cudaGetSymbolAddress(&p, g_qkv);  qkv = (float*)p;
    cudaGetSymbolAddress(&p, g_rowloss); rl = (float*)p;
    cudaGetSymbolAddress(&p, g_xf16); xf  = (__half*)p;
    cudaGetSymbolAddress(&p, g_hf16); hf  = (__half*)p;
    cudaGetSymbolAddress(&p, g_wh);   wh  = (__half*)p;
    cudaGetSymbolAddress(&p, g_wl);   wl  = (__half*)p;

    float* out = (float*)d_out;
    size_t logits_n = (size_t)BT * VOCAB;

    embed_kernel<<<(BT * DMODEL + 255) / 256, 256>>>(idx, tok_emb, pos_emb, x, xf);

    for (int l = 0; l < NLAYER; l++) {
        const float* wq = Wq + (size_t)l * DMODEL * DMODEL;
        const float* wk = Wk + (size_t)l * DMODEL * DMODEL;
        const float* wv = Wv + (size_t)l * DMODEL * DMODEL;

        // fused QKV weights -> [N=2304][K=768] f16 hi/lo
        convT_launch(wq, wh,                               wl,                               DMODEL, DMODEL);
        convT_launch(wk, wh + (size_t)DMODEL * DMODEL,     wl + (size_t)DMODEL * DMODEL,     DMODEL, DMODEL);
        convT_launch(wv, wh + (size_t)2 * DMODEL * DMODEL, wl + (size_t)2 * DMODEL * DMODEL, DMODEL, DMODEL);
        gemm2_launch(xf, wh, wl, nullptr, qkv, nullptr, BT, QKVLD, DMODEL, 0);

        attn_mma_kernel<<<dim3(TLEN / 64, NHEAD, BATCH), 256, ATT_SMEM>>>(qkv, y);

        resln_kernel<<<BT, 256>>>(y, x, ln1_g + (size_t)l * DMODEL,
                                  ln1_b + (size_t)l * DMODEL, x, xf);

        convT_launch(W1 + (size_t)l * DMODEL * FFDIM, wh, wl, DMODEL, FFDIM);
        gemm2_launch(xf, wh, wl, b1 + (size_t)l * FFDIM, nullptr, hf,
                     BT, FFDIM, DMODEL, 1);

        convT_launch(W2 + (size_t)l * FFDIM * DMODEL, wh, wl, FFDIM, DMODEL);
        gemm2_launch(hf, wh, wl, b2 + (size_t)l * DMODEL, y, nullptr,
                     BT, DMODEL, FFDIM, 0);

        resln_kernel<<<BT, 256>>>(y, x, ln2_g + (size_t)l * DMODEL,
                                  ln2_b + (size_t)l * DMODEL, x, xf);
    }

    // ---- lm head: fp16 single-product (A = xf from final resln) ----
    convT_launch(head_w, wh, nullptr, DMODEL, VOCAB);
    {
        dim3 grid((VOCAB + 127) / 128, (BT + 127) / 128);
        gemm_f16_kernel<<<grid, 256, FSMEM_BYTES>>>(xf, wh, head_b, out,
                                                    BT, VOCAB, DMODEL);
    }

    loss_row_kernel<<<BT, 256>>>(out, targets, rl);
    if ((size_t)out_size >= logits_n + 1)
        loss_final_kernel<<<1, 256>>>(rl, out + logits_n);
}